// round 2
// baseline (speedup 1.0000x reference)
#include <cuda_runtime.h>
#include <cuda_bf16.h>
#include <math.h>

// Problem constants
#define TT 2048
#define DD 2048
#define HH 16
#define DHH 128

// Scratch (allocation-free rule: __device__ globals)
__device__ float g_Q[TT * DD];
__device__ float g_K[TT * DD];
__device__ float g_V[TT * DD];
__device__ float g_Y[TT * DD];

// ---------------------------------------------------------------------------
// GEMM: C[M,N] = A[M,K] * B[N,K]^T + bias[N]   (M=N=K=2048)
// 128x128 block tile, BK=16, 256 threads, 8x8 per-thread, reg double buffer.
// smem layout As[k][m] / Bs[k][n], stride 132 (conflict-free LDS.128 reads,
// ~2-way conflict on transpose STS which is latency-overlapped).
// ---------------------------------------------------------------------------
__global__ __launch_bounds__(256, 2)
void gemm_nt_bias(const float* __restrict__ A, const float* __restrict__ B,
                  const float* __restrict__ bias, float* __restrict__ C)
{
    __shared__ float As[16 * 132];
    __shared__ float Bs[16 * 132];

    const int t  = threadIdx.x;
    const int tx = t & 15;
    const int ty = t >> 4;
    const int bm = blockIdx.y << 7;
    const int bn = blockIdx.x << 7;

    // load mapping: element e in [0,512): m = e>>2 (row), k4 = e&3 (float4 col)
    const int m0 = t >> 2;     // rows 0..63 (e0 = t), second load covers +64
    const int k4 = t & 3;

    const float4* Ag0 = (const float4*)(A + (size_t)(bm + m0) * DD) + k4;
    const float4* Ag1 = (const float4*)(A + (size_t)(bm + m0 + 64) * DD) + k4;
    const float4* Bg0 = (const float4*)(B + (size_t)(bn + m0) * DD) + k4;
    const float4* Bg1 = (const float4*)(B + (size_t)(bn + m0 + 64) * DD) + k4;

    float acc[8][8];
#pragma unroll
    for (int i = 0; i < 8; i++)
#pragma unroll
        for (int j = 0; j < 8; j++) acc[i][j] = 0.0f;

    // prefetch tile 0
    float4 pa0 = Ag0[0], pa1 = Ag1[0], pb0 = Bg0[0], pb1 = Bg1[0];

    for (int kt = 0; kt < 128; ++kt) {
        __syncthreads();
        // scatter-store (transpose) into smem: As[(k4*4+j)*132 + m]
        {
            float* pA0 = &As[(k4 * 4) * 132 + m0];
            pA0[0]       = pa0.x; pA0[132]     = pa0.y;
            pA0[2 * 132] = pa0.z; pA0[3 * 132] = pa0.w;
            float* pA1 = &As[(k4 * 4) * 132 + m0 + 64];
            pA1[0]       = pa1.x; pA1[132]     = pa1.y;
            pA1[2 * 132] = pa1.z; pA1[3 * 132] = pa1.w;
            float* pB0 = &Bs[(k4 * 4) * 132 + m0];
            pB0[0]       = pb0.x; pB0[132]     = pb0.y;
            pB0[2 * 132] = pb0.z; pB0[3 * 132] = pb0.w;
            float* pB1 = &Bs[(k4 * 4) * 132 + m0 + 64];
            pB1[0]       = pb1.x; pB1[132]     = pb1.y;
            pB1[2 * 132] = pb1.z; pB1[3 * 132] = pb1.w;
        }
        __syncthreads();

        // prefetch next tile while computing this one
        if (kt < 127) {
            pa0 = Ag0[(kt + 1) * 4];
            pa1 = Ag1[(kt + 1) * 4];
            pb0 = Bg0[(kt + 1) * 4];
            pb1 = Bg1[(kt + 1) * 4];
        }

#pragma unroll
        for (int k = 0; k < 16; ++k) {
            float4 a0 = *(const float4*)&As[k * 132 + (ty << 2)];
            float4 a1 = *(const float4*)&As[k * 132 + 64 + (ty << 2)];
            float4 b0 = *(const float4*)&Bs[k * 132 + (tx << 2)];
            float4 b1 = *(const float4*)&Bs[k * 132 + 64 + (tx << 2)];
            float av[8] = {a0.x, a0.y, a0.z, a0.w, a1.x, a1.y, a1.z, a1.w};
            float bv[8] = {b0.x, b0.y, b0.z, b0.w, b1.x, b1.y, b1.z, b1.w};
#pragma unroll
            for (int i = 0; i < 8; i++)
#pragma unroll
                for (int j = 0; j < 8; j++) acc[i][j] += av[i] * bv[j];
        }
    }

    // epilogue: + bias, vectorized stores
    float4 bb0 = *(const float4*)&bias[bn + (tx << 2)];
    float4 bb1 = *(const float4*)&bias[bn + 64 + (tx << 2)];
#pragma unroll
    for (int i = 0; i < 8; i++) {
        const int ri  = (i < 4) ? (ty * 4 + i) : (64 + ty * 4 + (i - 4));
        float* Crow = C + (size_t)(bm + ri) * DD + bn;
        float4 v0, v1;
        v0.x = acc[i][0] + bb0.x; v0.y = acc[i][1] + bb0.y;
        v0.z = acc[i][2] + bb0.z; v0.w = acc[i][3] + bb0.w;
        v1.x = acc[i][4] + bb1.x; v1.y = acc[i][5] + bb1.y;
        v1.z = acc[i][6] + bb1.z; v1.w = acc[i][7] + bb1.w;
        *(float4*)(Crow + (tx << 2))      = v0;
        *(float4*)(Crow + 64 + (tx << 2)) = v1;
    }
}

// ---------------------------------------------------------------------------
// Causal flash attention, fp32. One CTA = (head h, 128-row query block qb).
// Iterates 64-key blocks up to the causal limit. Online softmax in exp2
// domain (scale*log2e folded into Q at load). smem:
//   Qs[d][q] s132, Ks[d][s] s68, Vs[s][d] s132, Ps[s][q] s132  (~166 KB)
// ---------------------------------------------------------------------------
#define BQ 128
#define BS 64

__global__ __launch_bounds__(256, 1)
void attn_kernel()
{
    extern __shared__ float sm[];
    float* Qs = sm;                  // 128 * 132
    float* Ks = Qs + 128 * 132;      // 128 * 68
    float* Vs = Ks + 128 * 68;       // 64 * 132
    float* Ps = Vs + 64 * 132;       // 64 * 132

    const int t  = threadIdx.x;
    const int tx = t & 15;
    const int ty = t >> 4;
    const int h  = blockIdx.x & 15;
    const int qb = 15 - (blockIdx.x >> 4);   // heavy blocks first
    const int q0 = qb * BQ;
    const float qscale = 0.08838834764831845f * 1.4426950408889634f; // 1/sqrt(128)*log2(e)

    // ---- load Q tile transposed, scale folded in ----
    {
        const int q   = t & 127;
        const int d4b = t >> 7;   // 0 or 1
        const float* gq = g_Q + (size_t)(q0 + q) * DD + h * DHH;
#pragma unroll
        for (int i = 0; i < 16; ++i) {
            const int d4 = d4b + 2 * i;
            float4 v = *(const float4*)(gq + 4 * d4);
            float* p = &Qs[(4 * d4) * 132 + q];
            p[0]       = v.x * qscale;
            p[132]     = v.y * qscale;
            p[2 * 132] = v.z * qscale;
            p[3 * 132] = v.w * qscale;
        }
    }

    float oacc[8][8];
#pragma unroll
    for (int i = 0; i < 8; i++)
#pragma unroll
        for (int j = 0; j < 8; j++) oacc[i][j] = 0.0f;
    float mrow[8], lrow[8];
#pragma unroll
    for (int i = 0; i < 8; i++) { mrow[i] = -1e30f; lrow[i] = 0.0f; }

    const int nkb = 2 * (qb + 1);
    for (int kb = 0; kb < nkb; ++kb) {
        __syncthreads();   // previous iteration's consumers done

        // ---- load K tile transposed: Ks[d][s], conflict-free STS ----
        {
            const int s   = t & 63;
            const int d4b = t >> 6;   // 0..3
            const float* gk = g_K + (size_t)(kb * BS + s) * DD + h * DHH;
#pragma unroll
            for (int i = 0; i < 8; ++i) {
                const int d4 = d4b + 4 * i;
                float4 v = *(const float4*)(gk + 4 * d4);
                float* p = &Ks[(4 * d4) * 68 + s];
                p[0]  = v.x; p[68]  = v.y; p[136] = v.z; p[204] = v.w;
            }
        }
        // ---- load V tile natural: Vs[s][d], coalesced float4 ----
        {
#pragma unroll
            for (int i = 0; i < 8; ++i) {
                const int e = t + 256 * i;
                const int s = e >> 5, d4 = e & 31;
                float4 v = *(const float4*)(g_V + (size_t)(kb * BS + s) * DD + h * DHH + 4 * d4);
                *(float4*)&Vs[s * 132 + 4 * d4] = v;
            }
        }
        __syncthreads();

        // ---- GEMM1: S'[q,s] = (Q*qscale) . K   (in log2 domain) ----
        float sacc[8][4];
#pragma unroll
        for (int i = 0; i < 8; i++)
#pragma unroll
            for (int j = 0; j < 4; j++) sacc[i][j] = 0.0f;

#pragma unroll 8
        for (int d = 0; d < 128; ++d) {
            float4 a0 = *(const float4*)&Qs[d * 132 + (ty << 2)];
            float4 a1 = *(const float4*)&Qs[d * 132 + 64 + (ty << 2)];
            float4 b  = *(const float4*)&Ks[d * 68 + (tx << 2)];
            float av[8] = {a0.x, a0.y, a0.z, a0.w, a1.x, a1.y, a1.z, a1.w};
            float bv[4] = {b.x, b.y, b.z, b.w};
#pragma unroll
            for (int i = 0; i < 8; i++)
#pragma unroll
                for (int j = 0; j < 4; j++) sacc[i][j] += av[i] * bv[j];
        }

        // ---- causal mask (only possible in the last two key blocks) ----
        if (kb >= 2 * qb) {
#pragma unroll
            for (int i = 0; i < 8; i++) {
                const int row = q0 + ((i < 4) ? (4 * ty + i) : (64 + 4 * ty + i - 4));
#pragma unroll
                for (int j = 0; j < 4; j++) {
                    const int col = kb * BS + 4 * tx + j;
                    if (col > row) sacc[i][j] = -1e30f;
                }
            }
        }

        // ---- online softmax update (16-lane row groups) ----
#pragma unroll
        for (int i = 0; i < 8; i++) {
            float mx = fmaxf(fmaxf(sacc[i][0], sacc[i][1]),
                             fmaxf(sacc[i][2], sacc[i][3]));
#pragma unroll
            for (int o = 8; o > 0; o >>= 1)
                mx = fmaxf(mx, __shfl_xor_sync(0xffffffffu, mx, o));
            const float mnew  = fmaxf(mrow[i], mx);
            const float alpha = exp2f(mrow[i] - mnew);
            float sum = 0.0f;
#pragma unroll
            for (int j = 0; j < 4; j++) {
                const float p = exp2f(sacc[i][j] - mnew);
                sacc[i][j] = p;
                sum += p;
            }
#pragma unroll
            for (int o = 8; o > 0; o >>= 1)
                sum += __shfl_xor_sync(0xffffffffu, sum, o);
            lrow[i] = lrow[i] * alpha + sum;
            mrow[i] = mnew;
#pragma unroll
            for (int j = 0; j < 8; j++) oacc[i][j] *= alpha;
        }

        // ---- store P transposed: Ps[s][q] ----
#pragma unroll
        for (int i = 0; i < 8; i++) {
            const int row = (i < 4) ? (4 * ty + i) : (64 + 4 * ty + i - 4);
#pragma unroll
            for (int j = 0; j < 4; j++)
                Ps[(4 * tx + j) * 132 + row] = sacc[i][j];
        }
        __syncthreads();

        // ---- GEMM2: O += P . V ----
#pragma unroll 4
        for (int s = 0; s < 64; ++s) {
            float4 a0 = *(const float4*)&Ps[s * 132 + (ty << 2)];
            float4 a1 = *(const float4*)&Ps[s * 132 + 64 + (ty << 2)];
            float4 b0 = *(const float4*)&Vs[s * 132 + (tx << 2)];
            float4 b1 = *(const float4*)&Vs[s * 132 + 64 + (tx << 2)];
            float av[8] = {a0.x, a0.y, a0.z, a0.w, a1.x, a1.y, a1.z, a1.w};
            float bv[8] = {b0.x, b0.y, b0.z, b0.w, b1.x, b1.y, b1.z, b1.w};
#pragma unroll
            for (int i = 0; i < 8; i++)
#pragma unroll
                for (int j = 0; j < 8; j++) oacc[i][j] += av[i] * bv[j];
        }
    }

    // ---- epilogue: O /= l, write Y ----
#pragma unroll
    for (int i = 0; i < 8; i++) {
        const int ri  = (i < 4) ? (4 * ty + i) : (64 + 4 * ty + i - 4);
        const float inv = 1.0f / lrow[i];
        float* gy = g_Y + (size_t)(q0 + ri) * DD + h * DHH;
        float4 v0, v1;
        v0.x = oacc[i][0] * inv; v0.y = oacc[i][1] * inv;
        v0.z = oacc[i][2] * inv; v0.w = oacc[i][3] * inv;
        v1.x = oacc[i][4] * inv; v1.y = oacc[i][5] * inv;
        v1.z = oacc[i][6] * inv; v1.w = oacc[i][7] * inv;
        *(float4*)(gy + (tx << 2))      = v0;
        *(float4*)(gy + 64 + (tx << 2)) = v1;
    }
}

// ---------------------------------------------------------------------------
// Launch
// ---------------------------------------------------------------------------
extern "C" void kernel_launch(void* const* d_in, const int* in_sizes, int n_in,
                              void* d_out, int out_size)
{
    const float* x  = (const float*)d_in[0];
    const float* Wq = (const float*)d_in[1];
    const float* bq = (const float*)d_in[2];
    const float* Wk = (const float*)d_in[3];
    const float* bk = (const float*)d_in[4];
    const float* Wv = (const float*)d_in[5];
    const float* bv = (const float*)d_in[6];
    const float* Wo = (const float*)d_in[7];
    const float* bo = (const float*)d_in[8];
    float* out = (float*)d_out;

    float *Qp, *Kp, *Vp, *Yp;
    cudaGetSymbolAddress((void**)&Qp, g_Q);
    cudaGetSymbolAddress((void**)&Kp, g_K);
    cudaGetSymbolAddress((void**)&Vp, g_V);
    cudaGetSymbolAddress((void**)&Yp, g_Y);

    const int SMEM_ATTN = (128 * 132 + 128 * 68 + 64 * 132 + 64 * 132) * (int)sizeof(float);
    cudaFuncSetAttribute(attn_kernel, cudaFuncAttributeMaxDynamicSharedMemorySize, SMEM_ATTN);

    dim3 grid(16, 16);
    gemm_nt_bias<<<grid, 256>>>(x, Wq, bq, Qp);
    gemm_nt_bias<<<grid, 256>>>(x, Wk, bk, Kp);
    gemm_nt_bias<<<grid, 256>>>(x, Wv, bv, Vp);
    attn_kernel<<<256, 256, SMEM_ATTN>>>();
    gemm_nt_bias<<<grid, 256>>>(Yp, Wo, bo, out);
}

// round 4
// speedup vs baseline: 1.7593x; 1.7593x over previous
#include <cuda_runtime.h>
#include <cuda_bf16.h>
#include <math.h>
#include <stdint.h>

// Problem constants
#define TT 2048
#define DD 2048
#define HH 16
#define DHH 128

// ---------------------------------------------------------------------------
// Scratch (__device__ globals; allocation-free rule)
// ---------------------------------------------------------------------------
__device__ float g_Q[TT * DD];
__device__ float g_K[TT * DD];
__device__ float g_V[TT * DD];
__device__ float g_Y[TT * DD];

__device__ __nv_bfloat16 g_x_hi[TT * DD], g_x_lo[TT * DD];
__device__ __nv_bfloat16 g_Wq_hi[DD * DD], g_Wq_lo[DD * DD];
__device__ __nv_bfloat16 g_Wk_hi[DD * DD], g_Wk_lo[DD * DD];
__device__ __nv_bfloat16 g_Wv_hi[DD * DD], g_Wv_lo[DD * DD];
__device__ __nv_bfloat16 g_Wo_hi[DD * DD], g_Wo_lo[DD * DD];
__device__ __nv_bfloat16 g_Y_hi[TT * DD], g_Y_lo[TT * DD];

// ---------------------------------------------------------------------------
// sm_80-ISA tensor-core helpers (work at ptxas target sm_100 baseline)
// ---------------------------------------------------------------------------
__device__ __forceinline__ uint32_t smem_to_u32(const void* p) {
    uint32_t a;
    asm("{ .reg .u64 t; cvta.to.shared.u64 t, %1; cvt.u32.u64 %0, t; }"
        : "=r"(a) : "l"(p));
    return a;
}

__device__ __forceinline__ void cp16(uint32_t dst, const void* src) {
    asm volatile("cp.async.cg.shared.global [%0], [%1], 16;"
                 :: "r"(dst), "l"(src) : "memory");
}
#define CP_COMMIT() asm volatile("cp.async.commit_group;" ::: "memory")
#define CP_WAIT(n)  asm volatile("cp.async.wait_group %0;" :: "n"(n) : "memory")

__device__ __forceinline__ void ldsm_x4(uint32_t* r, uint32_t addr) {
    asm volatile("ldmatrix.sync.aligned.m8n8.x4.shared.b16 {%0,%1,%2,%3}, [%4];"
                 : "=r"(r[0]), "=r"(r[1]), "=r"(r[2]), "=r"(r[3]) : "r"(addr));
}

__device__ __forceinline__ void mma16816(float* d, const uint32_t* a, const uint32_t* b) {
    asm volatile(
        "mma.sync.aligned.m16n8k16.row.col.f32.bf16.bf16.f32 "
        "{%0,%1,%2,%3}, {%4,%5,%6,%7}, {%8,%9}, {%0,%1,%2,%3};"
        : "+f"(d[0]), "+f"(d[1]), "+f"(d[2]), "+f"(d[3])
        : "r"(a[0]), "r"(a[1]), "r"(a[2]), "r"(a[3]), "r"(b[0]), "r"(b[1]));
}

// ---------------------------------------------------------------------------
// split: fp32 -> (bf16 hi, bf16 lo),  lo = bf16(x - float(hi))
// ---------------------------------------------------------------------------
__global__ void split_kernel(const float* __restrict__ src,
                             __nv_bfloat16* __restrict__ hi,
                             __nv_bfloat16* __restrict__ lo)
{
    const int i = blockIdx.x * blockDim.x + threadIdx.x;  // float4 index
    float4 v = ((const float4*)src)[i];
    union { __nv_bfloat16 b[4]; uint2 u; } H, L;
    H.b[0] = __float2bfloat16(v.x); L.b[0] = __float2bfloat16(v.x - __bfloat162float(H.b[0]));
    H.b[1] = __float2bfloat16(v.y); L.b[1] = __float2bfloat16(v.y - __bfloat162float(H.b[1]));
    H.b[2] = __float2bfloat16(v.z); L.b[2] = __float2bfloat16(v.z - __bfloat162float(H.b[2]));
    H.b[3] = __float2bfloat16(v.w); L.b[3] = __float2bfloat16(v.w - __bfloat162float(H.b[3]));
    ((uint2*)hi)[i] = H.u;
    ((uint2*)lo)[i] = L.u;
}

// ---------------------------------------------------------------------------
// mma.sync GEMM: C[M,N] = A[M,K] @ W[N,K]^T + bias   (split bf16, fp32 accum)
// CTA 128x128, BK=64 (128B SW128-swizzled K-major rows), cp.async double
// buffer, 8 warps in 2x4, warp tile 64x32 via m16n8k16.
// grid = (16, 16, nz); z selects (W, bias, C) set (QKV fused).
// ---------------------------------------------------------------------------
#define STAGE_B   65536           // Ahi|Alo|Bhi|Blo, 16KB each
#define GEMM_SMEM (2 * STAGE_B)

__device__ __forceinline__ void load_tile_cp(const __nv_bfloat16* __restrict__ g,
                                             int row0, int k0, uint32_t sdst, int t)
{
    // 128 rows x 64 bf16 (128B), swizzled: dst = r*128 + ((c ^ (r&7))*16)
#pragma unroll
    for (int i = t; i < 1024; i += 256) {
        const int r = i >> 3, c = i & 7;
        cp16(sdst + r * 128 + ((c ^ (r & 7)) * 16),
             g + (size_t)(row0 + r) * DD + k0 + c * 8);
    }
}

__global__ __launch_bounds__(256, 1)
void gemm_mma(const __nv_bfloat16* __restrict__ Ahi, const __nv_bfloat16* __restrict__ Alo,
              const __nv_bfloat16* __restrict__ W0hi, const __nv_bfloat16* __restrict__ W0lo,
              const float* __restrict__ b0, float* __restrict__ C0,
              const __nv_bfloat16* __restrict__ W1hi, const __nv_bfloat16* __restrict__ W1lo,
              const float* __restrict__ b1, float* __restrict__ C1,
              const __nv_bfloat16* __restrict__ W2hi, const __nv_bfloat16* __restrict__ W2lo,
              const float* __restrict__ b2, float* __restrict__ C2)
{
    extern __shared__ __align__(1024) char smem[];
    const uint32_t sbase = smem_to_u32(smem);
    const int t   = threadIdx.x;
    const int wid = t >> 5;
    const int lid = t & 31;
    const int z   = blockIdx.z;

    const __nv_bfloat16* Whi = (z == 0) ? W0hi : ((z == 1) ? W1hi : W2hi);
    const __nv_bfloat16* Wlo = (z == 0) ? W0lo : ((z == 1) ? W1lo : W2lo);
    const float* bias        = (z == 0) ? b0   : ((z == 1) ? b1   : b2);
    float* C                 = (z == 0) ? C0   : ((z == 1) ? C1   : C2);

    const int bm = blockIdx.y * 128;
    const int bn = blockIdx.x * 128;
    const int warpM = wid >> 2;       // 0..1 -> m offset *64
    const int warpN = wid & 3;        // 0..3 -> n offset *32

    float acc[4][4][4];
#pragma unroll
    for (int i = 0; i < 4; i++)
#pragma unroll
        for (int j = 0; j < 4; j++)
#pragma unroll
            for (int k = 0; k < 4; k++) acc[i][j][k] = 0.0f;

    // ---- per-lane ldmatrix address components ----
    const int l8  = lid & 7;          // row-in-8
    const int mid = lid >> 3;         // matrix id 0..3
    // A: mats (rows m0-7 k0 | m8-15 k0 | m0-7 k1 | m8-15 k1)
    const int a_cb   = mid >> 1;
    const int a_rowl = warpM * 64 + l8 + (mid & 1) * 8;
    // B: mats (n0-7 k0 | n0-7 k1 | n8-15 k0 | n8-15 k1)
    const int b_cb   = mid & 1;
    const int b_rowl = warpN * 32 + l8 + (mid >> 1) * 8;

    uint32_t a_row_off[4], b_row_off[2];
#pragma unroll
    for (int mt = 0; mt < 4; ++mt) a_row_off[mt] = (uint32_t)(a_rowl + mt * 16) * 128u;
#pragma unroll
    for (int j = 0; j < 2; ++j)    b_row_off[j]  = (uint32_t)(b_rowl + j * 16) * 128u;

    uint32_t a_swz[4], b_swz[4];
#pragma unroll
    for (int ks = 0; ks < 4; ++ks) {
        a_swz[ks] = (uint32_t)(((ks * 2 + a_cb) ^ l8) * 16);
        b_swz[ks] = (uint32_t)(((ks * 2 + b_cb) ^ l8) * 16);
    }

    auto load_chunk = [&](int c) {
        const uint32_t st = sbase + (uint32_t)(c & 1) * STAGE_B;
        const int k0 = c * 64;
        load_tile_cp(Ahi, bm, k0, st,         t);
        load_tile_cp(Alo, bm, k0, st + 16384, t);
        load_tile_cp(Whi, bn, k0, st + 32768, t);
        load_tile_cp(Wlo, bn, k0, st + 49152, t);
        CP_COMMIT();
    };

    load_chunk(0);

    for (int c = 0; c < 32; ++c) {
        if (c + 1 < 32) { load_chunk(c + 1); CP_WAIT(1); }
        else            { CP_WAIT(0); }
        __syncthreads();

        const uint32_t st = sbase + (uint32_t)(c & 1) * STAGE_B;
        const uint32_t pA[3] = { st,         st,         st + 16384 };  // hi, hi, lo
        const uint32_t pB[3] = { st + 32768, st + 49152, st + 32768 };  // hi, lo, hi

#pragma unroll
        for (int p = 0; p < 3; ++p) {
#pragma unroll
            for (int ks = 0; ks < 4; ++ks) {
                uint32_t af[4][4];
#pragma unroll
                for (int mt = 0; mt < 4; ++mt)
                    ldsm_x4(af[mt], pA[p] + a_row_off[mt] + a_swz[ks]);
                uint32_t bf[2][4];
#pragma unroll
                for (int j = 0; j < 2; ++j)
                    ldsm_x4(bf[j], pB[p] + b_row_off[j] + b_swz[ks]);
#pragma unroll
                for (int mt = 0; mt < 4; ++mt)
#pragma unroll
                    for (int nt = 0; nt < 4; ++nt)
                        mma16816(acc[mt][nt], af[mt], &bf[nt >> 1][(nt & 1) * 2]);
            }
        }
        __syncthreads();
    }

    // ---- epilogue: bias + store ----
    const int lr  = lid >> 2;
    const int lc2 = (lid & 3) * 2;
    float2 bias2[4];
#pragma unroll
    for (int nt = 0; nt < 4; ++nt) {
        const int col = bn + warpN * 32 + nt * 8 + lc2;
        bias2[nt].x = __ldg(&bias[col]);
        bias2[nt].y = __ldg(&bias[col + 1]);
    }
#pragma unroll
    for (int mt = 0; mt < 4; ++mt) {
        const int row0 = bm + warpM * 64 + mt * 16 + lr;
#pragma unroll
        for (int nt = 0; nt < 4; ++nt) {
            const int col = bn + warpN * 32 + nt * 8 + lc2;
            float2 v0, v1;
            v0.x = acc[mt][nt][0] + bias2[nt].x;
            v0.y = acc[mt][nt][1] + bias2[nt].y;
            v1.x = acc[mt][nt][2] + bias2[nt].x;
            v1.y = acc[mt][nt][3] + bias2[nt].y;
            *(float2*)(C + (size_t)row0 * DD + col)       = v0;
            *(float2*)(C + (size_t)(row0 + 8) * DD + col) = v1;
        }
    }
}

// ---------------------------------------------------------------------------
// Causal flash attention, fp32 (unchanged passing version)
// ---------------------------------------------------------------------------
#define BQ 128
#define BS 64

__global__ __launch_bounds__(256, 1)
void attn_kernel()
{
    extern __shared__ float sm[];
    float* Qs = sm;                  // 128 * 132
    float* Ks = Qs + 128 * 132;      // 128 * 68
    float* Vs = Ks + 128 * 68;       // 64 * 132
    float* Ps = Vs + 64 * 132;       // 64 * 132

    const int t  = threadIdx.x;
    const int tx = t & 15;
    const int ty = t >> 4;
    const int h  = blockIdx.x & 15;
    const int qb = 15 - (blockIdx.x >> 4);
    const int q0 = qb * BQ;
    const float qscale = 0.08838834764831845f * 1.4426950408889634f;

    {
        const int q   = t & 127;
        const int d4b = t >> 7;
        const float* gq = g_Q + (size_t)(q0 + q) * DD + h * DHH;
#pragma unroll
        for (int i = 0; i < 16; ++i) {
            const int d4 = d4b + 2 * i;
            float4 v = *(const float4*)(gq + 4 * d4);
            float* p = &Qs[(4 * d4) * 132 + q];
            p[0]       = v.x * qscale;
            p[132]     = v.y * qscale;
            p[2 * 132] = v.z * qscale;
            p[3 * 132] = v.w * qscale;
        }
    }

    float oacc[8][8];
#pragma unroll
    for (int i = 0; i < 8; i++)
#pragma unroll
        for (int j = 0; j < 8; j++) oacc[i][j] = 0.0f;
    float mrow[8], lrow[8];
#pragma unroll
    for (int i = 0; i < 8; i++) { mrow[i] = -1e30f; lrow[i] = 0.0f; }

    const int nkb = 2 * (qb + 1);
    for (int kb = 0; kb < nkb; ++kb) {
        __syncthreads();

        {
            const int s   = t & 63;
            const int d4b = t >> 6;
            const float* gk = g_K + (size_t)(kb * BS + s) * DD + h * DHH;
#pragma unroll
            for (int i = 0; i < 8; ++i) {
                const int d4 = d4b + 4 * i;
                float4 v = *(const float4*)(gk + 4 * d4);
                float* p = &Ks[(4 * d4) * 68 + s];
                p[0]  = v.x; p[68]  = v.y; p[136] = v.z; p[204] = v.w;
            }
        }
        {
#pragma unroll
            for (int i = 0; i < 8; ++i) {
                const int e = t + 256 * i;
                const int s = e >> 5, d4 = e & 31;
                float4 v = *(const float4*)(g_V + (size_t)(kb * BS + s) * DD + h * DHH + 4 * d4);
                *(float4*)&Vs[s * 132 + 4 * d4] = v;
            }
        }
        __syncthreads();

        float sacc[8][4];
#pragma unroll
        for (int i = 0; i < 8; i++)
#pragma unroll
            for (int j = 0; j < 4; j++) sacc[i][j] = 0.0f;

#pragma unroll 8
        for (int d = 0; d < 128; ++d) {
            float4 a0 = *(const float4*)&Qs[d * 132 + (ty << 2)];
            float4 a1 = *(const float4*)&Qs[d * 132 + 64 + (ty << 2)];
            float4 b  = *(const float4*)&Ks[d * 68 + (tx << 2)];
            float av[8] = {a0.x, a0.y, a0.z, a0.w, a1.x, a1.y, a1.z, a1.w};
            float bv[4] = {b.x, b.y, b.z, b.w};
#pragma unroll
            for (int i = 0; i < 8; i++)
#pragma unroll
                for (int j = 0; j < 4; j++) sacc[i][j] += av[i] * bv[j];
        }

        if (kb >= 2 * qb) {
#pragma unroll
            for (int i = 0; i < 8; i++) {
                const int row = q0 + ((i < 4) ? (4 * ty + i) : (64 + 4 * ty + i - 4));
#pragma unroll
                for (int j = 0; j < 4; j++) {
                    const int col = kb * BS + 4 * tx + j;
                    if (col > row) sacc[i][j] = -1e30f;
                }
            }
        }

#pragma unroll
        for (int i = 0; i < 8; i++) {
            float mx = fmaxf(fmaxf(sacc[i][0], sacc[i][1]),
                             fmaxf(sacc[i][2], sacc[i][3]));
#pragma unroll
            for (int o = 8; o > 0; o >>= 1)
                mx = fmaxf(mx, __shfl_xor_sync(0xffffffffu, mx, o));
            const float mnew  = fmaxf(mrow[i], mx);
            const float alpha = exp2f(mrow[i] - mnew);
            float sum = 0.0f;
#pragma unroll
            for (int j = 0; j < 4; j++) {
                const float p = exp2f(sacc[i][j] - mnew);
                sacc[i][j] = p;
                sum += p;
            }
#pragma unroll
            for (int o = 8; o > 0; o >>= 1)
                sum += __shfl_xor_sync(0xffffffffu, sum, o);
            lrow[i] = lrow[i] * alpha + sum;
            mrow[i] = mnew;
#pragma unroll
            for (int j = 0; j < 8; j++) oacc[i][j] *= alpha;
        }

#pragma unroll
        for (int i = 0; i < 8; i++) {
            const int row = (i < 4) ? (4 * ty + i) : (64 + 4 * ty + i - 4);
#pragma unroll
            for (int j = 0; j < 4; j++)
                Ps[(4 * tx + j) * 132 + row] = sacc[i][j];
        }
        __syncthreads();

#pragma unroll 4
        for (int s = 0; s < 64; ++s) {
            float4 a0 = *(const float4*)&Ps[s * 132 + (ty << 2)];
            float4 a1 = *(const float4*)&Ps[s * 132 + 64 + (ty << 2)];
            float4 b0 = *(const float4*)&Vs[s * 132 + (tx << 2)];
            float4 b1 = *(const float4*)&Vs[s * 132 + 64 + (tx << 2)];
            float av[8] = {a0.x, a0.y, a0.z, a0.w, a1.x, a1.y, a1.z, a1.w};
            float bv[8] = {b0.x, b0.y, b0.z, b0.w, b1.x, b1.y, b1.z, b1.w};
#pragma unroll
            for (int i = 0; i < 8; i++)
#pragma unroll
                for (int j = 0; j < 8; j++) oacc[i][j] += av[i] * bv[j];
        }
    }

#pragma unroll
    for (int i = 0; i < 8; i++) {
        const int ri  = (i < 4) ? (4 * ty + i) : (64 + 4 * ty + i - 4);
        const float inv = 1.0f / lrow[i];
        float* gy = g_Y + (size_t)(q0 + ri) * DD + h * DHH;
        float4 v0, v1;
        v0.x = oacc[i][0] * inv; v0.y = oacc[i][1] * inv;
        v0.z = oacc[i][2] * inv; v0.w = oacc[i][3] * inv;
        v1.x = oacc[i][4] * inv; v1.y = oacc[i][5] * inv;
        v1.z = oacc[i][6] * inv; v1.w = oacc[i][7] * inv;
        *(float4*)(gy + (tx << 2))      = v0;
        *(float4*)(gy + 64 + (tx << 2)) = v1;
    }
}

// ---------------------------------------------------------------------------
// Launch
// ---------------------------------------------------------------------------
extern "C" void kernel_launch(void* const* d_in, const int* in_sizes, int n_in,
                              void* d_out, int out_size)
{
    const float* x  = (const float*)d_in[0];
    const float* Wq = (const float*)d_in[1];
    const float* bq = (const float*)d_in[2];
    const float* Wk = (const float*)d_in[3];
    const float* bk = (const float*)d_in[4];
    const float* Wv = (const float*)d_in[5];
    const float* bv = (const float*)d_in[6];
    const float* Wo = (const float*)d_in[7];
    const float* bo = (const float*)d_in[8];
    float* out = (float*)d_out;

    float *Qp, *Kp, *Vp, *Yp;
    cudaGetSymbolAddress((void**)&Qp, g_Q);
    cudaGetSymbolAddress((void**)&Kp, g_K);
    cudaGetSymbolAddress((void**)&Vp, g_V);
    cudaGetSymbolAddress((void**)&Yp, g_Y);

    __nv_bfloat16 *xhi, *xlo, *wqh, *wql, *wkh, *wkl, *wvh, *wvl, *woh, *wol, *yhi, *ylo;
    cudaGetSymbolAddress((void**)&xhi, g_x_hi);  cudaGetSymbolAddress((void**)&xlo, g_x_lo);
    cudaGetSymbolAddress((void**)&wqh, g_Wq_hi); cudaGetSymbolAddress((void**)&wql, g_Wq_lo);
    cudaGetSymbolAddress((void**)&wkh, g_Wk_hi); cudaGetSymbolAddress((void**)&wkl, g_Wk_lo);
    cudaGetSymbolAddress((void**)&wvh, g_Wv_hi); cudaGetSymbolAddress((void**)&wvl, g_Wv_lo);
    cudaGetSymbolAddress((void**)&woh, g_Wo_hi); cudaGetSymbolAddress((void**)&wol, g_Wo_lo);
    cudaGetSymbolAddress((void**)&yhi, g_Y_hi);  cudaGetSymbolAddress((void**)&ylo, g_Y_lo);

    const int SMEM_ATTN = (128 * 132 + 128 * 68 + 64 * 132 + 64 * 132) * (int)sizeof(float);
    cudaFuncSetAttribute(attn_kernel, cudaFuncAttributeMaxDynamicSharedMemorySize, SMEM_ATTN);
    cudaFuncSetAttribute(gemm_mma, cudaFuncAttributeMaxDynamicSharedMemorySize, GEMM_SMEM);

    const int nsplit = (TT * DD / 4) / 256;  // 4096 blocks
    split_kernel<<<nsplit, 256>>>(x,  xhi, xlo);
    split_kernel<<<nsplit, 256>>>(Wq, wqh, wql);
    split_kernel<<<nsplit, 256>>>(Wk, wkh, wkl);
    split_kernel<<<nsplit, 256>>>(Wv, wvh, wvl);
    split_kernel<<<nsplit, 256>>>(Wo, woh, wol);

    // fused QKV projection: z=0 -> Q, z=1 -> K, z=2 -> V
    gemm_mma<<<dim3(16, 16, 3), 256, GEMM_SMEM>>>(xhi, xlo,
                                                  wqh, wql, bq, Qp,
                                                  wkh, wkl, bk, Kp,
                                                  wvh, wvl, bv, Vp);

    attn_kernel<<<256, 256, SMEM_ATTN>>>();

    split_kernel<<<nsplit, 256>>>(Yp, yhi, ylo);
    gemm_mma<<<dim3(16, 16, 1), 256, GEMM_SMEM>>>(yhi, ylo,
                                                  woh, wol, bo, out,
                                                  woh, wol, bo, out,
                                                  woh, wol, bo, out);
}

// round 5
// speedup vs baseline: 2.6495x; 1.5060x over previous
#include <cuda_runtime.h>
#include <cuda_bf16.h>
#include <math.h>
#include <stdint.h>

// Problem constants
#define TT 2048
#define DD 2048
#define HH 16
#define DHH 128

// ---------------------------------------------------------------------------
// Scratch (__device__ globals; allocation-free rule)
// ---------------------------------------------------------------------------
__device__ __nv_bfloat16 g_x_hi[TT * DD], g_x_lo[TT * DD];
__device__ __nv_bfloat16 g_Wq_hi[DD * DD], g_Wq_lo[DD * DD];
__device__ __nv_bfloat16 g_Wk_hi[DD * DD], g_Wk_lo[DD * DD];
__device__ __nv_bfloat16 g_Wv_hi[DD * DD], g_Wv_lo[DD * DD];
__device__ __nv_bfloat16 g_Wo_hi[DD * DD], g_Wo_lo[DD * DD];
__device__ __nv_bfloat16 g_Qhi[TT * DD], g_Qlo[TT * DD];
__device__ __nv_bfloat16 g_Khi[TT * DD], g_Klo[TT * DD];
__device__ __nv_bfloat16 g_Vhi[TT * DD], g_Vlo[TT * DD];
__device__ __nv_bfloat16 g_Yhi[TT * DD], g_Ylo[TT * DD];

// ---------------------------------------------------------------------------
// sm_80-ISA helpers (ptxas target here is sm_100 baseline: no tcgen05)
// ---------------------------------------------------------------------------
__device__ __forceinline__ uint32_t smem_to_u32(const void* p) {
    uint32_t a;
    asm("{ .reg .u64 t; cvta.to.shared.u64 t, %1; cvt.u32.u64 %0, t; }"
        : "=r"(a) : "l"(p));
    return a;
}
__device__ __forceinline__ void cp16(uint32_t dst, const void* src) {
    asm volatile("cp.async.cg.shared.global [%0], [%1], 16;"
                 :: "r"(dst), "l"(src) : "memory");
}
#define CP_COMMIT() asm volatile("cp.async.commit_group;" ::: "memory")
#define CP_WAIT(n)  asm volatile("cp.async.wait_group %0;" :: "n"(n) : "memory")

__device__ __forceinline__ void ldsm_x4(uint32_t* r, uint32_t addr) {
    asm volatile("ldmatrix.sync.aligned.m8n8.x4.shared.b16 {%0,%1,%2,%3}, [%4];"
                 : "=r"(r[0]), "=r"(r[1]), "=r"(r[2]), "=r"(r[3]) : "r"(addr));
}
__device__ __forceinline__ void ldsm_x4_t(uint32_t* r, uint32_t addr) {
    asm volatile("ldmatrix.sync.aligned.m8n8.x4.trans.shared.b16 {%0,%1,%2,%3}, [%4];"
                 : "=r"(r[0]), "=r"(r[1]), "=r"(r[2]), "=r"(r[3]) : "r"(addr));
}
__device__ __forceinline__ void mma16816(float* d, const uint32_t* a, const uint32_t* b) {
    asm volatile(
        "mma.sync.aligned.m16n8k16.row.col.f32.bf16.bf16.f32 "
        "{%0,%1,%2,%3}, {%4,%5,%6,%7}, {%8,%9}, {%0,%1,%2,%3};"
        : "+f"(d[0]), "+f"(d[1]), "+f"(d[2]), "+f"(d[3])
        : "r"(a[0]), "r"(a[1]), "r"(a[2]), "r"(a[3]), "r"(b[0]), "r"(b[1]));
}
__device__ __forceinline__ float ex2a(float x) {
    float y;
    asm("ex2.approx.ftz.f32 %0, %1;" : "=f"(y) : "f"(x));
    return y;
}
__device__ __forceinline__ uint32_t pack_bf16(float lo, float hi) {
    __nv_bfloat162 v = __float22bfloat162_rn(make_float2(lo, hi));
    return *(uint32_t*)&v;
}
// residual pair: given packed hi bf16x2 and the two floats, pack bf16 residuals
__device__ __forceinline__ uint32_t pack_bf16_res(uint32_t hipk, float lo, float hi) {
    float f0 = __uint_as_float(hipk << 16);
    float f1 = __uint_as_float(hipk & 0xffff0000u);
    return pack_bf16(lo - f0, hi - f1);
}

#define SCALE_Q (0.08838834764831845f * 1.4426950408889634f)

// ---------------------------------------------------------------------------
// split: fp32 -> (bf16 hi, bf16 lo)
// ---------------------------------------------------------------------------
__global__ void split_kernel(const float* __restrict__ src,
                             __nv_bfloat16* __restrict__ hi,
                             __nv_bfloat16* __restrict__ lo)
{
    const int i = blockIdx.x * blockDim.x + threadIdx.x;
    float4 v = ((const float4*)src)[i];
    union { __nv_bfloat16 b[4]; uint2 u; } H, L;
    H.b[0] = __float2bfloat16(v.x); L.b[0] = __float2bfloat16(v.x - __bfloat162float(H.b[0]));
    H.b[1] = __float2bfloat16(v.y); L.b[1] = __float2bfloat16(v.y - __bfloat162float(H.b[1]));
    H.b[2] = __float2bfloat16(v.z); L.b[2] = __float2bfloat16(v.z - __bfloat162float(H.b[2]));
    H.b[3] = __float2bfloat16(v.w); L.b[3] = __float2bfloat16(v.w - __bfloat162float(H.b[3]));
    ((uint2*)hi)[i] = H.u;
    ((uint2*)lo)[i] = L.u;
}

// ---------------------------------------------------------------------------
// mma.sync GEMM: C = A @ W^T + bias (split bf16, fp32 accum)
// Epilogue: either fp32 store (Cf) or split-bf16 store (Chi/Clo, scaled).
// ---------------------------------------------------------------------------
#define STAGE_B   65536
#define GEMM_SMEM (2 * STAGE_B)

__device__ __forceinline__ void load_tile_cp(const __nv_bfloat16* __restrict__ g,
                                             int row0, int k0, uint32_t sdst, int t)
{
#pragma unroll
    for (int i = t; i < 1024; i += 256) {
        const int r = i >> 3, c = i & 7;
        cp16(sdst + r * 128 + ((c ^ (r & 7)) * 16),
             g + (size_t)(row0 + r) * DD + k0 + c * 8);
    }
}

__global__ __launch_bounds__(256, 1)
void gemm_mma(const __nv_bfloat16* __restrict__ Ahi, const __nv_bfloat16* __restrict__ Alo,
              const __nv_bfloat16* __restrict__ W0hi, const __nv_bfloat16* __restrict__ W0lo,
              const float* __restrict__ b0, float* Cf0, __nv_bfloat16* Chi0, __nv_bfloat16* Clo0, float cs0,
              const __nv_bfloat16* __restrict__ W1hi, const __nv_bfloat16* __restrict__ W1lo,
              const float* __restrict__ b1, float* Cf1, __nv_bfloat16* Chi1, __nv_bfloat16* Clo1, float cs1,
              const __nv_bfloat16* __restrict__ W2hi, const __nv_bfloat16* __restrict__ W2lo,
              const float* __restrict__ b2, float* Cf2, __nv_bfloat16* Chi2, __nv_bfloat16* Clo2, float cs2)
{
    extern __shared__ __align__(1024) char smem[];
    const uint32_t sbase = smem_to_u32(smem);
    const int t   = threadIdx.x;
    const int wid = t >> 5;
    const int lid = t & 31;
    const int z   = blockIdx.z;

    const __nv_bfloat16* Whi = (z == 0) ? W0hi : ((z == 1) ? W1hi : W2hi);
    const __nv_bfloat16* Wlo = (z == 0) ? W0lo : ((z == 1) ? W1lo : W2lo);
    const float* bias        = (z == 0) ? b0   : ((z == 1) ? b1   : b2);
    float* Cf                = (z == 0) ? Cf0  : ((z == 1) ? Cf1  : Cf2);
    __nv_bfloat16* Chi       = (z == 0) ? Chi0 : ((z == 1) ? Chi1 : Chi2);
    __nv_bfloat16* Clo       = (z == 0) ? Clo0 : ((z == 1) ? Clo1 : Clo2);
    const float cs           = (z == 0) ? cs0  : ((z == 1) ? cs1  : cs2);

    const int bm = blockIdx.y * 128;
    const int bn = blockIdx.x * 128;
    const int warpM = wid >> 2;
    const int warpN = wid & 3;

    float acc[4][4][4];
#pragma unroll
    for (int i = 0; i < 4; i++)
#pragma unroll
        for (int j = 0; j < 4; j++)
#pragma unroll
            for (int k = 0; k < 4; k++) acc[i][j][k] = 0.0f;

    const int l8  = lid & 7;
    const int mid = lid >> 3;
    const int a_cb   = mid >> 1;
    const int a_rowl = warpM * 64 + l8 + (mid & 1) * 8;
    const int b_cb   = mid & 1;
    const int b_rowl = warpN * 32 + l8 + (mid >> 1) * 8;

    uint32_t a_row_off[4], b_row_off[2];
#pragma unroll
    for (int mt = 0; mt < 4; ++mt) a_row_off[mt] = (uint32_t)(a_rowl + mt * 16) * 128u;
#pragma unroll
    for (int j = 0; j < 2; ++j)    b_row_off[j]  = (uint32_t)(b_rowl + j * 16) * 128u;

    uint32_t a_swz[4], b_swz[4];
#pragma unroll
    for (int ks = 0; ks < 4; ++ks) {
        a_swz[ks] = (uint32_t)(((ks * 2 + a_cb) ^ l8) * 16);
        b_swz[ks] = (uint32_t)(((ks * 2 + b_cb) ^ l8) * 16);
    }

    auto load_chunk = [&](int c) {
        const uint32_t st = sbase + (uint32_t)(c & 1) * STAGE_B;
        const int k0 = c * 64;
        load_tile_cp(Ahi, bm, k0, st,         t);
        load_tile_cp(Alo, bm, k0, st + 16384, t);
        load_tile_cp(Whi, bn, k0, st + 32768, t);
        load_tile_cp(Wlo, bn, k0, st + 49152, t);
        CP_COMMIT();
    };

    load_chunk(0);

    for (int c = 0; c < 32; ++c) {
        if (c + 1 < 32) { load_chunk(c + 1); CP_WAIT(1); }
        else            { CP_WAIT(0); }
        __syncthreads();

        const uint32_t st = sbase + (uint32_t)(c & 1) * STAGE_B;
#pragma unroll
        for (int ks = 0; ks < 4; ++ks) {
            uint32_t ah[4][4], al[4][4];
#pragma unroll
            for (int mt = 0; mt < 4; ++mt) {
                ldsm_x4(ah[mt], st +         a_row_off[mt] + a_swz[ks]);
                ldsm_x4(al[mt], st + 16384 + a_row_off[mt] + a_swz[ks]);
            }
            uint32_t bh[2][4], bl[2][4];
#pragma unroll
            for (int j = 0; j < 2; ++j) {
                ldsm_x4(bh[j], st + 32768 + b_row_off[j] + b_swz[ks]);
                ldsm_x4(bl[j], st + 49152 + b_row_off[j] + b_swz[ks]);
            }
#pragma unroll
            for (int mt = 0; mt < 4; ++mt)
#pragma unroll
                for (int nt = 0; nt < 4; ++nt) {
                    mma16816(acc[mt][nt], ah[mt], &bh[nt >> 1][(nt & 1) * 2]);
                    mma16816(acc[mt][nt], ah[mt], &bl[nt >> 1][(nt & 1) * 2]);
                    mma16816(acc[mt][nt], al[mt], &bh[nt >> 1][(nt & 1) * 2]);
                }
        }
        __syncthreads();
    }

    // ---- epilogue ----
    const int lr  = lid >> 2;
    const int lc2 = (lid & 3) * 2;
    float2 bias2[4];
#pragma unroll
    for (int nt = 0; nt < 4; ++nt) {
        const int col = bn + warpN * 32 + nt * 8 + lc2;
        bias2[nt].x = __ldg(&bias[col]);
        bias2[nt].y = __ldg(&bias[col + 1]);
    }
#pragma unroll
    for (int mt = 0; mt < 4; ++mt) {
        const int row0 = bm + warpM * 64 + mt * 16 + lr;
#pragma unroll
        for (int nt = 0; nt < 4; ++nt) {
            const int col = bn + warpN * 32 + nt * 8 + lc2;
            float o0 = acc[mt][nt][0] + bias2[nt].x;
            float o1 = acc[mt][nt][1] + bias2[nt].y;
            float o2 = acc[mt][nt][2] + bias2[nt].x;
            float o3 = acc[mt][nt][3] + bias2[nt].y;
            if (Cf) {
                *(float2*)(Cf + (size_t)row0 * DD + col)       = make_float2(o0, o1);
                *(float2*)(Cf + (size_t)(row0 + 8) * DD + col) = make_float2(o2, o3);
            } else {
                o0 *= cs; o1 *= cs; o2 *= cs; o3 *= cs;
                uint32_t h0 = pack_bf16(o0, o1);
                uint32_t h1 = pack_bf16(o2, o3);
                *(uint32_t*)(Chi + (size_t)row0 * DD + col)       = h0;
                *(uint32_t*)(Chi + (size_t)(row0 + 8) * DD + col) = h1;
                *(uint32_t*)(Clo + (size_t)row0 * DD + col)       = pack_bf16_res(h0, o0, o1);
                *(uint32_t*)(Clo + (size_t)(row0 + 8) * DD + col) = pack_bf16_res(h1, o2, o3);
            }
        }
    }
}

// ---------------------------------------------------------------------------
// Flash attention, mma.sync split-bf16, fp32 softmax (MUFU EX2).
// CTA = (head, 128-query block). 8 warps, each owns 16 query rows.
// smem: Qhi|Qlo (64KB) + 2 stages of Khi|Klo|Vhi|Vlo (64KB each) = 192KB.
// Rows are 256B (128 bf16), 16B-unit XOR-swizzled: unit c -> c ^ (row&7).
// ---------------------------------------------------------------------------
#define ABS 64
#define A_QHI    0
#define A_QLO    32768
#define A_STAGES 65536
#define A_STAGE  65536
#define ATTN_SMEM (A_STAGES + 2 * A_STAGE)   // 196608

__device__ __forceinline__ void attn_load_kv(uint32_t stbase, int kb, int h, int t)
{
    const int s0 = kb * ABS;
#pragma unroll
    for (int i = t; i < 4096; i += 256) {
        const int tensor = i >> 10;          // 0 Khi, 1 Klo, 2 Vhi, 3 Vlo
        const int r = (i >> 4) & 63;
        const int c = i & 15;
        const __nv_bfloat16* g = (tensor == 0) ? g_Khi : (tensor == 1) ? g_Klo
                               : (tensor == 2) ? g_Vhi : g_Vlo;
        cp16(stbase + tensor * 16384 + r * 256 + ((c ^ (r & 7)) << 4),
             g + (size_t)(s0 + r) * DD + h * DHH + c * 8);
    }
    CP_COMMIT();
}

__global__ __launch_bounds__(256, 1)
void attn_mma()
{
    extern __shared__ __align__(1024) char smem[];
    const uint32_t sb = smem_to_u32(smem);
    const int t   = threadIdx.x;
    const int wid = t >> 5;
    const int lid = t & 31;
    const int l8  = lid & 7;
    const int mid = lid >> 3;
    const int h   = blockIdx.x & 15;
    const int qb  = 15 - (blockIdx.x >> 4);   // heavy blocks first
    const int q0  = qb * 128;

    // ---- Q tiles (hi|lo), own cp.async group ----
#pragma unroll
    for (int i = t; i < 4096; i += 256) {
        const int tensor = i >> 11;
        const int r = (i >> 4) & 127;
        const int c = i & 15;
        const __nv_bfloat16* g = tensor ? g_Qlo : g_Qhi;
        cp16(sb + A_QHI + tensor * 32768 + r * 256 + ((c ^ (r & 7)) << 4),
             g + (size_t)(q0 + r) * DD + h * DHH + c * 8);
    }
    CP_COMMIT();

    attn_load_kv(sb + A_STAGES, 0, h, t);

    float oacc[16][4];
#pragma unroll
    for (int i = 0; i < 16; i++)
#pragma unroll
        for (int j = 0; j < 4; j++) oacc[i][j] = 0.0f;
    float mrow0 = -1e30f, mrow1 = -1e30f, lrow0 = 0.0f, lrow1 = 0.0f;

    const int nkb = 2 * (qb + 1);
    for (int kb = 0; kb < nkb; ++kb) {
        if (kb + 1 < nkb) { attn_load_kv(sb + A_STAGES + ((kb + 1) & 1) * A_STAGE, kb + 1, h, t); CP_WAIT(1); }
        else              { CP_WAIT(0); }
        __syncthreads();

        const uint32_t st = sb + A_STAGES + (uint32_t)(kb & 1) * A_STAGE;
        // warp fully masked (all its rows < first key of this block)?
        const bool active = (kb * ABS <= q0 + wid * 16 + 15);
        if (active) {
            // ---- S = Qs . K^T (3-pass split) ----
            float sacc[8][4];
#pragma unroll
            for (int i = 0; i < 8; i++)
#pragma unroll
                for (int j = 0; j < 4; j++) sacc[i][j] = 0.0f;

#pragma unroll
            for (int ks = 0; ks < 8; ++ks) {
                const int qrow = wid * 16 + (lid & 15);
                const uint32_t qc = (uint32_t)(2 * ks + (lid >> 4));
                const uint32_t qoff = (uint32_t)qrow * 256 + (((qc ^ (qrow & 7))) << 4);
                uint32_t ah[4], al[4];
                ldsm_x4(ah, sb + A_QHI + qoff);
                ldsm_x4(al, sb + A_QLO + qoff);
                uint32_t bh[4][4], bl[4][4];
#pragma unroll
                for (int j = 0; j < 4; ++j) {
                    const int krow = j * 16 + l8 + (mid >> 1) * 8;
                    const uint32_t kc = (uint32_t)(2 * ks + (mid & 1));
                    const uint32_t koff = (uint32_t)krow * 256 + (((kc ^ (krow & 7))) << 4);
                    ldsm_x4(bh[j], st + koff);            // Khi
                    ldsm_x4(bl[j], st + 16384 + koff);    // Klo
                }
#pragma unroll
                for (int j = 0; j < 4; ++j)
#pragma unroll
                    for (int e = 0; e < 2; ++e) {
                        mma16816(sacc[2 * j + e], ah, &bh[j][2 * e]);
                        mma16816(sacc[2 * j + e], ah, &bl[j][2 * e]);
                        mma16816(sacc[2 * j + e], al, &bh[j][2 * e]);
                    }
            }

            // ---- causal mask (diagonal blocks only) ----
            const int rlo = q0 + wid * 16 + (lid >> 2);
            const int rhi = rlo + 8;
            if (kb >= 2 * qb) {
#pragma unroll
                for (int nt = 0; nt < 8; ++nt) {
                    const int c0 = kb * ABS + nt * 8 + (lid & 3) * 2;
                    if (c0 > rlo)     sacc[nt][0] = -1e30f;
                    if (c0 + 1 > rlo) sacc[nt][1] = -1e30f;
                    if (c0 > rhi)     sacc[nt][2] = -1e30f;
                    if (c0 + 1 > rhi) sacc[nt][3] = -1e30f;
                }
            }

            // ---- online softmax (log2 domain) ----
            float mx0 = -1e30f, mx1 = -1e30f;
#pragma unroll
            for (int nt = 0; nt < 8; ++nt) {
                mx0 = fmaxf(mx0, fmaxf(sacc[nt][0], sacc[nt][1]));
                mx1 = fmaxf(mx1, fmaxf(sacc[nt][2], sacc[nt][3]));
            }
            mx0 = fmaxf(mx0, __shfl_xor_sync(0xffffffffu, mx0, 1));
            mx0 = fmaxf(mx0, __shfl_xor_sync(0xffffffffu, mx0, 2));
            mx1 = fmaxf(mx1, __shfl_xor_sync(0xffffffffu, mx1, 1));
            mx1 = fmaxf(mx1, __shfl_xor_sync(0xffffffffu, mx1, 2));
            const float mnew0 = fmaxf(mrow0, mx0);
            const float mnew1 = fmaxf(mrow1, mx1);
            const float alpha0 = ex2a(mrow0 - mnew0);
            const float alpha1 = ex2a(mrow1 - mnew1);
            float sum0 = 0.0f, sum1 = 0.0f;
#pragma unroll
            for (int nt = 0; nt < 8; ++nt) {
                sacc[nt][0] = ex2a(sacc[nt][0] - mnew0); sum0 += sacc[nt][0];
                sacc[nt][1] = ex2a(sacc[nt][1] - mnew0); sum0 += sacc[nt][1];
                sacc[nt][2] = ex2a(sacc[nt][2] - mnew1); sum1 += sacc[nt][2];
                sacc[nt][3] = ex2a(sacc[nt][3] - mnew1); sum1 += sacc[nt][3];
            }
            sum0 += __shfl_xor_sync(0xffffffffu, sum0, 1);
            sum0 += __shfl_xor_sync(0xffffffffu, sum0, 2);
            sum1 += __shfl_xor_sync(0xffffffffu, sum1, 1);
            sum1 += __shfl_xor_sync(0xffffffffu, sum1, 2);
            lrow0 = lrow0 * alpha0 + sum0;  mrow0 = mnew0;
            lrow1 = lrow1 * alpha1 + sum1;  mrow1 = mnew1;
#pragma unroll
            for (int nt = 0; nt < 16; ++nt) {
                oacc[nt][0] *= alpha0; oacc[nt][1] *= alpha0;
                oacc[nt][2] *= alpha1; oacc[nt][3] *= alpha1;
            }

            // ---- O += P . V (3-pass split; P repacked from sacc) ----
#pragma unroll
            for (int ks = 0; ks < 4; ++ks) {
                uint32_t ph[4], pl[4];
#pragma unroll
                for (int half = 0; half < 2; ++half) {
                    const int nt2 = 2 * ks + half;
                    uint32_t h0 = pack_bf16(sacc[nt2][0], sacc[nt2][1]);
                    uint32_t h1 = pack_bf16(sacc[nt2][2], sacc[nt2][3]);
                    ph[2 * half]     = h0;
                    ph[2 * half + 1] = h1;
                    pl[2 * half]     = pack_bf16_res(h0, sacc[nt2][0], sacc[nt2][1]);
                    pl[2 * half + 1] = pack_bf16_res(h1, sacc[nt2][2], sacc[nt2][3]);
                }
#pragma unroll
                for (int half = 0; half < 2; ++half) {
                    uint32_t vh[4][4], vl[4][4];
#pragma unroll
                    for (int j = 0; j < 4; ++j) {
                        const int jj = half * 4 + j;
                        const int vrow = ks * 16 + l8 + (mid & 1) * 8;
                        const uint32_t vc = (uint32_t)(jj * 2 + (mid >> 1));
                        const uint32_t voff = (uint32_t)vrow * 256 + (((vc ^ (vrow & 7))) << 4);
                        ldsm_x4_t(vh[j], st + 32768 + voff);   // Vhi
                        ldsm_x4_t(vl[j], st + 49152 + voff);   // Vlo
                    }
#pragma unroll
                    for (int j = 0; j < 4; ++j) {
                        const int jj = half * 4 + j;
#pragma unroll
                        for (int e = 0; e < 2; ++e) {
                            mma16816(oacc[2 * jj + e], ph, &vh[j][2 * e]);
                            mma16816(oacc[2 * jj + e], ph, &vl[j][2 * e]);
                            mma16816(oacc[2 * jj + e], pl, &vh[j][2 * e]);
                        }
                    }
                }
            }
        }
        __syncthreads();
    }

    // ---- epilogue: O /= l, write Yhi/Ylo (bf16 split) ----
    const float inv0 = 1.0f / lrow0;
    const float inv1 = 1.0f / lrow1;
    const int r0 = q0 + wid * 16 + (lid >> 2);
    const int r1 = r0 + 8;
    const int colb = h * DHH + (lid & 3) * 2;
#pragma unroll
    for (int nt = 0; nt < 16; ++nt) {
        const int col = colb + nt * 8;
        float o0 = oacc[nt][0] * inv0, o1 = oacc[nt][1] * inv0;
        float o2 = oacc[nt][2] * inv1, o3 = oacc[nt][3] * inv1;
        uint32_t h0 = pack_bf16(o0, o1);
        uint32_t h1 = pack_bf16(o2, o3);
        *(uint32_t*)(g_Yhi + (size_t)r0 * DD + col) = h0;
        *(uint32_t*)(g_Yhi + (size_t)r1 * DD + col) = h1;
        *(uint32_t*)(g_Ylo + (size_t)r0 * DD + col) = pack_bf16_res(h0, o0, o1);
        *(uint32_t*)(g_Ylo + (size_t)r1 * DD + col) = pack_bf16_res(h1, o2, o3);
    }
}

// ---------------------------------------------------------------------------
// Launch
// ---------------------------------------------------------------------------
extern "C" void kernel_launch(void* const* d_in, const int* in_sizes, int n_in,
                              void* d_out, int out_size)
{
    const float* x  = (const float*)d_in[0];
    const float* Wq = (const float*)d_in[1];
    const float* bq = (const float*)d_in[2];
    const float* Wk = (const float*)d_in[3];
    const float* bk = (const float*)d_in[4];
    const float* Wv = (const float*)d_in[5];
    const float* bv = (const float*)d_in[6];
    const float* Wo = (const float*)d_in[7];
    const float* bo = (const float*)d_in[8];
    float* out = (float*)d_out;

    __nv_bfloat16 *xhi, *xlo, *wqh, *wql, *wkh, *wkl, *wvh, *wvl, *woh, *wol;
    __nv_bfloat16 *qhi, *qlo, *khi, *klo, *vhi, *vlo, *yhi, *ylo;
    cudaGetSymbolAddress((void**)&xhi, g_x_hi);  cudaGetSymbolAddress((void**)&xlo, g_x_lo);
    cudaGetSymbolAddress((void**)&wqh, g_Wq_hi); cudaGetSymbolAddress((void**)&wql, g_Wq_lo);
    cudaGetSymbolAddress((void**)&wkh, g_Wk_hi); cudaGetSymbolAddress((void**)&wkl, g_Wk_lo);
    cudaGetSymbolAddress((void**)&wvh, g_Wv_hi); cudaGetSymbolAddress((void**)&wvl, g_Wv_lo);
    cudaGetSymbolAddress((void**)&woh, g_Wo_hi); cudaGetSymbolAddress((void**)&wol, g_Wo_lo);
    cudaGetSymbolAddress((void**)&qhi, g_Qhi);   cudaGetSymbolAddress((void**)&qlo, g_Qlo);
    cudaGetSymbolAddress((void**)&khi, g_Khi);   cudaGetSymbolAddress((void**)&klo, g_Klo);
    cudaGetSymbolAddress((void**)&vhi, g_Vhi);   cudaGetSymbolAddress((void**)&vlo, g_Vlo);
    cudaGetSymbolAddress((void**)&yhi, g_Yhi);   cudaGetSymbolAddress((void**)&ylo, g_Ylo);

    cudaFuncSetAttribute(gemm_mma, cudaFuncAttributeMaxDynamicSharedMemorySize, GEMM_SMEM);
    cudaFuncSetAttribute(attn_mma, cudaFuncAttributeMaxDynamicSharedMemorySize, ATTN_SMEM);

    const int nsplit = (TT * DD / 4) / 256;
    split_kernel<<<nsplit, 256>>>(x,  xhi, xlo);
    split_kernel<<<nsplit, 256>>>(Wq, wqh, wql);
    split_kernel<<<nsplit, 256>>>(Wk, wkh, wkl);
    split_kernel<<<nsplit, 256>>>(Wv, wvh, wvl);
    split_kernel<<<nsplit, 256>>>(Wo, woh, wol);

    // fused QKV projection, epilogue emits split-bf16 (Q pre-scaled for softmax)
    gemm_mma<<<dim3(16, 16, 3), 256, GEMM_SMEM>>>(
        xhi, xlo,
        wqh, wql, bq, nullptr, qhi, qlo, SCALE_Q,
        wkh, wkl, bk, nullptr, khi, klo, 1.0f,
        wvh, wvl, bv, nullptr, vhi, vlo, 1.0f);

    attn_mma<<<256, 256, ATTN_SMEM>>>();

    // output projection, fp32 epilogue
    gemm_mma<<<dim3(16, 16, 1), 256, GEMM_SMEM>>>(
        yhi, ylo,
        woh, wol, bo, out, nullptr, nullptr, 1.0f,
        woh, wol, bo, out, nullptr, nullptr, 1.0f,
        woh, wol, bo, out, nullptr, nullptr, 1.0f);
}

// round 6
// speedup vs baseline: 3.6682x; 1.3845x over previous
#include <cuda_runtime.h>
#include <cuda_fp16.h>
#include <cuda_bf16.h>
#include <math.h>
#include <stdint.h>

// Problem constants
#define TT 2048
#define DD 2048
#define HH 16
#define DHH 128

// ---------------------------------------------------------------------------
// Scratch (__device__ globals; allocation-free rule).  All fp16.
// ---------------------------------------------------------------------------
__device__ __half g_xh[TT * DD], g_xl[TT * DD];          // x split pair
__device__ __half g_Wq_f[DD * DD], g_Wk_f[DD * DD];      // weights single fp16
__device__ __half g_Wv_f[DD * DD], g_Wo_f[DD * DD];
__device__ __half g_Qh[TT * DD], g_Ql[TT * DD];          // Q pair (pre-scaled)
__device__ __half g_Kf[TT * DD];                         // K single
__device__ __half g_Vh[TT * DD], g_Vl[TT * DD];          // V pair
__device__ __half g_Yh[TT * DD], g_Yl[TT * DD];          // attention out pair

// ---------------------------------------------------------------------------
// sm_80-ISA helpers (ptxas target here is sm_100 baseline: no tcgen05)
// ---------------------------------------------------------------------------
__device__ __forceinline__ uint32_t smem_to_u32(const void* p) {
    uint32_t a;
    asm("{ .reg .u64 t; cvta.to.shared.u64 t, %1; cvt.u32.u64 %0, t; }"
        : "=r"(a) : "l"(p));
    return a;
}
__device__ __forceinline__ void cp16(uint32_t dst, const void* src) {
    asm volatile("cp.async.cg.shared.global [%0], [%1], 16;"
                 :: "r"(dst), "l"(src) : "memory");
}
#define CP_COMMIT() asm volatile("cp.async.commit_group;" ::: "memory")
#define CP_WAIT(n)  asm volatile("cp.async.wait_group %0;" :: "n"(n) : "memory")

__device__ __forceinline__ void ldsm_x4(uint32_t* r, uint32_t addr) {
    asm volatile("ldmatrix.sync.aligned.m8n8.x4.shared.b16 {%0,%1,%2,%3}, [%4];"
                 : "=r"(r[0]), "=r"(r[1]), "=r"(r[2]), "=r"(r[3]) : "r"(addr));
}
__device__ __forceinline__ void ldsm_x4_t(uint32_t* r, uint32_t addr) {
    asm volatile("ldmatrix.sync.aligned.m8n8.x4.trans.shared.b16 {%0,%1,%2,%3}, [%4];"
                 : "=r"(r[0]), "=r"(r[1]), "=r"(r[2]), "=r"(r[3]) : "r"(addr));
}
__device__ __forceinline__ void mma16816(float* d, const uint32_t* a, const uint32_t* b) {
    asm volatile(
        "mma.sync.aligned.m16n8k16.row.col.f32.f16.f16.f32 "
        "{%0,%1,%2,%3}, {%4,%5,%6,%7}, {%8,%9}, {%0,%1,%2,%3};"
        : "+f"(d[0]), "+f"(d[1]), "+f"(d[2]), "+f"(d[3])
        : "r"(a[0]), "r"(a[1]), "r"(a[2]), "r"(a[3]), "r"(b[0]), "r"(b[1]));
}
__device__ __forceinline__ float ex2a(float x) {
    float y;
    asm("ex2.approx.ftz.f32 %0, %1;" : "=f"(y) : "f"(x));
    return y;
}
__device__ __forceinline__ uint32_t pack_h2(float a, float b) {
    __half2 v = __floats2half2_rn(a, b);
    return *(uint32_t*)&v;
}
__device__ __forceinline__ uint32_t pack_h2_res(uint32_t hipk, float a, float b) {
    __half2 h = *(__half2*)&hipk;
    return pack_h2(a - __half2float(__low2half(h)), b - __half2float(__high2half(h)));
}

#define SCALE_Q (0.08838834764831845f * 1.4426950408889634f)  // 1/sqrt(128)*log2(e)

// ---------------------------------------------------------------------------
// split pair: fp32 -> (fp16 hi, fp16 lo)
// ---------------------------------------------------------------------------
__global__ void split_pair(const float* __restrict__ src,
                           __half* __restrict__ hi, __half* __restrict__ lo)
{
    const int i = blockIdx.x * blockDim.x + threadIdx.x;
    float4 v = ((const float4*)src)[i];
    uint32_t h0 = pack_h2(v.x, v.y), h1 = pack_h2(v.z, v.w);
    ((uint2*)hi)[i] = make_uint2(h0, h1);
    ((uint2*)lo)[i] = make_uint2(pack_h2_res(h0, v.x, v.y), pack_h2_res(h1, v.z, v.w));
}

// convert 4 weight matrices fp32 -> fp16 single (z selects tensor)
__global__ void conv_f16(const float* __restrict__ s0, __half* __restrict__ d0,
                         const float* __restrict__ s1, __half* __restrict__ d1,
                         const float* __restrict__ s2, __half* __restrict__ d2,
                         const float* __restrict__ s3, __half* __restrict__ d3)
{
    const int z = blockIdx.y;
    const float* s = (z == 0) ? s0 : (z == 1) ? s1 : (z == 2) ? s2 : s3;
    __half* d      = (z == 0) ? d0 : (z == 1) ? d1 : (z == 2) ? d2 : d3;
    const int i = blockIdx.x * blockDim.x + threadIdx.x;
    float4 v = ((const float4*)s)[i];
    ((uint2*)d)[i] = make_uint2(pack_h2(v.x, v.y), pack_h2(v.z, v.w));
}

// ---------------------------------------------------------------------------
// 2-pass fp16 GEMM: C = (Ahi+Alo) @ Wf^T + bias, fp32 accum.
// CTA 128x128, BK=64, 8 warps (2x4), warp tile 64x32, cp.async double buffer.
// Epilogue modes: fp32 (Cf), fp16 pair (Chi+Clo, scaled), fp16 single (Chi).
// ---------------------------------------------------------------------------
#define STAGE_B   49152                // Ahi|Alo|Bf, 16KB each
#define GEMM_SMEM (2 * STAGE_B)

__device__ __forceinline__ void load_tile_cp(const __half* __restrict__ g,
                                             int row0, int k0, uint32_t sdst, int t)
{
#pragma unroll
    for (int i = t; i < 1024; i += 256) {
        const int r = i >> 3, c = i & 7;
        cp16(sdst + r * 128 + ((c ^ (r & 7)) * 16),
             g + (size_t)(row0 + r) * DD + k0 + c * 8);
    }
}

__global__ __launch_bounds__(256, 1)
void gemm_mma(const __half* __restrict__ Ahi, const __half* __restrict__ Alo,
              const __half* __restrict__ W0, const float* __restrict__ b0,
              float* Cf0, __half* Chi0, __half* Clo0, float cs0,
              const __half* __restrict__ W1, const float* __restrict__ b1,
              float* Cf1, __half* Chi1, __half* Clo1, float cs1,
              const __half* __restrict__ W2, const float* __restrict__ b2,
              float* Cf2, __half* Chi2, __half* Clo2, float cs2)
{
    extern __shared__ __align__(1024) char smem[];
    const uint32_t sbase = smem_to_u32(smem);
    const int t   = threadIdx.x;
    const int wid = t >> 5;
    const int lid = t & 31;
    const int z   = blockIdx.z;

    const __half* Wf   = (z == 0) ? W0   : ((z == 1) ? W1   : W2);
    const float* bias  = (z == 0) ? b0   : ((z == 1) ? b1   : b2);
    float* Cf          = (z == 0) ? Cf0  : ((z == 1) ? Cf1  : Cf2);
    __half* Chi        = (z == 0) ? Chi0 : ((z == 1) ? Chi1 : Chi2);
    __half* Clo        = (z == 0) ? Clo0 : ((z == 1) ? Clo1 : Clo2);
    const float cs     = (z == 0) ? cs0  : ((z == 1) ? cs1  : cs2);

    const int bm = blockIdx.y * 128;
    const int bn = blockIdx.x * 128;
    const int warpM = wid >> 2;
    const int warpN = wid & 3;

    float acc[4][4][4];
#pragma unroll
    for (int i = 0; i < 4; i++)
#pragma unroll
        for (int j = 0; j < 4; j++)
#pragma unroll
            for (int k = 0; k < 4; k++) acc[i][j][k] = 0.0f;

    const int l8  = lid & 7;
    const int mid = lid >> 3;
    const int a_cb   = mid >> 1;
    const int a_rowl = warpM * 64 + l8 + (mid & 1) * 8;
    const int b_cb   = mid & 1;
    const int b_rowl = warpN * 32 + l8 + (mid >> 1) * 8;

    uint32_t a_row_off[4], b_row_off[2];
#pragma unroll
    for (int mt = 0; mt < 4; ++mt) a_row_off[mt] = (uint32_t)(a_rowl + mt * 16) * 128u;
#pragma unroll
    for (int j = 0; j < 2; ++j)    b_row_off[j]  = (uint32_t)(b_rowl + j * 16) * 128u;

    uint32_t a_swz[4], b_swz[4];
#pragma unroll
    for (int ks = 0; ks < 4; ++ks) {
        a_swz[ks] = (uint32_t)(((ks * 2 + a_cb) ^ l8) * 16);
        b_swz[ks] = (uint32_t)(((ks * 2 + b_cb) ^ l8) * 16);
    }

    auto load_chunk = [&](int c) {
        const uint32_t st = sbase + (uint32_t)(c & 1) * STAGE_B;
        const int k0 = c * 64;
        load_tile_cp(Ahi, bm, k0, st,         t);
        load_tile_cp(Alo, bm, k0, st + 16384, t);
        load_tile_cp(Wf,  bn, k0, st + 32768, t);
        CP_COMMIT();
    };

    load_chunk(0);

    for (int c = 0; c < 32; ++c) {
        if (c + 1 < 32) { load_chunk(c + 1); CP_WAIT(1); }
        else            { CP_WAIT(0); }
        __syncthreads();

        const uint32_t st = sbase + (uint32_t)(c & 1) * STAGE_B;
#pragma unroll
        for (int ks = 0; ks < 4; ++ks) {
            uint32_t ah[4][4], al[4][4];
#pragma unroll
            for (int mt = 0; mt < 4; ++mt) {
                ldsm_x4(ah[mt], st +         a_row_off[mt] + a_swz[ks]);
                ldsm_x4(al[mt], st + 16384 + a_row_off[mt] + a_swz[ks]);
            }
            uint32_t bf[2][4];
#pragma unroll
            for (int j = 0; j < 2; ++j)
                ldsm_x4(bf[j], st + 32768 + b_row_off[j] + b_swz[ks]);
#pragma unroll
            for (int mt = 0; mt < 4; ++mt)
#pragma unroll
                for (int nt = 0; nt < 4; ++nt) {
                    mma16816(acc[mt][nt], ah[mt], &bf[nt >> 1][(nt & 1) * 2]);
                    mma16816(acc[mt][nt], al[mt], &bf[nt >> 1][(nt & 1) * 2]);
                }
        }
        __syncthreads();
    }

    // ---- epilogue ----
    const int lr  = lid >> 2;
    const int lc2 = (lid & 3) * 2;
    float2 bias2[4];
#pragma unroll
    for (int nt = 0; nt < 4; ++nt) {
        const int col = bn + warpN * 32 + nt * 8 + lc2;
        bias2[nt].x = __ldg(&bias[col]);
        bias2[nt].y = __ldg(&bias[col + 1]);
    }
#pragma unroll
    for (int mt = 0; mt < 4; ++mt) {
        const int row0 = bm + warpM * 64 + mt * 16 + lr;
#pragma unroll
        for (int nt = 0; nt < 4; ++nt) {
            const int col = bn + warpN * 32 + nt * 8 + lc2;
            float o0 = acc[mt][nt][0] + bias2[nt].x;
            float o1 = acc[mt][nt][1] + bias2[nt].y;
            float o2 = acc[mt][nt][2] + bias2[nt].x;
            float o3 = acc[mt][nt][3] + bias2[nt].y;
            if (Cf) {
                *(float2*)(Cf + (size_t)row0 * DD + col)       = make_float2(o0, o1);
                *(float2*)(Cf + (size_t)(row0 + 8) * DD + col) = make_float2(o2, o3);
            } else {
                o0 *= cs; o1 *= cs; o2 *= cs; o3 *= cs;
                uint32_t h0 = pack_h2(o0, o1);
                uint32_t h1 = pack_h2(o2, o3);
                *(uint32_t*)(Chi + (size_t)row0 * DD + col)       = h0;
                *(uint32_t*)(Chi + (size_t)(row0 + 8) * DD + col) = h1;
                if (Clo) {
                    *(uint32_t*)(Clo + (size_t)row0 * DD + col)       = pack_h2_res(h0, o0, o1);
                    *(uint32_t*)(Clo + (size_t)(row0 + 8) * DD + col) = pack_h2_res(h1, o2, o3);
                }
            }
        }
    }
}

// ---------------------------------------------------------------------------
// Flash attention, fp16 mma (QK: Q-pair x K-single; PV: P-single x V-pair).
// CTA = (head, 128-query block). 8 warps, each owns 16 query rows.
// smem: Qh|Ql (64KB) + 2 stages of Kf|Vh|Vl (48KB each) = 160KB.
// ---------------------------------------------------------------------------
#define ABS 64
#define A_QHI    0
#define A_QLO    32768
#define A_STAGES 65536
#define A_STAGE  49152
#define ATTN_SMEM (A_STAGES + 2 * A_STAGE)   // 163840

__device__ __forceinline__ void attn_load_kv(uint32_t stbase, int kb, int h, int t)
{
    const int s0 = kb * ABS;
#pragma unroll
    for (int i = t; i < 3072; i += 256) {
        const int tensor = i >> 10;          // 0 Kf, 1 Vh, 2 Vl
        const int r = (i >> 4) & 63;
        const int c = i & 15;
        const __half* g = (tensor == 0) ? g_Kf : (tensor == 1) ? g_Vh : g_Vl;
        cp16(stbase + tensor * 16384 + r * 256 + ((c ^ (r & 7)) << 4),
             g + (size_t)(s0 + r) * DD + h * DHH + c * 8);
    }
    CP_COMMIT();
}

__global__ __launch_bounds__(256, 1)
void attn_mma()
{
    extern __shared__ __align__(1024) char smem[];
    const uint32_t sb = smem_to_u32(smem);
    const int t   = threadIdx.x;
    const int wid = t >> 5;
    const int lid = t & 31;
    const int l8  = lid & 7;
    const int mid = lid >> 3;
    const int h   = blockIdx.x & 15;
    const int qb  = 15 - (blockIdx.x >> 4);   // heavy blocks first
    const int q0  = qb * 128;

    // ---- Q tiles (hi|lo), own cp.async group ----
#pragma unroll
    for (int i = t; i < 4096; i += 256) {
        const int tensor = i >> 11;
        const int r = (i >> 4) & 127;
        const int c = i & 15;
        const __half* g = tensor ? g_Ql : g_Qh;
        cp16(sb + A_QHI + tensor * 32768 + r * 256 + ((c ^ (r & 7)) << 4),
             g + (size_t)(q0 + r) * DD + h * DHH + c * 8);
    }
    CP_COMMIT();

    attn_load_kv(sb + A_STAGES, 0, h, t);

    float oacc[16][4];
#pragma unroll
    for (int i = 0; i < 16; i++)
#pragma unroll
        for (int j = 0; j < 4; j++) oacc[i][j] = 0.0f;
    float mrow0 = -1e30f, mrow1 = -1e30f, lrow0 = 0.0f, lrow1 = 0.0f;

    const int nkb = 2 * (qb + 1);
    for (int kb = 0; kb < nkb; ++kb) {
        if (kb + 1 < nkb) { attn_load_kv(sb + A_STAGES + ((kb + 1) & 1) * A_STAGE, kb + 1, h, t); CP_WAIT(1); }
        else              { CP_WAIT(0); }
        __syncthreads();

        const uint32_t st = sb + A_STAGES + (uint32_t)(kb & 1) * A_STAGE;
        const bool active = (kb * ABS <= q0 + wid * 16 + 15);
        if (active) {
            // ---- S = Q . K^T  (2-pass: Qhi + Qlo, K single) ----
            float sacc[8][4];
#pragma unroll
            for (int i = 0; i < 8; i++)
#pragma unroll
                for (int j = 0; j < 4; j++) sacc[i][j] = 0.0f;

#pragma unroll
            for (int ks = 0; ks < 8; ++ks) {
                const int qrow = wid * 16 + (lid & 15);
                const uint32_t qc = (uint32_t)(2 * ks + (lid >> 4));
                const uint32_t qoff = (uint32_t)qrow * 256 + (((qc ^ (qrow & 7))) << 4);
                uint32_t ah[4], al[4];
                ldsm_x4(ah, sb + A_QHI + qoff);
                ldsm_x4(al, sb + A_QLO + qoff);
                uint32_t bf[4][4];
#pragma unroll
                for (int j = 0; j < 4; ++j) {
                    const int krow = j * 16 + l8 + (mid >> 1) * 8;
                    const uint32_t kc = (uint32_t)(2 * ks + (mid & 1));
                    const uint32_t koff = (uint32_t)krow * 256 + (((kc ^ (krow & 7))) << 4);
                    ldsm_x4(bf[j], st + koff);
                }
#pragma unroll
                for (int j = 0; j < 4; ++j)
#pragma unroll
                    for (int e = 0; e < 2; ++e) {
                        mma16816(sacc[2 * j + e], ah, &bf[j][2 * e]);
                        mma16816(sacc[2 * j + e], al, &bf[j][2 * e]);
                    }
            }

            // ---- causal mask (diagonal blocks only) ----
            const int rlo = q0 + wid * 16 + (lid >> 2);
            const int rhi = rlo + 8;
            if (kb >= 2 * qb) {
#pragma unroll
                for (int nt = 0; nt < 8; ++nt) {
                    const int c0 = kb * ABS + nt * 8 + (lid & 3) * 2;
                    if (c0 > rlo)     sacc[nt][0] = -1e30f;
                    if (c0 + 1 > rlo) sacc[nt][1] = -1e30f;
                    if (c0 > rhi)     sacc[nt][2] = -1e30f;
                    if (c0 + 1 > rhi) sacc[nt][3] = -1e30f;
                }
            }

            // ---- online softmax (log2 domain) ----
            float mx0 = -1e30f, mx1 = -1e30f;
#pragma unroll
            for (int nt = 0; nt < 8; ++nt) {
                mx0 = fmaxf(mx0, fmaxf(sacc[nt][0], sacc[nt][1]));
                mx1 = fmaxf(mx1, fmaxf(sacc[nt][2], sacc[nt][3]));
            }
            mx0 = fmaxf(mx0, __shfl_xor_sync(0xffffffffu, mx0, 1));
            mx0 = fmaxf(mx0, __shfl_xor_sync(0xffffffffu, mx0, 2));
            mx1 = fmaxf(mx1, __shfl_xor_sync(0xffffffffu, mx1, 1));
            mx1 = fmaxf(mx1, __shfl_xor_sync(0xffffffffu, mx1, 2));
            const float mnew0 = fmaxf(mrow0, mx0);
            const float mnew1 = fmaxf(mrow1, mx1);
            const float alpha0 = ex2a(mrow0 - mnew0);
            const float alpha1 = ex2a(mrow1 - mnew1);
            float sum0 = 0.0f, sum1 = 0.0f;
#pragma unroll
            for (int nt = 0; nt < 8; ++nt) {
                sacc[nt][0] = ex2a(sacc[nt][0] - mnew0); sum0 += sacc[nt][0];
                sacc[nt][1] = ex2a(sacc[nt][1] - mnew0); sum0 += sacc[nt][1];
                sacc[nt][2] = ex2a(sacc[nt][2] - mnew1); sum1 += sacc[nt][2];
                sacc[nt][3] = ex2a(sacc[nt][3] - mnew1); sum1 += sacc[nt][3];
            }
            sum0 += __shfl_xor_sync(0xffffffffu, sum0, 1);
            sum0 += __shfl_xor_sync(0xffffffffu, sum0, 2);
            sum1 += __shfl_xor_sync(0xffffffffu, sum1, 1);
            sum1 += __shfl_xor_sync(0xffffffffu, sum1, 2);
            lrow0 = lrow0 * alpha0 + sum0;  mrow0 = mnew0;
            lrow1 = lrow1 * alpha1 + sum1;  mrow1 = mnew1;
#pragma unroll
            for (int nt = 0; nt < 16; ++nt) {
                oacc[nt][0] *= alpha0; oacc[nt][1] *= alpha0;
                oacc[nt][2] *= alpha1; oacc[nt][3] *= alpha1;
            }

            // ---- O += P . V  (P single fp16, V pair) ----
#pragma unroll
            for (int ks = 0; ks < 4; ++ks) {
                uint32_t ph[4];
#pragma unroll
                for (int half = 0; half < 2; ++half) {
                    const int nt2 = 2 * ks + half;
                    ph[2 * half]     = pack_h2(sacc[nt2][0], sacc[nt2][1]);
                    ph[2 * half + 1] = pack_h2(sacc[nt2][2], sacc[nt2][3]);
                }
#pragma unroll
                for (int half = 0; half < 2; ++half) {
                    uint32_t vh[4][4], vl[4][4];
#pragma unroll
                    for (int j = 0; j < 4; ++j) {
                        const int jj = half * 4 + j;
                        const int vrow = ks * 16 + l8 + (mid & 1) * 8;
                        const uint32_t vc = (uint32_t)(jj * 2 + (mid >> 1));
                        const uint32_t voff = (uint32_t)vrow * 256 + (((vc ^ (vrow & 7))) << 4);
                        ldsm_x4_t(vh[j], st + 16384 + voff);   // Vh
                        ldsm_x4_t(vl[j], st + 32768 + voff);   // Vl
                    }
#pragma unroll
                    for (int j = 0; j < 4; ++j) {
                        const int jj = half * 4 + j;
#pragma unroll
                        for (int e = 0; e < 2; ++e) {
                            mma16816(oacc[2 * jj + e], ph, &vh[j][2 * e]);
                            mma16816(oacc[2 * jj + e], ph, &vl[j][2 * e]);
                        }
                    }
                }
            }
        }
        __syncthreads();
    }

    // ---- epilogue: O /= l, write Yh/Yl (fp16 pair) ----
    const float inv0 = 1.0f / lrow0;
    const float inv1 = 1.0f / lrow1;
    const int r0 = q0 + wid * 16 + (lid >> 2);
    const int r1 = r0 + 8;
    const int colb = h * DHH + (lid & 3) * 2;
#pragma unroll
    for (int nt = 0; nt < 16; ++nt) {
        const int col = colb + nt * 8;
        float o0 = oacc[nt][0] * inv0, o1 = oacc[nt][1] * inv0;
        float o2 = oacc[nt][2] * inv1, o3 = oacc[nt][3] * inv1;
        uint32_t h0 = pack_h2(o0, o1);
        uint32_t h1 = pack_h2(o2, o3);
        *(uint32_t*)(g_Yh + (size_t)r0 * DD + col) = h0;
        *(uint32_t*)(g_Yh + (size_t)r1 * DD + col) = h1;
        *(uint32_t*)(g_Yl + (size_t)r0 * DD + col) = pack_h2_res(h0, o0, o1);
        *(uint32_t*)(g_Yl + (size_t)r1 * DD + col) = pack_h2_res(h1, o2, o3);
    }
}

// ---------------------------------------------------------------------------
// Launch
// ---------------------------------------------------------------------------
extern "C" void kernel_launch(void* const* d_in, const int* in_sizes, int n_in,
                              void* d_out, int out_size)
{
    const float* x  = (const float*)d_in[0];
    const float* Wq = (const float*)d_in[1];
    const float* bq = (const float*)d_in[2];
    const float* Wk = (const float*)d_in[3];
    const float* bk = (const float*)d_in[4];
    const float* Wv = (const float*)d_in[5];
    const float* bv = (const float*)d_in[6];
    const float* Wo = (const float*)d_in[7];
    const float* bo = (const float*)d_in[8];
    float* out = (float*)d_out;

    __half *xh, *xl, *wq, *wk, *wv, *wo;
    __half *qh, *ql, *kf, *vh, *vl, *yh, *yl;
    cudaGetSymbolAddress((void**)&xh, g_xh);   cudaGetSymbolAddress((void**)&xl, g_xl);
    cudaGetSymbolAddress((void**)&wq, g_Wq_f); cudaGetSymbolAddress((void**)&wk, g_Wk_f);
    cudaGetSymbolAddress((void**)&wv, g_Wv_f); cudaGetSymbolAddress((void**)&wo, g_Wo_f);
    cudaGetSymbolAddress((void**)&qh, g_Qh);   cudaGetSymbolAddress((void**)&ql, g_Ql);
    cudaGetSymbolAddress((void**)&kf, g_Kf);
    cudaGetSymbolAddress((void**)&vh, g_Vh);   cudaGetSymbolAddress((void**)&vl, g_Vl);
    cudaGetSymbolAddress((void**)&yh, g_Yh);   cudaGetSymbolAddress((void**)&yl, g_Yl);

    cudaFuncSetAttribute(gemm_mma, cudaFuncAttributeMaxDynamicSharedMemorySize, GEMM_SMEM);
    cudaFuncSetAttribute(attn_mma, cudaFuncAttributeMaxDynamicSharedMemorySize, ATTN_SMEM);

    const int nv4 = (TT * DD / 4) / 256;   // 4096 blocks of 256 (float4 granules)
    split_pair<<<nv4, 256>>>(x, xh, xl);
    conv_f16<<<dim3(nv4, 4), 256>>>(Wq, wq, Wk, wk, Wv, wv, Wo, wo);

    // fused QKV projection: z=0 Q (fp16 pair, pre-scaled), z=1 K (single), z=2 V (pair)
    gemm_mma<<<dim3(16, 16, 3), 256, GEMM_SMEM>>>(
        xh, xl,
        wq, bq, nullptr, qh, ql, SCALE_Q,
        wk, bk, nullptr, kf, nullptr, 1.0f,
        wv, bv, nullptr, vh, vl, 1.0f);

    attn_mma<<<256, 256, ATTN_SMEM>>>();

    // output projection: A = Y pair, W = Wo single, fp32 epilogue
    gemm_mma<<<dim3(16, 16, 1), 256, GEMM_SMEM>>>(
        yh, yl,
        wo, bo, out, nullptr, nullptr, 1.0f,
        wo, bo, out, nullptr, nullptr, 1.0f,
        wo, bo, out, nullptr, nullptr, 1.0f);
}

// round 7
// speedup vs baseline: 3.9257x; 1.0702x over previous
#include <cuda_runtime.h>
#include <cuda_fp16.h>
#include <math.h>
#include <stdint.h>

// Problem constants
#define TT 2048
#define DD 2048
#define HH 16
#define DHH 128

// ---------------------------------------------------------------------------
// Scratch (__device__ globals; allocation-free rule).  All fp16.
// ---------------------------------------------------------------------------
__device__ __half g_xh[TT * DD], g_xl[TT * DD];          // x split pair
__device__ __half g_Wq_f[DD * DD], g_Wk_f[DD * DD];      // weights single fp16
__device__ __half g_Wv_f[DD * DD], g_Wo_f[DD * DD];
__device__ __half g_Qf[TT * DD];                         // Q single (pre-scaled)
__device__ __half g_Kf[TT * DD];                         // K single
__device__ __half g_Vf[TT * DD];                         // V single
__device__ __half g_Yf[TT * DD];                         // attention out single

// ---------------------------------------------------------------------------
// sm_80-ISA helpers (ptxas target here is sm_100 baseline: no tcgen05)
// ---------------------------------------------------------------------------
__device__ __forceinline__ uint32_t smem_to_u32(const void* p) {
    uint32_t a;
    asm("{ .reg .u64 t; cvta.to.shared.u64 t, %1; cvt.u32.u64 %0, t; }"
        : "=r"(a) : "l"(p));
    return a;
}
__device__ __forceinline__ void cp16(uint32_t dst, const void* src) {
    asm volatile("cp.async.cg.shared.global [%0], [%1], 16;"
                 :: "r"(dst), "l"(src) : "memory");
}
#define CP_COMMIT() asm volatile("cp.async.commit_group;" ::: "memory")
#define CP_WAIT(n)  asm volatile("cp.async.wait_group %0;" :: "n"(n) : "memory")

__device__ __forceinline__ void ldsm_x4(uint32_t* r, uint32_t addr) {
    asm volatile("ldmatrix.sync.aligned.m8n8.x4.shared.b16 {%0,%1,%2,%3}, [%4];"
                 : "=r"(r[0]), "=r"(r[1]), "=r"(r[2]), "=r"(r[3]) : "r"(addr));
}
__device__ __forceinline__ void ldsm_x4_t(uint32_t* r, uint32_t addr) {
    asm volatile("ldmatrix.sync.aligned.m8n8.x4.trans.shared.b16 {%0,%1,%2,%3}, [%4];"
                 : "=r"(r[0]), "=r"(r[1]), "=r"(r[2]), "=r"(r[3]) : "r"(addr));
}
__device__ __forceinline__ void mma16816(float* d, const uint32_t* a, const uint32_t* b) {
    asm volatile(
        "mma.sync.aligned.m16n8k16.row.col.f32.f16.f16.f32 "
        "{%0,%1,%2,%3}, {%4,%5,%6,%7}, {%8,%9}, {%0,%1,%2,%3};"
        : "+f"(d[0]), "+f"(d[1]), "+f"(d[2]), "+f"(d[3])
        : "r"(a[0]), "r"(a[1]), "r"(a[2]), "r"(a[3]), "r"(b[0]), "r"(b[1]));
}
__device__ __forceinline__ float ex2a(float x) {
    float y;
    asm("ex2.approx.ftz.f32 %0, %1;" : "=f"(y) : "f"(x));
    return y;
}
__device__ __forceinline__ uint32_t pack_h2(float a, float b) {
    __half2 v = __floats2half2_rn(a, b);
    return *(uint32_t*)&v;
}
__device__ __forceinline__ uint32_t pack_h2_res(uint32_t hipk, float a, float b) {
    __half2 h = *(__half2*)&hipk;
    return pack_h2(a - __half2float(__low2half(h)), b - __half2float(__high2half(h)));
}

#define SCALE_Q (0.08838834764831845f * 1.4426950408889634f)  // 1/sqrt(128)*log2(e)

// ---------------------------------------------------------------------------
// split pair: fp32 -> (fp16 hi, fp16 lo)
// ---------------------------------------------------------------------------
__global__ void split_pair(const float* __restrict__ src,
                           __half* __restrict__ hi, __half* __restrict__ lo)
{
    const int i = blockIdx.x * blockDim.x + threadIdx.x;
    float4 v = ((const float4*)src)[i];
    uint32_t h0 = pack_h2(v.x, v.y), h1 = pack_h2(v.z, v.w);
    ((uint2*)hi)[i] = make_uint2(h0, h1);
    ((uint2*)lo)[i] = make_uint2(pack_h2_res(h0, v.x, v.y), pack_h2_res(h1, v.z, v.w));
}

// convert 4 weight matrices fp32 -> fp16 single (blockIdx.y selects tensor)
__global__ void conv_f16(const float* __restrict__ s0, __half* __restrict__ d0,
                         const float* __restrict__ s1, __half* __restrict__ d1,
                         const float* __restrict__ s2, __half* __restrict__ d2,
                         const float* __restrict__ s3, __half* __restrict__ d3)
{
    const int z = blockIdx.y;
    const float* s = (z == 0) ? s0 : (z == 1) ? s1 : (z == 2) ? s2 : s3;
    __half* d      = (z == 0) ? d0 : (z == 1) ? d1 : (z == 2) ? d2 : d3;
    const int i = blockIdx.x * blockDim.x + threadIdx.x;
    float4 v = ((const float4*)s)[i];
    ((uint2*)d)[i] = make_uint2(pack_h2(v.x, v.y), pack_h2(v.z, v.w));
}

// ---------------------------------------------------------------------------
// fp16 GEMM: C = A @ W^T + bias, fp32 accum. A = pair (Ahi+Alo) or single.
// CTA 128x128, BK=64, 8 warps (2x4), warp tile 64x32, 3-stage cp.async
// pipeline with ONE __syncthreads per chunk.
// ---------------------------------------------------------------------------
#define STAGE_B   49152                // Ahi|Alo|Bf, 16KB each
#define GEMM_SMEM (3 * STAGE_B)        // 147456

__device__ __forceinline__ void load_tile_cp(const __half* __restrict__ g,
                                             int row0, int k0, uint32_t sdst, int t)
{
#pragma unroll
    for (int i = t; i < 1024; i += 256) {
        const int r = i >> 3, c = i & 7;
        cp16(sdst + r * 128 + ((c ^ (r & 7)) * 16),
             g + (size_t)(row0 + r) * DD + k0 + c * 8);
    }
}

__global__ __launch_bounds__(256, 1)
void gemm_mma(const __half* __restrict__ Ahi, const __half* __restrict__ Alo,
              const __half* __restrict__ W0, const float* __restrict__ b0,
              float* Cf0, __half* Ch0, float cs0,
              const __half* __restrict__ W1, const float* __restrict__ b1,
              float* Cf1, __half* Ch1, float cs1,
              const __half* __restrict__ W2, const float* __restrict__ b2,
              float* Cf2, __half* Ch2, float cs2)
{
    extern __shared__ __align__(1024) char smem[];
    const uint32_t sbase = smem_to_u32(smem);
    const int t   = threadIdx.x;
    const int wid = t >> 5;
    const int lid = t & 31;
    const int z   = blockIdx.z;

    const __half* Wf   = (z == 0) ? W0  : ((z == 1) ? W1  : W2);
    const float* bias  = (z == 0) ? b0  : ((z == 1) ? b1  : b2);
    float* Cf          = (z == 0) ? Cf0 : ((z == 1) ? Cf1 : Cf2);
    __half* Ch         = (z == 0) ? Ch0 : ((z == 1) ? Ch1 : Ch2);
    const float cs     = (z == 0) ? cs0 : ((z == 1) ? cs1 : cs2);
    const bool pairA   = (Alo != nullptr);

    const int bm = blockIdx.y * 128;
    const int bn = blockIdx.x * 128;
    const int warpM = wid >> 2;
    const int warpN = wid & 3;

    float acc[4][4][4];
#pragma unroll
    for (int i = 0; i < 4; i++)
#pragma unroll
        for (int j = 0; j < 4; j++)
#pragma unroll
            for (int k = 0; k < 4; k++) acc[i][j][k] = 0.0f;

    const int l8  = lid & 7;
    const int mid = lid >> 3;
    const int a_cb   = mid >> 1;
    const int a_rowl = warpM * 64 + l8 + (mid & 1) * 8;
    const int b_cb   = mid & 1;
    const int b_rowl = warpN * 32 + l8 + (mid >> 1) * 8;

    uint32_t a_row_off[4], b_row_off[2];
#pragma unroll
    for (int mt = 0; mt < 4; ++mt) a_row_off[mt] = (uint32_t)(a_rowl + mt * 16) * 128u;
#pragma unroll
    for (int j = 0; j < 2; ++j)    b_row_off[j]  = (uint32_t)(b_rowl + j * 16) * 128u;

    uint32_t a_swz[4], b_swz[4];
#pragma unroll
    for (int ks = 0; ks < 4; ++ks) {
        a_swz[ks] = (uint32_t)(((ks * 2 + a_cb) ^ l8) * 16);
        b_swz[ks] = (uint32_t)(((ks * 2 + b_cb) ^ l8) * 16);
    }

    auto load_chunk = [&](int c) {
        const uint32_t st = sbase + (uint32_t)(c % 3) * STAGE_B;
        const int k0 = c * 64;
        load_tile_cp(Ahi, bm, k0, st, t);
        if (pairA) load_tile_cp(Alo, bm, k0, st + 16384, t);
        load_tile_cp(Wf, bn, k0, st + 32768, t);
        CP_COMMIT();
    };

    load_chunk(0);
    load_chunk(1);
    CP_WAIT(1);
    __syncthreads();

    for (int c = 0; c < 32; ++c) {
        if (c + 2 < 32) load_chunk(c + 2);

        const uint32_t st = sbase + (uint32_t)(c % 3) * STAGE_B;
#pragma unroll
        for (int ks = 0; ks < 4; ++ks) {
            uint32_t ah[4][4], al[4][4];
#pragma unroll
            for (int mt = 0; mt < 4; ++mt) {
                ldsm_x4(ah[mt], st + a_row_off[mt] + a_swz[ks]);
                if (pairA) ldsm_x4(al[mt], st + 16384 + a_row_off[mt] + a_swz[ks]);
            }
            uint32_t bf[2][4];
#pragma unroll
            for (int j = 0; j < 2; ++j)
                ldsm_x4(bf[j], st + 32768 + b_row_off[j] + b_swz[ks]);
#pragma unroll
            for (int mt = 0; mt < 4; ++mt)
#pragma unroll
                for (int nt = 0; nt < 4; ++nt) {
                    mma16816(acc[mt][nt], ah[mt], &bf[nt >> 1][(nt & 1) * 2]);
                    if (pairA) mma16816(acc[mt][nt], al[mt], &bf[nt >> 1][(nt & 1) * 2]);
                }
        }

        if (c + 2 < 32)      { CP_WAIT(1); }
        else if (c + 1 < 32) { CP_WAIT(0); }
        if (c + 1 < 32) __syncthreads();
    }

    // ---- epilogue ----
    const int lr  = lid >> 2;
    const int lc2 = (lid & 3) * 2;
    float2 bias2[4];
#pragma unroll
    for (int nt = 0; nt < 4; ++nt) {
        const int col = bn + warpN * 32 + nt * 8 + lc2;
        bias2[nt].x = __ldg(&bias[col]);
        bias2[nt].y = __ldg(&bias[col + 1]);
    }
#pragma unroll
    for (int mt = 0; mt < 4; ++mt) {
        const int row0 = bm + warpM * 64 + mt * 16 + lr;
#pragma unroll
        for (int nt = 0; nt < 4; ++nt) {
            const int col = bn + warpN * 32 + nt * 8 + lc2;
            float o0 = acc[mt][nt][0] + bias2[nt].x;
            float o1 = acc[mt][nt][1] + bias2[nt].y;
            float o2 = acc[mt][nt][2] + bias2[nt].x;
            float o3 = acc[mt][nt][3] + bias2[nt].y;
            if (Cf) {
                *(float2*)(Cf + (size_t)row0 * DD + col)       = make_float2(o0, o1);
                *(float2*)(Cf + (size_t)(row0 + 8) * DD + col) = make_float2(o2, o3);
            } else {
                *(uint32_t*)(Ch + (size_t)row0 * DD + col)       = pack_h2(o0 * cs, o1 * cs);
                *(uint32_t*)(Ch + (size_t)(row0 + 8) * DD + col) = pack_h2(o2 * cs, o3 * cs);
            }
        }
    }
}

// ---------------------------------------------------------------------------
// Flash attention, fp16 mma, all operands single-precision fp16.
// CTA = (head, 128-query block). 8 warps, each owns 16 query rows.
// smem: Qf (32KB) + 3 stages of Kf|Vf (32KB each) = 128KB.
// 3-stage cp.async pipeline, one __syncthreads per key block.
// ---------------------------------------------------------------------------
#define ABS 64
#define A_STAGES 32768
#define A_STAGE  32768
#define ATTN_SMEM (A_STAGES + 3 * A_STAGE)   // 131072

__device__ __forceinline__ void attn_load_kv(uint32_t sb, int kb, int h, int t)
{
    const uint32_t stbase = sb + A_STAGES + (uint32_t)(kb % 3) * A_STAGE;
    const int s0 = kb * ABS;
#pragma unroll
    for (int i = t; i < 2048; i += 256) {
        const int tensor = i >> 10;          // 0 Kf, 1 Vf
        const int r = (i >> 4) & 63;
        const int c = i & 15;
        const __half* g = tensor ? g_Vf : g_Kf;
        cp16(stbase + tensor * 16384 + r * 256 + ((c ^ (r & 7)) << 4),
             g + (size_t)(s0 + r) * DD + h * DHH + c * 8);
    }
    CP_COMMIT();
}

__global__ __launch_bounds__(256, 1)
void attn_mma()
{
    extern __shared__ __align__(1024) char smem[];
    const uint32_t sb = smem_to_u32(smem);
    const int t   = threadIdx.x;
    const int wid = t >> 5;
    const int lid = t & 31;
    const int l8  = lid & 7;
    const int mid = lid >> 3;
    const int h   = blockIdx.x & 15;
    const int qb  = 15 - (blockIdx.x >> 4);   // heavy blocks first
    const int q0  = qb * 128;
    const int nkb = 2 * (qb + 1);

    // ---- group 0: Q tile + kv block 0 ----
#pragma unroll
    for (int i = t; i < 2048; i += 256) {
        const int r = i >> 4;
        const int c = i & 15;
        cp16(sb + r * 256 + ((c ^ (r & 7)) << 4),
             g_Qf + (size_t)(q0 + r) * DD + h * DHH + c * 8);
    }
    {
        const uint32_t stbase = sb + A_STAGES;
#pragma unroll
        for (int i = t; i < 2048; i += 256) {
            const int tensor = i >> 10;
            const int r = (i >> 4) & 63;
            const int c = i & 15;
            const __half* g = tensor ? g_Vf : g_Kf;
            cp16(stbase + tensor * 16384 + r * 256 + ((c ^ (r & 7)) << 4),
                 g + (size_t)(r) * DD + h * DHH + c * 8);
        }
    }
    CP_COMMIT();
    if (1 < nkb) attn_load_kv(sb, 1, h, t);
    CP_WAIT(1);
    __syncthreads();

    float oacc[16][4];
#pragma unroll
    for (int i = 0; i < 16; i++)
#pragma unroll
        for (int j = 0; j < 4; j++) oacc[i][j] = 0.0f;
    float mrow0 = -1e30f, mrow1 = -1e30f, lrow0 = 0.0f, lrow1 = 0.0f;

    for (int kb = 0; kb < nkb; ++kb) {
        if (kb + 2 < nkb) attn_load_kv(sb, kb + 2, h, t);

        const uint32_t st = sb + A_STAGES + (uint32_t)(kb % 3) * A_STAGE;
        const bool active = (kb * ABS <= q0 + wid * 16 + 15);
        if (active) {
            // ---- S = Q . K^T  (single pass) ----
            float sacc[8][4];
#pragma unroll
            for (int i = 0; i < 8; i++)
#pragma unroll
                for (int j = 0; j < 4; j++) sacc[i][j] = 0.0f;

#pragma unroll
            for (int ks = 0; ks < 8; ++ks) {
                const int qrow = wid * 16 + (lid & 15);
                const uint32_t qc = (uint32_t)(2 * ks + (lid >> 4));
                const uint32_t qoff = (uint32_t)qrow * 256 + (((qc ^ (qrow & 7))) << 4);
                uint32_t af[4];
                ldsm_x4(af, sb + qoff);
                uint32_t bf[4][4];
#pragma unroll
                for (int j = 0; j < 4; ++j) {
                    const int krow = j * 16 + l8 + (mid >> 1) * 8;
                    const uint32_t kc = (uint32_t)(2 * ks + (mid & 1));
                    const uint32_t koff = (uint32_t)krow * 256 + (((kc ^ (krow & 7))) << 4);
                    ldsm_x4(bf[j], st + koff);
                }
#pragma unroll
                for (int j = 0; j < 4; ++j)
#pragma unroll
                    for (int e = 0; e < 2; ++e)
                        mma16816(sacc[2 * j + e], af, &bf[j][2 * e]);
            }

            // ---- causal mask (diagonal blocks only) ----
            const int rlo = q0 + wid * 16 + (lid >> 2);
            const int rhi = rlo + 8;
            if (kb >= 2 * qb) {
#pragma unroll
                for (int nt = 0; nt < 8; ++nt) {
                    const int c0 = kb * ABS + nt * 8 + (lid & 3) * 2;
                    if (c0 > rlo)     sacc[nt][0] = -1e30f;
                    if (c0 + 1 > rlo) sacc[nt][1] = -1e30f;
                    if (c0 > rhi)     sacc[nt][2] = -1e30f;
                    if (c0 + 1 > rhi) sacc[nt][3] = -1e30f;
                }
            }

            // ---- online softmax (log2 domain) ----
            float mx0 = -1e30f, mx1 = -1e30f;
#pragma unroll
            for (int nt = 0; nt < 8; ++nt) {
                mx0 = fmaxf(mx0, fmaxf(sacc[nt][0], sacc[nt][1]));
                mx1 = fmaxf(mx1, fmaxf(sacc[nt][2], sacc[nt][3]));
            }
            mx0 = fmaxf(mx0, __shfl_xor_sync(0xffffffffu, mx0, 1));
            mx0 = fmaxf(mx0, __shfl_xor_sync(0xffffffffu, mx0, 2));
            mx1 = fmaxf(mx1, __shfl_xor_sync(0xffffffffu, mx1, 1));
            mx1 = fmaxf(mx1, __shfl_xor_sync(0xffffffffu, mx1, 2));
            const float mnew0 = fmaxf(mrow0, mx0);
            const float mnew1 = fmaxf(mrow1, mx1);
            const float alpha0 = ex2a(mrow0 - mnew0);
            const float alpha1 = ex2a(mrow1 - mnew1);
            float sum0 = 0.0f, sum1 = 0.0f;
#pragma unroll
            for (int nt = 0; nt < 8; ++nt) {
                sacc[nt][0] = ex2a(sacc[nt][0] - mnew0); sum0 += sacc[nt][0];
                sacc[nt][1] = ex2a(sacc[nt][1] - mnew0); sum0 += sacc[nt][1];
                sacc[nt][2] = ex2a(sacc[nt][2] - mnew1); sum1 += sacc[nt][2];
                sacc[nt][3] = ex2a(sacc[nt][3] - mnew1); sum1 += sacc[nt][3];
            }
            sum0 += __shfl_xor_sync(0xffffffffu, sum0, 1);
            sum0 += __shfl_xor_sync(0xffffffffu, sum0, 2);
            sum1 += __shfl_xor_sync(0xffffffffu, sum1, 1);
            sum1 += __shfl_xor_sync(0xffffffffu, sum1, 2);
            lrow0 = lrow0 * alpha0 + sum0;  mrow0 = mnew0;
            lrow1 = lrow1 * alpha1 + sum1;  mrow1 = mnew1;
#pragma unroll
            for (int nt = 0; nt < 16; ++nt) {
                oacc[nt][0] *= alpha0; oacc[nt][1] *= alpha0;
                oacc[nt][2] *= alpha1; oacc[nt][3] *= alpha1;
            }

            // ---- O += P . V  (single pass) ----
#pragma unroll
            for (int ks = 0; ks < 4; ++ks) {
                uint32_t ph[4];
#pragma unroll
                for (int half = 0; half < 2; ++half) {
                    const int nt2 = 2 * ks + half;
                    ph[2 * half]     = pack_h2(sacc[nt2][0], sacc[nt2][1]);
                    ph[2 * half + 1] = pack_h2(sacc[nt2][2], sacc[nt2][3]);
                }
#pragma unroll
                for (int half = 0; half < 2; ++half) {
                    uint32_t vf[4][4];
#pragma unroll
                    for (int j = 0; j < 4; ++j) {
                        const int jj = half * 4 + j;
                        const int vrow = ks * 16 + l8 + (mid & 1) * 8;
                        const uint32_t vc = (uint32_t)(jj * 2 + (mid >> 1));
                        const uint32_t voff = (uint32_t)vrow * 256 + (((vc ^ (vrow & 7))) << 4);
                        ldsm_x4_t(vf[j], st + 16384 + voff);
                    }
#pragma unroll
                    for (int j = 0; j < 4; ++j) {
                        const int jj = half * 4 + j;
#pragma unroll
                        for (int e = 0; e < 2; ++e)
                            mma16816(oacc[2 * jj + e], ph, &vf[j][2 * e]);
                    }
                }
            }
        }

        if (kb + 2 < nkb)      { CP_WAIT(1); }
        else if (kb + 1 < nkb) { CP_WAIT(0); }
        if (kb + 1 < nkb) __syncthreads();
    }

    // ---- epilogue: O /= l, write Yf (fp16 single) ----
    const float inv0 = 1.0f / lrow0;
    const float inv1 = 1.0f / lrow1;
    const int r0 = q0 + wid * 16 + (lid >> 2);
    const int r1 = r0 + 8;
    const int colb = h * DHH + (lid & 3) * 2;
#pragma unroll
    for (int nt = 0; nt < 16; ++nt) {
        const int col = colb + nt * 8;
        *(uint32_t*)(g_Yf + (size_t)r0 * DD + col) =
            pack_h2(oacc[nt][0] * inv0, oacc[nt][1] * inv0);
        *(uint32_t*)(g_Yf + (size_t)r1 * DD + col) =
            pack_h2(oacc[nt][2] * inv1, oacc[nt][3] * inv1);
    }
}

// ---------------------------------------------------------------------------
// Launch
// ---------------------------------------------------------------------------
extern "C" void kernel_launch(void* const* d_in, const int* in_sizes, int n_in,
                              void* d_out, int out_size)
{
    const float* x  = (const float*)d_in[0];
    const float* Wq = (const float*)d_in[1];
    const float* bq = (const float*)d_in[2];
    const float* Wk = (const float*)d_in[3];
    const float* bk = (const float*)d_in[4];
    const float* Wv = (const float*)d_in[5];
    const float* bv = (const float*)d_in[6];
    const float* Wo = (const float*)d_in[7];
    const float* bo = (const float*)d_in[8];
    float* out = (float*)d_out;

    __half *xh, *xl, *wq, *wk, *wv, *wo, *qf, *kf, *vf, *yf;
    cudaGetSymbolAddress((void**)&xh, g_xh);   cudaGetSymbolAddress((void**)&xl, g_xl);
    cudaGetSymbolAddress((void**)&wq, g_Wq_f); cudaGetSymbolAddress((void**)&wk, g_Wk_f);
    cudaGetSymbolAddress((void**)&wv, g_Wv_f); cudaGetSymbolAddress((void**)&wo, g_Wo_f);
    cudaGetSymbolAddress((void**)&qf, g_Qf);   cudaGetSymbolAddress((void**)&kf, g_Kf);
    cudaGetSymbolAddress((void**)&vf, g_Vf);   cudaGetSymbolAddress((void**)&yf, g_Yf);

    cudaFuncSetAttribute(gemm_mma, cudaFuncAttributeMaxDynamicSharedMemorySize, GEMM_SMEM);
    cudaFuncSetAttribute(attn_mma, cudaFuncAttributeMaxDynamicSharedMemorySize, ATTN_SMEM);

    const int nv4 = (TT * DD / 4) / 256;   // 4096 blocks (float4 granules)
    split_pair<<<nv4, 256>>>(x, xh, xl);
    conv_f16<<<dim3(nv4, 4), 256>>>(Wq, wq, Wk, wk, Wv, wv, Wo, wo);

    // fused QKV projection (A = x pair): Q (scaled), K, V all fp16 single out
    gemm_mma<<<dim3(16, 16, 3), 256, GEMM_SMEM>>>(
        xh, xl,
        wq, bq, nullptr, qf, SCALE_Q,
        wk, bk, nullptr, kf, 1.0f,
        wv, bv, nullptr, vf, 1.0f);

    attn_mma<<<256, 256, ATTN_SMEM>>>();

    // output projection: A = Y single (1-pass), fp32 epilogue
    gemm_mma<<<dim3(16, 16, 1), 256, GEMM_SMEM>>>(
        yf, nullptr,
        wo, bo, out, nullptr, 1.0f,
        wo, bo, out, nullptr, 1.0f,
        wo, bo, out, nullptr, 1.0f);
}

// round 8
// speedup vs baseline: 6.5525x; 1.6691x over previous
#include <cuda_runtime.h>
#include <cuda_fp16.h>
#include <math.h>
#include <stdint.h>

// Problem constants
#define TT 2048
#define DD 2048
#define HH 16
#define DHH 128

// ---------------------------------------------------------------------------
// Scratch (__device__ globals; allocation-free rule).  All fp16 single.
// ---------------------------------------------------------------------------
__device__ __half g_xf[TT * DD];
__device__ __half g_Wq_f[DD * DD], g_Wk_f[DD * DD];
__device__ __half g_Wv_f[DD * DD], g_Wo_f[DD * DD];
__device__ __half g_Qf[TT * DD];                         // Q (pre-scaled)
__device__ __half g_Kf[TT * DD];
__device__ __half g_Vf[TT * DD];
__device__ __half g_Yf[TT * DD];

// ---------------------------------------------------------------------------
// sm_80-ISA helpers (ptxas target here is sm_100 baseline: no tcgen05)
// ---------------------------------------------------------------------------
__device__ __forceinline__ uint32_t smem_to_u32(const void* p) {
    uint32_t a;
    asm("{ .reg .u64 t; cvta.to.shared.u64 t, %1; cvt.u32.u64 %0, t; }"
        : "=r"(a) : "l"(p));
    return a;
}
__device__ __forceinline__ void cp16(uint32_t dst, const void* src) {
    asm volatile("cp.async.cg.shared.global [%0], [%1], 16;"
                 :: "r"(dst), "l"(src) : "memory");
}
#define CP_COMMIT() asm volatile("cp.async.commit_group;" ::: "memory")
#define CP_WAIT(n)  asm volatile("cp.async.wait_group %0;" :: "n"(n) : "memory")

__device__ __forceinline__ void ldsm_x4(uint32_t* r, uint32_t addr) {
    asm volatile("ldmatrix.sync.aligned.m8n8.x4.shared.b16 {%0,%1,%2,%3}, [%4];"
                 : "=r"(r[0]), "=r"(r[1]), "=r"(r[2]), "=r"(r[3]) : "r"(addr));
}
__device__ __forceinline__ void ldsm_x4_t(uint32_t* r, uint32_t addr) {
    asm volatile("ldmatrix.sync.aligned.m8n8.x4.trans.shared.b16 {%0,%1,%2,%3}, [%4];"
                 : "=r"(r[0]), "=r"(r[1]), "=r"(r[2]), "=r"(r[3]) : "r"(addr));
}
__device__ __forceinline__ void mma16816(float* d, const uint32_t* a, const uint32_t* b) {
    asm volatile(
        "mma.sync.aligned.m16n8k16.row.col.f32.f16.f16.f32 "
        "{%0,%1,%2,%3}, {%4,%5,%6,%7}, {%8,%9}, {%0,%1,%2,%3};"
        : "+f"(d[0]), "+f"(d[1]), "+f"(d[2]), "+f"(d[3])
        : "r"(a[0]), "r"(a[1]), "r"(a[2]), "r"(a[3]), "r"(b[0]), "r"(b[1]));
}
__device__ __forceinline__ float ex2a(float x) {
    float y;
    asm("ex2.approx.ftz.f32 %0, %1;" : "=f"(y) : "f"(x));
    return y;
}
__device__ __forceinline__ uint32_t pack_h2(float a, float b) {
    __half2 v = __floats2half2_rn(a, b);
    return *(uint32_t*)&v;
}

#define SCALE_Q (0.08838834764831845f * 1.4426950408889634f)  // 1/sqrt(128)*log2(e)

// ---------------------------------------------------------------------------
// convert fp32 -> fp16 single; blockIdx.y selects one of 5 tensors
// ---------------------------------------------------------------------------
__global__ void conv_f16(const float* __restrict__ s0, __half* __restrict__ d0,
                         const float* __restrict__ s1, __half* __restrict__ d1,
                         const float* __restrict__ s2, __half* __restrict__ d2,
                         const float* __restrict__ s3, __half* __restrict__ d3,
                         const float* __restrict__ s4, __half* __restrict__ d4)
{
    const int z = blockIdx.y;
    const float* s = (z == 0) ? s0 : (z == 1) ? s1 : (z == 2) ? s2 : (z == 3) ? s3 : s4;
    __half* d      = (z == 0) ? d0 : (z == 1) ? d1 : (z == 2) ? d2 : (z == 3) ? d3 : d4;
    const int i = blockIdx.x * blockDim.x + threadIdx.x;
    float4 v = ((const float4*)s)[i];
    ((uint2*)d)[i] = make_uint2(pack_h2(v.x, v.y), pack_h2(v.z, v.w));
}

// ---------------------------------------------------------------------------
// 1-pass fp16 GEMM: C = A @ W^T + bias, fp32 accum.
// CTA 128x128, BK=64, 8 warps (2x4), warp tile 64x32.
// 3-stage cp.async pipeline, one __syncthreads per chunk, 2 CTAs/SM.
// ---------------------------------------------------------------------------
#define STAGE_B   32768                // A|W, 16KB each
#define GEMM_SMEM (3 * STAGE_B)        // 98304 -> occ 2

__device__ __forceinline__ void load_tile_cp(const __half* __restrict__ g,
                                             int row0, int k0, uint32_t sdst, int t)
{
#pragma unroll
    for (int i = t; i < 1024; i += 256) {
        const int r = i >> 3, c = i & 7;
        cp16(sdst + r * 128 + ((c ^ (r & 7)) * 16),
             g + (size_t)(row0 + r) * DD + k0 + c * 8);
    }
}

__global__ __launch_bounds__(256, 2)
void gemm_mma(const __half* __restrict__ Af,
              const __half* __restrict__ W0, const float* __restrict__ b0,
              float* Cf0, __half* Ch0, float cs0,
              const __half* __restrict__ W1, const float* __restrict__ b1,
              float* Cf1, __half* Ch1, float cs1,
              const __half* __restrict__ W2, const float* __restrict__ b2,
              float* Cf2, __half* Ch2, float cs2)
{
    extern __shared__ __align__(1024) char smem[];
    const uint32_t sbase = smem_to_u32(smem);
    const int t   = threadIdx.x;
    const int wid = t >> 5;
    const int lid = t & 31;
    const int z   = blockIdx.z;

    const __half* Wf   = (z == 0) ? W0  : ((z == 1) ? W1  : W2);
    const float* bias  = (z == 0) ? b0  : ((z == 1) ? b1  : b2);
    float* Cf          = (z == 0) ? Cf0 : ((z == 1) ? Cf1 : Cf2);
    __half* Ch         = (z == 0) ? Ch0 : ((z == 1) ? Ch1 : Ch2);
    const float cs     = (z == 0) ? cs0 : ((z == 1) ? cs1 : cs2);

    const int bm = blockIdx.y * 128;
    const int bn = blockIdx.x * 128;
    const int warpM = wid >> 2;
    const int warpN = wid & 3;

    float acc[4][4][4];
#pragma unroll
    for (int i = 0; i < 4; i++)
#pragma unroll
        for (int j = 0; j < 4; j++)
#pragma unroll
            for (int k = 0; k < 4; k++) acc[i][j][k] = 0.0f;

    const int l8  = lid & 7;
    const int mid = lid >> 3;
    const int a_cb   = mid >> 1;
    const int a_rowl = warpM * 64 + l8 + (mid & 1) * 8;
    const int b_cb   = mid & 1;
    const int b_rowl = warpN * 32 + l8 + (mid >> 1) * 8;

    uint32_t a_row_off[4], b_row_off[2];
#pragma unroll
    for (int mt = 0; mt < 4; ++mt) a_row_off[mt] = (uint32_t)(a_rowl + mt * 16) * 128u;
#pragma unroll
    for (int j = 0; j < 2; ++j)    b_row_off[j]  = (uint32_t)(b_rowl + j * 16) * 128u;

    uint32_t a_swz[4], b_swz[4];
#pragma unroll
    for (int ks = 0; ks < 4; ++ks) {
        a_swz[ks] = (uint32_t)(((ks * 2 + a_cb) ^ l8) * 16);
        b_swz[ks] = (uint32_t)(((ks * 2 + b_cb) ^ l8) * 16);
    }

    auto load_chunk = [&](int c) {
        const uint32_t st = sbase + (uint32_t)(c % 3) * STAGE_B;
        const int k0 = c * 64;
        load_tile_cp(Af, bm, k0, st, t);
        load_tile_cp(Wf, bn, k0, st + 16384, t);
        CP_COMMIT();
    };

    load_chunk(0);
    load_chunk(1);
    CP_WAIT(1);
    __syncthreads();

    for (int c = 0; c < 32; ++c) {
        if (c + 2 < 32) load_chunk(c + 2);

        const uint32_t st = sbase + (uint32_t)(c % 3) * STAGE_B;
#pragma unroll
        for (int ks = 0; ks < 4; ++ks) {
            uint32_t af[4][4];
#pragma unroll
            for (int mt = 0; mt < 4; ++mt)
                ldsm_x4(af[mt], st + a_row_off[mt] + a_swz[ks]);
            uint32_t bf[2][4];
#pragma unroll
            for (int j = 0; j < 2; ++j)
                ldsm_x4(bf[j], st + 16384 + b_row_off[j] + b_swz[ks]);
#pragma unroll
            for (int mt = 0; mt < 4; ++mt)
#pragma unroll
                for (int nt = 0; nt < 4; ++nt)
                    mma16816(acc[mt][nt], af[mt], &bf[nt >> 1][(nt & 1) * 2]);
        }

        if (c + 2 < 32)      { CP_WAIT(1); }
        else if (c + 1 < 32) { CP_WAIT(0); }
        if (c + 1 < 32) __syncthreads();
    }

    // ---- epilogue ----
    const int lr  = lid >> 2;
    const int lc2 = (lid & 3) * 2;
    float2 bias2[4];
#pragma unroll
    for (int nt = 0; nt < 4; ++nt) {
        const int col = bn + warpN * 32 + nt * 8 + lc2;
        bias2[nt].x = __ldg(&bias[col]);
        bias2[nt].y = __ldg(&bias[col + 1]);
    }
#pragma unroll
    for (int mt = 0; mt < 4; ++mt) {
        const int row0 = bm + warpM * 64 + mt * 16 + lr;
#pragma unroll
        for (int nt = 0; nt < 4; ++nt) {
            const int col = bn + warpN * 32 + nt * 8 + lc2;
            float o0 = acc[mt][nt][0] + bias2[nt].x;
            float o1 = acc[mt][nt][1] + bias2[nt].y;
            float o2 = acc[mt][nt][2] + bias2[nt].x;
            float o3 = acc[mt][nt][3] + bias2[nt].y;
            if (Cf) {
                *(float2*)(Cf + (size_t)row0 * DD + col)       = make_float2(o0, o1);
                *(float2*)(Cf + (size_t)(row0 + 8) * DD + col) = make_float2(o2, o3);
            } else {
                *(uint32_t*)(Ch + (size_t)row0 * DD + col)       = pack_h2(o0 * cs, o1 * cs);
                *(uint32_t*)(Ch + (size_t)(row0 + 8) * DD + col) = pack_h2(o2 * cs, o3 * cs);
            }
        }
    }
}

// ---------------------------------------------------------------------------
// Flash attention, fp16 mma, all operands single fp16.
// CTA = (head, 128-query block). 8 warps, each owns 16 query rows.
// smem: Qf (32KB) + 3 stages of Kf|Vf (32KB each) = 128KB.
// 3-stage cp.async pipeline, one __syncthreads per key block.
// ---------------------------------------------------------------------------
#define ABS 64
#define A_STAGES 32768
#define A_STAGE  32768
#define ATTN_SMEM (A_STAGES + 3 * A_STAGE)   // 131072

__device__ __forceinline__ void attn_load_kv(uint32_t sb, int kb, int h, int t)
{
    const uint32_t stbase = sb + A_STAGES + (uint32_t)(kb % 3) * A_STAGE;
    const int s0 = kb * ABS;
#pragma unroll
    for (int i = t; i < 2048; i += 256) {
        const int tensor = i >> 10;          // 0 Kf, 1 Vf
        const int r = (i >> 4) & 63;
        const int c = i & 15;
        const __half* g = tensor ? g_Vf : g_Kf;
        cp16(stbase + tensor * 16384 + r * 256 + ((c ^ (r & 7)) << 4),
             g + (size_t)(s0 + r) * DD + h * DHH + c * 8);
    }
    CP_COMMIT();
}

__global__ __launch_bounds__(256, 1)
void attn_mma()
{
    extern __shared__ __align__(1024) char smem[];
    const uint32_t sb = smem_to_u32(smem);
    const int t   = threadIdx.x;
    const int wid = t >> 5;
    const int lid = t & 31;
    const int l8  = lid & 7;
    const int mid = lid >> 3;
    const int h   = blockIdx.x & 15;
    const int qb  = 15 - (blockIdx.x >> 4);   // heavy blocks first
    const int q0  = qb * 128;
    const int nkb = 2 * (qb + 1);

    // ---- group 0: Q tile + kv block 0 ----
#pragma unroll
    for (int i = t; i < 2048; i += 256) {
        const int r = i >> 4;
        const int c = i & 15;
        cp16(sb + r * 256 + ((c ^ (r & 7)) << 4),
             g_Qf + (size_t)(q0 + r) * DD + h * DHH + c * 8);
    }
    {
        const uint32_t stbase = sb + A_STAGES;
#pragma unroll
        for (int i = t; i < 2048; i += 256) {
            const int tensor = i >> 10;
            const int r = (i >> 4) & 63;
            const int c = i & 15;
            const __half* g = tensor ? g_Vf : g_Kf;
            cp16(stbase + tensor * 16384 + r * 256 + ((c ^ (r & 7)) << 4),
                 g + (size_t)(r) * DD + h * DHH + c * 8);
        }
    }
    CP_COMMIT();
    if (1 < nkb) attn_load_kv(sb, 1, h, t);
    CP_WAIT(1);
    __syncthreads();

    float oacc[16][4];
#pragma unroll
    for (int i = 0; i < 16; i++)
#pragma unroll
        for (int j = 0; j < 4; j++) oacc[i][j] = 0.0f;
    float mrow0 = -1e30f, mrow1 = -1e30f, lrow0 = 0.0f, lrow1 = 0.0f;

    for (int kb = 0; kb < nkb; ++kb) {
        if (kb + 2 < nkb) attn_load_kv(sb, kb + 2, h, t);

        const uint32_t st = sb + A_STAGES + (uint32_t)(kb % 3) * A_STAGE;
        const bool active = (kb * ABS <= q0 + wid * 16 + 15);
        if (active) {
            // ---- S = Q . K^T ----
            float sacc[8][4];
#pragma unroll
            for (int i = 0; i < 8; i++)
#pragma unroll
                for (int j = 0; j < 4; j++) sacc[i][j] = 0.0f;

#pragma unroll
            for (int ks = 0; ks < 8; ++ks) {
                const int qrow = wid * 16 + (lid & 15);
                const uint32_t qc = (uint32_t)(2 * ks + (lid >> 4));
                const uint32_t qoff = (uint32_t)qrow * 256 + (((qc ^ (qrow & 7))) << 4);
                uint32_t af[4];
                ldsm_x4(af, sb + qoff);
                uint32_t bf[4][4];
#pragma unroll
                for (int j = 0; j < 4; ++j) {
                    const int krow = j * 16 + l8 + (mid >> 1) * 8;
                    const uint32_t kc = (uint32_t)(2 * ks + (mid & 1));
                    const uint32_t koff = (uint32_t)krow * 256 + (((kc ^ (krow & 7))) << 4);
                    ldsm_x4(bf[j], st + koff);
                }
#pragma unroll
                for (int j = 0; j < 4; ++j)
#pragma unroll
                    for (int e = 0; e < 2; ++e)
                        mma16816(sacc[2 * j + e], af, &bf[j][2 * e]);
            }

            // ---- causal mask (diagonal blocks only) ----
            const int rlo = q0 + wid * 16 + (lid >> 2);
            const int rhi = rlo + 8;
            if (kb >= 2 * qb) {
#pragma unroll
                for (int nt = 0; nt < 8; ++nt) {
                    const int c0 = kb * ABS + nt * 8 + (lid & 3) * 2;
                    if (c0 > rlo)     sacc[nt][0] = -1e30f;
                    if (c0 + 1 > rlo) sacc[nt][1] = -1e30f;
                    if (c0 > rhi)     sacc[nt][2] = -1e30f;
                    if (c0 + 1 > rhi) sacc[nt][3] = -1e30f;
                }
            }

            // ---- online softmax (log2 domain) ----
            float mx0 = -1e30f, mx1 = -1e30f;
#pragma unroll
            for (int nt = 0; nt < 8; ++nt) {
                mx0 = fmaxf(mx0, fmaxf(sacc[nt][0], sacc[nt][1]));
                mx1 = fmaxf(mx1, fmaxf(sacc[nt][2], sacc[nt][3]));
            }
            mx0 = fmaxf(mx0, __shfl_xor_sync(0xffffffffu, mx0, 1));
            mx0 = fmaxf(mx0, __shfl_xor_sync(0xffffffffu, mx0, 2));
            mx1 = fmaxf(mx1, __shfl_xor_sync(0xffffffffu, mx1, 1));
            mx1 = fmaxf(mx1, __shfl_xor_sync(0xffffffffu, mx1, 2));
            const float mnew0 = fmaxf(mrow0, mx0);
            const float mnew1 = fmaxf(mrow1, mx1);
            const float alpha0 = ex2a(mrow0 - mnew0);
            const float alpha1 = ex2a(mrow1 - mnew1);
            float sum0 = 0.0f, sum1 = 0.0f;
#pragma unroll
            for (int nt = 0; nt < 8; ++nt) {
                sacc[nt][0] = ex2a(sacc[nt][0] - mnew0); sum0 += sacc[nt][0];
                sacc[nt][1] = ex2a(sacc[nt][1] - mnew0); sum0 += sacc[nt][1];
                sacc[nt][2] = ex2a(sacc[nt][2] - mnew1); sum1 += sacc[nt][2];
                sacc[nt][3] = ex2a(sacc[nt][3] - mnew1); sum1 += sacc[nt][3];
            }
            sum0 += __shfl_xor_sync(0xffffffffu, sum0, 1);
            sum0 += __shfl_xor_sync(0xffffffffu, sum0, 2);
            sum1 += __shfl_xor_sync(0xffffffffu, sum1, 1);
            sum1 += __shfl_xor_sync(0xffffffffu, sum1, 2);
            lrow0 = lrow0 * alpha0 + sum0;  mrow0 = mnew0;
            lrow1 = lrow1 * alpha1 + sum1;  mrow1 = mnew1;
#pragma unroll
            for (int nt = 0; nt < 16; ++nt) {
                oacc[nt][0] *= alpha0; oacc[nt][1] *= alpha0;
                oacc[nt][2] *= alpha1; oacc[nt][3] *= alpha1;
            }

            // ---- O += P . V ----
#pragma unroll
            for (int ks = 0; ks < 4; ++ks) {
                uint32_t ph[4];
#pragma unroll
                for (int half = 0; half < 2; ++half) {
                    const int nt2 = 2 * ks + half;
                    ph[2 * half]     = pack_h2(sacc[nt2][0], sacc[nt2][1]);
                    ph[2 * half + 1] = pack_h2(sacc[nt2][2], sacc[nt2][3]);
                }
#pragma unroll
                for (int half = 0; half < 2; ++half) {
                    uint32_t vf[4][4];
#pragma unroll
                    for (int j = 0; j < 4; ++j) {
                        const int jj = half * 4 + j;
                        const int vrow = ks * 16 + l8 + (mid & 1) * 8;
                        const uint32_t vc = (uint32_t)(jj * 2 + (mid >> 1));
                        const uint32_t voff = (uint32_t)vrow * 256 + (((vc ^ (vrow & 7))) << 4);
                        ldsm_x4_t(vf[j], st + 16384 + voff);
                    }
#pragma unroll
                    for (int j = 0; j < 4; ++j) {
                        const int jj = half * 4 + j;
#pragma unroll
                        for (int e = 0; e < 2; ++e)
                            mma16816(oacc[2 * jj + e], ph, &vf[j][2 * e]);
                    }
                }
            }
        }

        if (kb + 2 < nkb)      { CP_WAIT(1); }
        else if (kb + 1 < nkb) { CP_WAIT(0); }
        if (kb + 1 < nkb) __syncthreads();
    }

    // ---- epilogue: O /= l, write Yf ----
    const float inv0 = 1.0f / lrow0;
    const float inv1 = 1.0f / lrow1;
    const int r0 = q0 + wid * 16 + (lid >> 2);
    const int r1 = r0 + 8;
    const int colb = h * DHH + (lid & 3) * 2;
#pragma unroll
    for (int nt = 0; nt < 16; ++nt) {
        const int col = colb + nt * 8;
        *(uint32_t*)(g_Yf + (size_t)r0 * DD + col) =
            pack_h2(oacc[nt][0] * inv0, oacc[nt][1] * inv0);
        *(uint32_t*)(g_Yf + (size_t)r1 * DD + col) =
            pack_h2(oacc[nt][2] * inv1, oacc[nt][3] * inv1);
    }
}

// ---------------------------------------------------------------------------
// Launch
// ---------------------------------------------------------------------------
extern "C" void kernel_launch(void* const* d_in, const int* in_sizes, int n_in,
                              void* d_out, int out_size)
{
    const float* x  = (const float*)d_in[0];
    const float* Wq = (const float*)d_in[1];
    const float* bq = (const float*)d_in[2];
    const float* Wk = (const float*)d_in[3];
    const float* bk = (const float*)d_in[4];
    const float* Wv = (const float*)d_in[5];
    const float* bv = (const float*)d_in[6];
    const float* Wo = (const float*)d_in[7];
    const float* bo = (const float*)d_in[8];
    float* out = (float*)d_out;

    __half *xf, *wq, *wk, *wv, *wo, *qf, *kf, *vf, *yf;
    cudaGetSymbolAddress((void**)&xf, g_xf);
    cudaGetSymbolAddress((void**)&wq, g_Wq_f); cudaGetSymbolAddress((void**)&wk, g_Wk_f);
    cudaGetSymbolAddress((void**)&wv, g_Wv_f); cudaGetSymbolAddress((void**)&wo, g_Wo_f);
    cudaGetSymbolAddress((void**)&qf, g_Qf);   cudaGetSymbolAddress((void**)&kf, g_Kf);
    cudaGetSymbolAddress((void**)&vf, g_Vf);   cudaGetSymbolAddress((void**)&yf, g_Yf);

    cudaFuncSetAttribute(gemm_mma, cudaFuncAttributeMaxDynamicSharedMemorySize, GEMM_SMEM);
    cudaFuncSetAttribute(attn_mma, cudaFuncAttributeMaxDynamicSharedMemorySize, ATTN_SMEM);

    const int nv4 = (TT * DD / 4) / 256;   // 4096 blocks (float4 granules)
    conv_f16<<<dim3(nv4, 5), 256>>>(x, xf, Wq, wq, Wk, wk, Wv, wv, Wo, wo);

    // fused QKV projection (1-pass): Q (scaled), K, V fp16 out
    gemm_mma<<<dim3(16, 16, 3), 256, GEMM_SMEM>>>(
        xf,
        wq, bq, nullptr, qf, SCALE_Q,
        wk, bk, nullptr, kf, 1.0f,
        wv, bv, nullptr, vf, 1.0f);

    attn_mma<<<256, 256, ATTN_SMEM>>>();

    // output projection (1-pass), fp32 epilogue
    gemm_mma<<<dim3(16, 16, 1), 256, GEMM_SMEM>>>(
        yf,
        wo, bo, out, nullptr, 1.0f,
        wo, bo, out, nullptr, 1.0f,
        wo, bo, out, nullptr, 1.0f);
}

// round 13
// speedup vs baseline: 6.6748x; 1.0187x over previous
#include <cuda_runtime.h>
#include <cuda_fp16.h>
#include <math.h>
#include <stdint.h>

// Problem constants
#define TT 2048
#define DD 2048
#define HH 16
#define DHH 128

// ---------------------------------------------------------------------------
// Scratch (__device__ globals; allocation-free rule).  All fp16 single.
// ---------------------------------------------------------------------------
__device__ __half g_xf[TT * DD];
__device__ __half g_Wq_f[DD * DD], g_Wk_f[DD * DD];
__device__ __half g_Wv_f[DD * DD], g_Wo_f[DD * DD];
__device__ __half g_Qf[TT * DD];                         // Q (pre-scaled)
__device__ __half g_Kf[TT * DD];
__device__ __half g_Vf[TT * DD];
__device__ __half g_Yf[TT * DD];

// ---------------------------------------------------------------------------
// sm_80-ISA helpers (ptxas target here is sm_100 baseline: no tcgen05)
// ---------------------------------------------------------------------------
__device__ __forceinline__ uint32_t smem_to_u32(const void* p) {
    uint32_t a;
    asm("{ .reg .u64 t; cvta.to.shared.u64 t, %1; cvt.u32.u64 %0, t; }"
        : "=r"(a) : "l"(p));
    return a;
}
__device__ __forceinline__ void cp16(uint32_t dst, const void* src) {
    asm volatile("cp.async.cg.shared.global [%0], [%1], 16;"
                 :: "r"(dst), "l"(src) : "memory");
}
#define CP_COMMIT() asm volatile("cp.async.commit_group;" ::: "memory")
#define CP_WAIT(n)  asm volatile("cp.async.wait_group %0;" :: "n"(n) : "memory")

__device__ __forceinline__ void ldsm_x4(uint32_t* r, uint32_t addr) {
    asm volatile("ldmatrix.sync.aligned.m8n8.x4.shared.b16 {%0,%1,%2,%3}, [%4];"
                 : "=r"(r[0]), "=r"(r[1]), "=r"(r[2]), "=r"(r[3]) : "r"(addr));
}
__device__ __forceinline__ void ldsm_x4_t(uint32_t* r, uint32_t addr) {
    asm volatile("ldmatrix.sync.aligned.m8n8.x4.trans.shared.b16 {%0,%1,%2,%3}, [%4];"
                 : "=r"(r[0]), "=r"(r[1]), "=r"(r[2]), "=r"(r[3]) : "r"(addr));
}
__device__ __forceinline__ void mma16816(float* d, const uint32_t* a, const uint32_t* b) {
    asm volatile(
        "mma.sync.aligned.m16n8k16.row.col.f32.f16.f16.f32 "
        "{%0,%1,%2,%3}, {%4,%5,%6,%7}, {%8,%9}, {%0,%1,%2,%3};"
        : "+f"(d[0]), "+f"(d[1]), "+f"(d[2]), "+f"(d[3])
        : "r"(a[0]), "r"(a[1]), "r"(a[2]), "r"(a[3]), "r"(b[0]), "r"(b[1]));
}
__device__ __forceinline__ float ex2a(float x) {
    float y;
    asm("ex2.approx.ftz.f32 %0, %1;" : "=f"(y) : "f"(x));
    return y;
}
__device__ __forceinline__ uint32_t pack_h2(float a, float b) {
    __half2 v = __floats2half2_rn(a, b);
    return *(uint32_t*)&v;
}

#define SCALE_Q (0.08838834764831845f * 1.4426950408889634f)  // 1/sqrt(128)*log2(e)

// ---------------------------------------------------------------------------
// convert fp32 -> fp16 single; blockIdx.y selects one of 5 tensors
// ---------------------------------------------------------------------------
__global__ void conv_f16(const float* __restrict__ s0, __half* __restrict__ d0,
                         const float* __restrict__ s1, __half* __restrict__ d1,
                         const float* __restrict__ s2, __half* __restrict__ d2,
                         const float* __restrict__ s3, __half* __restrict__ d3,
                         const float* __restrict__ s4, __half* __restrict__ d4)
{
    const int z = blockIdx.y;
    const float* s = (z == 0) ? s0 : (z == 1) ? s1 : (z == 2) ? s2 : (z == 3) ? s3 : s4;
    __half* d      = (z == 0) ? d0 : (z == 1) ? d1 : (z == 2) ? d2 : (z == 3) ? d3 : d4;
    const int i = blockIdx.x * blockDim.x + threadIdx.x;
    float4 v = ((const float4*)s)[i];
    ((uint2*)d)[i] = make_uint2(pack_h2(v.x, v.y), pack_h2(v.z, v.w));
}

// ---------------------------------------------------------------------------
// 1-pass fp16 GEMM (UNCHANGED from 296.9us baseline): C = A @ W^T + bias.
// CTA 128x128, BK=64, 8 warps (2x4), 3-stage cp.async pipeline, 2 CTAs/SM.
// ---------------------------------------------------------------------------
#define STAGE_B   32768                // A|W, 16KB each
#define GEMM_SMEM (3 * STAGE_B)        // 98304 -> occ 2

__device__ __forceinline__ void load_tile_cp(const __half* __restrict__ g,
                                             int row0, int k0, uint32_t sdst, int t)
{
#pragma unroll
    for (int i = t; i < 1024; i += 256) {
        const int r = i >> 3, c = i & 7;
        cp16(sdst + r * 128 + ((c ^ (r & 7)) * 16),
             g + (size_t)(row0 + r) * DD + k0 + c * 8);
    }
}

__global__ __launch_bounds__(256, 2)
void gemm_mma(const __half* __restrict__ Af,
              const __half* __restrict__ W0, const float* __restrict__ b0,
              float* Cf0, __half* Ch0, float cs0,
              const __half* __restrict__ W1, const float* __restrict__ b1,
              float* Cf1, __half* Ch1, float cs1,
              const __half* __restrict__ W2, const float* __restrict__ b2,
              float* Cf2, __half* Ch2, float cs2)
{
    extern __shared__ __align__(1024) char smem[];
    const uint32_t sbase = smem_to_u32(smem);
    const int t   = threadIdx.x;
    const int wid = t >> 5;
    const int lid = t & 31;
    const int z   = blockIdx.z;

    const __half* Wf   = (z == 0) ? W0  : ((z == 1) ? W1  : W2);
    const float* bias  = (z == 0) ? b0  : ((z == 1) ? b1  : b2);
    float* Cf          = (z == 0) ? Cf0 : ((z == 1) ? Cf1 : Cf2);
    __half* Ch         = (z == 0) ? Ch0 : ((z == 1) ? Ch1 : Ch2);
    const float cs     = (z == 0) ? cs0 : ((z == 1) ? cs1 : cs2);

    const int bm = blockIdx.y * 128;
    const int bn = blockIdx.x * 128;
    const int warpM = wid >> 2;
    const int warpN = wid & 3;

    float acc[4][4][4];
#pragma unroll
    for (int i = 0; i < 4; i++)
#pragma unroll
        for (int j = 0; j < 4; j++)
#pragma unroll
            for (int k = 0; k < 4; k++) acc[i][j][k] = 0.0f;

    const int l8  = lid & 7;
    const int mid = lid >> 3;
    const int a_cb   = mid >> 1;
    const int a_rowl = warpM * 64 + l8 + (mid & 1) * 8;
    const int b_cb   = mid & 1;
    const int b_rowl = warpN * 32 + l8 + (mid >> 1) * 8;

    uint32_t a_row_off[4], b_row_off[2];
#pragma unroll
    for (int mt = 0; mt < 4; ++mt) a_row_off[mt] = (uint32_t)(a_rowl + mt * 16) * 128u;
#pragma unroll
    for (int j = 0; j < 2; ++j)    b_row_off[j]  = (uint32_t)(b_rowl + j * 16) * 128u;

    uint32_t a_swz[4], b_swz[4];
#pragma unroll
    for (int ks = 0; ks < 4; ++ks) {
        a_swz[ks] = (uint32_t)(((ks * 2 + a_cb) ^ l8) * 16);
        b_swz[ks] = (uint32_t)(((ks * 2 + b_cb) ^ l8) * 16);
    }

    auto load_chunk = [&](int c) {
        const uint32_t st = sbase + (uint32_t)(c % 3) * STAGE_B;
        const int k0 = c * 64;
        load_tile_cp(Af, bm, k0, st, t);
        load_tile_cp(Wf, bn, k0, st + 16384, t);
        CP_COMMIT();
    };

    load_chunk(0);
    load_chunk(1);
    CP_WAIT(1);
    __syncthreads();

    for (int c = 0; c < 32; ++c) {
        if (c + 2 < 32) load_chunk(c + 2);

        const uint32_t st = sbase + (uint32_t)(c % 3) * STAGE_B;
#pragma unroll
        for (int ks = 0; ks < 4; ++ks) {
            uint32_t af[4][4];
#pragma unroll
            for (int mt = 0; mt < 4; ++mt)
                ldsm_x4(af[mt], st + a_row_off[mt] + a_swz[ks]);
            uint32_t bf[2][4];
#pragma unroll
            for (int j = 0; j < 2; ++j)
                ldsm_x4(bf[j], st + 16384 + b_row_off[j] + b_swz[ks]);
#pragma unroll
            for (int mt = 0; mt < 4; ++mt)
#pragma unroll
                for (int nt = 0; nt < 4; ++nt)
                    mma16816(acc[mt][nt], af[mt], &bf[nt >> 1][(nt & 1) * 2]);
        }

        if (c + 2 < 32)      { CP_WAIT(1); }
        else if (c + 1 < 32) { CP_WAIT(0); }
        if (c + 1 < 32) __syncthreads();
    }

    // ---- epilogue ----
    const int lr  = lid >> 2;
    const int lc2 = (lid & 3) * 2;
    float2 bias2[4];
#pragma unroll
    for (int nt = 0; nt < 4; ++nt) {
        const int col = bn + warpN * 32 + nt * 8 + lc2;
        bias2[nt].x = __ldg(&bias[col]);
        bias2[nt].y = __ldg(&bias[col + 1]);
    }
#pragma unroll
    for (int mt = 0; mt < 4; ++mt) {
        const int row0 = bm + warpM * 64 + mt * 16 + lr;
#pragma unroll
        for (int nt = 0; nt < 4; ++nt) {
            const int col = bn + warpN * 32 + nt * 8 + lc2;
            float o0 = acc[mt][nt][0] + bias2[nt].x;
            float o1 = acc[mt][nt][1] + bias2[nt].y;
            float o2 = acc[mt][nt][2] + bias2[nt].x;
            float o3 = acc[mt][nt][3] + bias2[nt].y;
            if (Cf) {
                *(float2*)(Cf + (size_t)row0 * DD + col)       = make_float2(o0, o1);
                *(float2*)(Cf + (size_t)(row0 + 8) * DD + col) = make_float2(o2, o3);
            } else {
                *(uint32_t*)(Ch + (size_t)row0 * DD + col)       = pack_h2(o0 * cs, o1 * cs);
                *(uint32_t*)(Ch + (size_t)(row0 + 8) * DD + col) = pack_h2(o2 * cs, o3 * cs);
            }
        }
    }
}

// ---------------------------------------------------------------------------
// Flash attention, fp16 mma, 128-KEY blocks (one softmax chain per 128 keys).
// CTA = (head, 128-query block). 8 warps, each owns 16 query rows.
// smem: Qf (32KB) + 3 stages of Kf|Vf (64KB each) = 224KB.
// 3-stage cp.async pipeline, one __syncthreads per key block.
// Pipeline prime handles nkb==1 (qb=0): must CP_WAIT(0) when only one
// group was committed (CP_WAIT(1) would NOT wait and compute races the DMA).
// ---------------------------------------------------------------------------
#define ABS 128
#define A_STAGES 32768
#define A_STAGE  65536                        // Kf 32KB | Vf 32KB
#define ATTN_SMEM (A_STAGES + 3 * A_STAGE)    // 229376

__device__ __forceinline__ void attn_load_kv(uint32_t sb, int kb, int h, int t)
{
    const uint32_t stbase = sb + A_STAGES + (uint32_t)(kb % 3) * A_STAGE;
    const int s0 = kb * ABS;
#pragma unroll
    for (int i = t; i < 4096; i += 256) {
        const int tensor = i >> 11;          // 0 Kf, 1 Vf
        const int r = (i >> 4) & 127;
        const int c = i & 15;
        const __half* g = tensor ? g_Vf : g_Kf;
        cp16(stbase + tensor * 32768 + r * 256 + ((c ^ (r & 7)) << 4),
             g + (size_t)(s0 + r) * DD + h * DHH + c * 8);
    }
    CP_COMMIT();
}

__global__ __launch_bounds__(256, 1)
void attn_mma()
{
    extern __shared__ __align__(1024) char smem[];
    const uint32_t sb = smem_to_u32(smem);
    const int t   = threadIdx.x;
    const int wid = t >> 5;
    const int lid = t & 31;
    const int l8  = lid & 7;
    const int mid = lid >> 3;
    const int h   = blockIdx.x & 15;
    const int qb  = 15 - (blockIdx.x >> 4);   // heavy blocks first
    const int q0  = qb * 128;
    const int nkb = qb + 1;

    // ---- prime: group 0 = Q tile + KV block 0, optional group 1 = KV1 ----
#pragma unroll
    for (int i = t; i < 2048; i += 256) {
        const int r = i >> 4;
        const int c = i & 15;
        cp16(sb + r * 256 + ((c ^ (r & 7)) << 4),
             g_Qf + (size_t)(q0 + r) * DD + h * DHH + c * 8);
    }
    attn_load_kv(sb, 0, h, t);            // commits group 0 (Q + KV0)
    if (nkb > 1) {
        attn_load_kv(sb, 1, h, t);        // group 1
        CP_WAIT(1);                       // group 0 complete
    } else {
        CP_WAIT(0);                       // only one group exists: full drain
    }
    __syncthreads();

    float oacc[16][4];
#pragma unroll
    for (int i = 0; i < 16; i++)
#pragma unroll
        for (int j = 0; j < 4; j++) oacc[i][j] = 0.0f;
    float mrow0 = -1e30f, mrow1 = -1e30f, lrow0 = 0.0f, lrow1 = 0.0f;

    for (int kb = 0; kb < nkb; ++kb) {
        if (kb + 2 < nkb) attn_load_kv(sb, kb + 2, h, t);

        const uint32_t st = sb + A_STAGES + (uint32_t)(kb % 3) * A_STAGE;

        // ---- S = Q . K^T  (128 q x 128 s) ----
        float sacc[16][4];
#pragma unroll
        for (int i = 0; i < 16; i++)
#pragma unroll
            for (int j = 0; j < 4; j++) sacc[i][j] = 0.0f;

#pragma unroll
        for (int ks = 0; ks < 8; ++ks) {
            const int qrow = wid * 16 + (lid & 15);
            const uint32_t qc = (uint32_t)(2 * ks + (lid >> 4));
            const uint32_t qoff = (uint32_t)qrow * 256 + (((qc ^ (qrow & 7))) << 4);
            uint32_t af[4];
            ldsm_x4(af, sb + qoff);
#pragma unroll
            for (int j = 0; j < 8; ++j) {
                const int krow = j * 16 + l8 + (mid >> 1) * 8;
                const uint32_t kc = (uint32_t)(2 * ks + (mid & 1));
                const uint32_t koff = (uint32_t)krow * 256 + (((kc ^ (krow & 7))) << 4);
                uint32_t bf[4];
                ldsm_x4(bf, st + koff);
                mma16816(sacc[2 * j],     af, &bf[0]);
                mma16816(sacc[2 * j + 1], af, &bf[2]);
            }
        }

        // ---- causal mask (diagonal block only: kb == qb) ----
        const int rlo = q0 + wid * 16 + (lid >> 2);
        const int rhi = rlo + 8;
        if (kb == qb) {
#pragma unroll
            for (int nt = 0; nt < 16; ++nt) {
                const int c0 = kb * ABS + nt * 8 + (lid & 3) * 2;
                if (c0 > rlo)     sacc[nt][0] = -1e30f;
                if (c0 + 1 > rlo) sacc[nt][1] = -1e30f;
                if (c0 > rhi)     sacc[nt][2] = -1e30f;
                if (c0 + 1 > rhi) sacc[nt][3] = -1e30f;
            }
        }

        // ---- online softmax (log2 domain), ONE chain per 128 keys ----
        float mx0 = -1e30f, mx1 = -1e30f;
#pragma unroll
        for (int nt = 0; nt < 16; ++nt) {
            mx0 = fmaxf(mx0, fmaxf(sacc[nt][0], sacc[nt][1]));
            mx1 = fmaxf(mx1, fmaxf(sacc[nt][2], sacc[nt][3]));
        }
        mx0 = fmaxf(mx0, __shfl_xor_sync(0xffffffffu, mx0, 1));
        mx0 = fmaxf(mx0, __shfl_xor_sync(0xffffffffu, mx0, 2));
        mx1 = fmaxf(mx1, __shfl_xor_sync(0xffffffffu, mx1, 1));
        mx1 = fmaxf(mx1, __shfl_xor_sync(0xffffffffu, mx1, 2));
        const float mnew0 = fmaxf(mrow0, mx0);
        const float mnew1 = fmaxf(mrow1, mx1);
        const float alpha0 = ex2a(mrow0 - mnew0);
        const float alpha1 = ex2a(mrow1 - mnew1);
        float sum0 = 0.0f, sum1 = 0.0f;
#pragma unroll
        for (int nt = 0; nt < 16; ++nt) {
            sacc[nt][0] = ex2a(sacc[nt][0] - mnew0); sum0 += sacc[nt][0];
            sacc[nt][1] = ex2a(sacc[nt][1] - mnew0); sum0 += sacc[nt][1];
            sacc[nt][2] = ex2a(sacc[nt][2] - mnew1); sum1 += sacc[nt][2];
            sacc[nt][3] = ex2a(sacc[nt][3] - mnew1); sum1 += sacc[nt][3];
        }
        sum0 += __shfl_xor_sync(0xffffffffu, sum0, 1);
        sum0 += __shfl_xor_sync(0xffffffffu, sum0, 2);
        sum1 += __shfl_xor_sync(0xffffffffu, sum1, 1);
        sum1 += __shfl_xor_sync(0xffffffffu, sum1, 2);
        lrow0 = lrow0 * alpha0 + sum0;  mrow0 = mnew0;
        lrow1 = lrow1 * alpha1 + sum1;  mrow1 = mnew1;
#pragma unroll
        for (int nt = 0; nt < 16; ++nt) {
            oacc[nt][0] *= alpha0; oacc[nt][1] *= alpha0;
            oacc[nt][2] *= alpha1; oacc[nt][3] *= alpha1;
        }

        // ---- O += P . V  (128 s-rows) ----
#pragma unroll
        for (int ks = 0; ks < 8; ++ks) {
            uint32_t ph[4];
            ph[0] = pack_h2(sacc[2 * ks][0],     sacc[2 * ks][1]);
            ph[1] = pack_h2(sacc[2 * ks][2],     sacc[2 * ks][3]);
            ph[2] = pack_h2(sacc[2 * ks + 1][0], sacc[2 * ks + 1][1]);
            ph[3] = pack_h2(sacc[2 * ks + 1][2], sacc[2 * ks + 1][3]);
            const int vrow = ks * 16 + l8 + (mid & 1) * 8;
#pragma unroll
            for (int jj = 0; jj < 8; ++jj) {
                const uint32_t vc = (uint32_t)(jj * 2 + (mid >> 1));
                const uint32_t voff = (uint32_t)vrow * 256 + (((vc ^ (vrow & 7))) << 4);
                uint32_t vf[4];
                ldsm_x4_t(vf, st + 32768 + voff);
                mma16816(oacc[2 * jj],     ph, &vf[0]);
                mma16816(oacc[2 * jj + 1], ph, &vf[2]);
            }
        }

        if (kb + 2 < nkb)      { CP_WAIT(1); }
        else if (kb + 1 < nkb) { CP_WAIT(0); }
        if (kb + 1 < nkb) __syncthreads();
    }

    // ---- epilogue: O /= l, write Yf ----
    const float inv0 = 1.0f / lrow0;
    const float inv1 = 1.0f / lrow1;
    const int r0 = q0 + wid * 16 + (lid >> 2);
    const int r1 = r0 + 8;
    const int colb = h * DHH + (lid & 3) * 2;
#pragma unroll
    for (int nt = 0; nt < 16; ++nt) {
        const int col = colb + nt * 8;
        *(uint32_t*)(g_Yf + (size_t)r0 * DD + col) =
            pack_h2(oacc[nt][0] * inv0, oacc[nt][1] * inv0);
        *(uint32_t*)(g_Yf + (size_t)r1 * DD + col) =
            pack_h2(oacc[nt][2] * inv1, oacc[nt][3] * inv1);
    }
}

// ---------------------------------------------------------------------------
// Launch
// ---------------------------------------------------------------------------
extern "C" void kernel_launch(void* const* d_in, const int* in_sizes, int n_in,
                              void* d_out, int out_size)
{
    const float* x  = (const float*)d_in[0];
    const float* Wq = (const float*)d_in[1];
    const float* bq = (const float*)d_in[2];
    const float* Wk = (const float*)d_in[3];
    const float* bk = (const float*)d_in[4];
    const float* Wv = (const float*)d_in[5];
    const float* bv = (const float*)d_in[6];
    const float* Wo = (const float*)d_in[7];
    const float* bo = (const float*)d_in[8];
    float* out = (float*)d_out;

    __half *xf, *wq, *wk, *wv, *wo, *qf, *kf, *vf, *yf;
    cudaGetSymbolAddress((void**)&xf, g_xf);
    cudaGetSymbolAddress((void**)&wq, g_Wq_f); cudaGetSymbolAddress((void**)&wk, g_Wk_f);
    cudaGetSymbolAddress((void**)&wv, g_Wv_f); cudaGetSymbolAddress((void**)&wo, g_Wo_f);
    cudaGetSymbolAddress((void**)&qf, g_Qf);   cudaGetSymbolAddress((void**)&kf, g_Kf);
    cudaGetSymbolAddress((void**)&vf, g_Vf);   cudaGetSymbolAddress((void**)&yf, g_Yf);

    cudaFuncSetAttribute(gemm_mma, cudaFuncAttributeMaxDynamicSharedMemorySize, GEMM_SMEM);
    cudaFuncSetAttribute(attn_mma, cudaFuncAttributeMaxDynamicSharedMemorySize, ATTN_SMEM);

    const int nv4 = (TT * DD / 4) / 256;   // 4096 blocks (float4 granules)
    conv_f16<<<dim3(nv4, 5), 256>>>(x, xf, Wq, wq, Wk, wk, Wv, wv, Wo, wo);

    // fused QKV projection (1-pass): Q (scaled), K, V fp16 out
    gemm_mma<<<dim3(16, 16, 3), 256, GEMM_SMEM>>>(
        xf,
        wq, bq, nullptr, qf, SCALE_Q,
        wk, bk, nullptr, kf, 1.0f,
        wv, bv, nullptr, vf, 1.0f);

    attn_mma<<<256, 256, ATTN_SMEM>>>();

    // output projection (1-pass), fp32 epilogue
    gemm_mma<<<dim3(16, 16, 1), 256, GEMM_SMEM>>>(
        yf,
        wo, bo, out, nullptr, 1.0f,
        wo, bo, out, nullptr, 1.0f,
        wo, bo, out, nullptr, 1.0f);
}

// round 15
// speedup vs baseline: 6.7250x; 1.0075x over previous
#include <cuda_runtime.h>
#include <cuda_fp16.h>
#include <math.h>
#include <stdint.h>

// Problem constants
#define TT 2048
#define DD 2048
#define HH 16
#define DHH 128

// ---------------------------------------------------------------------------
// Scratch (__device__ globals; allocation-free rule).  All fp16 single.
// ---------------------------------------------------------------------------
__device__ __half g_xf[TT * DD];
__device__ __half g_Wq_f[DD * DD], g_Wk_f[DD * DD];
__device__ __half g_Wv_f[DD * DD], g_Wo_f[DD * DD];
__device__ __half g_Qf[TT * DD];                         // Q (pre-scaled)
__device__ __half g_Kf[TT * DD];
__device__ __half g_Vf[TT * DD];
__device__ __half g_Yf[TT * DD];

// ---------------------------------------------------------------------------
// sm_80-ISA helpers (ptxas target here is sm_100 baseline: no tcgen05)
// ---------------------------------------------------------------------------
__device__ __forceinline__ uint32_t smem_to_u32(const void* p) {
    uint32_t a;
    asm("{ .reg .u64 t; cvta.to.shared.u64 t, %1; cvt.u32.u64 %0, t; }"
        : "=r"(a) : "l"(p));
    return a;
}
__device__ __forceinline__ void cp16(uint32_t dst, const void* src) {
    asm volatile("cp.async.cg.shared.global [%0], [%1], 16;"
                 :: "r"(dst), "l"(src) : "memory");
}
#define CP_COMMIT() asm volatile("cp.async.commit_group;" ::: "memory")
#define CP_WAIT(n)  asm volatile("cp.async.wait_group %0;" :: "n"(n) : "memory")

__device__ __forceinline__ void ldsm_x4(uint32_t* r, uint32_t addr) {
    asm volatile("ldmatrix.sync.aligned.m8n8.x4.shared.b16 {%0,%1,%2,%3}, [%4];"
                 : "=r"(r[0]), "=r"(r[1]), "=r"(r[2]), "=r"(r[3]) : "r"(addr));
}
__device__ __forceinline__ void ldsm_x4_t(uint32_t* r, uint32_t addr) {
    asm volatile("ldmatrix.sync.aligned.m8n8.x4.trans.shared.b16 {%0,%1,%2,%3}, [%4];"
                 : "=r"(r[0]), "=r"(r[1]), "=r"(r[2]), "=r"(r[3]) : "r"(addr));
}
__device__ __forceinline__ void mma16816(float* d, const uint32_t* a, const uint32_t* b) {
    asm volatile(
        "mma.sync.aligned.m16n8k16.row.col.f32.f16.f16.f32 "
        "{%0,%1,%2,%3}, {%4,%5,%6,%7}, {%8,%9}, {%0,%1,%2,%3};"
        : "+f"(d[0]), "+f"(d[1]), "+f"(d[2]), "+f"(d[3])
        : "r"(a[0]), "r"(a[1]), "r"(a[2]), "r"(a[3]), "r"(b[0]), "r"(b[1]));
}
__device__ __forceinline__ float ex2a(float x) {
    float y;
    asm("ex2.approx.ftz.f32 %0, %1;" : "=f"(y) : "f"(x));
    return y;
}
__device__ __forceinline__ uint32_t pack_h2(float a, float b) {
    __half2 v = __floats2half2_rn(a, b);
    return *(uint32_t*)&v;
}

#define SCALE_Q (0.08838834764831845f * 1.4426950408889634f)  // 1/sqrt(128)*log2(e)

// ---------------------------------------------------------------------------
// convert fp32 -> fp16 single; blockIdx.y selects one of 5 tensors
// ---------------------------------------------------------------------------
__global__ void conv_f16(const float* __restrict__ s0, __half* __restrict__ d0,
                         const float* __restrict__ s1, __half* __restrict__ d1,
                         const float* __restrict__ s2, __half* __restrict__ d2,
                         const float* __restrict__ s3, __half* __restrict__ d3,
                         const float* __restrict__ s4, __half* __restrict__ d4)
{
    const int z = blockIdx.y;
    const float* s = (z == 0) ? s0 : (z == 1) ? s1 : (z == 2) ? s2 : (z == 3) ? s3 : s4;
    __half* d      = (z == 0) ? d0 : (z == 1) ? d1 : (z == 2) ? d2 : (z == 3) ? d3 : d4;
    const int i = blockIdx.x * blockDim.x + threadIdx.x;
    float4 v = ((const float4*)s)[i];
    ((uint2*)d)[i] = make_uint2(pack_h2(v.x, v.y), pack_h2(v.z, v.w));
}

// ---------------------------------------------------------------------------
// 1-pass fp16 GEMM: C = A @ W^T + bias, fp32 accum.
// CTA tile 128(M) x 256(N), BK=64, 8 warps in 2x4, warp tile 64x64
// (acc 128 regs) -> smem LDSM traffic 125B/HMMA (was 187).
// 3-stage cp.async pipeline, one __syncthreads per chunk, occ 1.
// ---------------------------------------------------------------------------
#define STAGE_B   49152                // A 16KB | W 32KB
#define GEMM_SMEM (3 * STAGE_B)        // 147456

__device__ __forceinline__ void load_tile_cp(const __half* __restrict__ g,
                                             int row0, int k0, uint32_t sdst,
                                             int t, int n16)
{
#pragma unroll
    for (int i = t; i < n16; i += 256) {
        const int r = i >> 3, c = i & 7;
        cp16(sdst + r * 128 + ((c ^ (r & 7)) * 16),
             g + (size_t)(row0 + r) * DD + k0 + c * 8);
    }
}

__global__ __launch_bounds__(256, 1)
void gemm_mma(const __half* __restrict__ Af,
              const __half* __restrict__ W0, const float* __restrict__ b0,
              float* Cf0, __half* Ch0, float cs0,
              const __half* __restrict__ W1, const float* __restrict__ b1,
              float* Cf1, __half* Ch1, float cs1,
              const __half* __restrict__ W2, const float* __restrict__ b2,
              float* Cf2, __half* Ch2, float cs2)
{
    extern __shared__ __align__(1024) char smem[];
    const uint32_t sbase = smem_to_u32(smem);
    const int t   = threadIdx.x;
    const int wid = t >> 5;
    const int lid = t & 31;
    const int z   = blockIdx.z;

    const __half* Wf   = (z == 0) ? W0  : ((z == 1) ? W1  : W2);
    const float* bias  = (z == 0) ? b0  : ((z == 1) ? b1  : b2);
    float* Cf          = (z == 0) ? Cf0 : ((z == 1) ? Cf1 : Cf2);
    __half* Ch         = (z == 0) ? Ch0 : ((z == 1) ? Ch1 : Ch2);
    const float cs     = (z == 0) ? cs0 : ((z == 1) ? cs1 : cs2);

    const int bm = blockIdx.y * 128;
    const int bn = blockIdx.x * 256;
    const int warpM = wid >> 2;       // 0..1  (64 M-rows each)
    const int warpN = wid & 3;        // 0..3  (64 N-cols each)

    float acc[4][8][4];
#pragma unroll
    for (int i = 0; i < 4; i++)
#pragma unroll
        for (int j = 0; j < 8; j++)
#pragma unroll
            for (int k = 0; k < 4; k++) acc[i][j][k] = 0.0f;

    const int l8  = lid & 7;
    const int mid = lid >> 3;
    const int a_cb   = mid >> 1;
    const int a_rowl = warpM * 64 + l8 + (mid & 1) * 8;
    const int b_cb   = mid & 1;
    const int b_rowl = warpN * 64 + l8 + (mid >> 1) * 8;

    uint32_t a_row_off[4], b_row_off[4];
#pragma unroll
    for (int mt = 0; mt < 4; ++mt) a_row_off[mt] = (uint32_t)(a_rowl + mt * 16) * 128u;
#pragma unroll
    for (int j = 0; j < 4; ++j)    b_row_off[j]  = (uint32_t)(b_rowl + j * 16) * 128u;

    uint32_t a_swz[4], b_swz[4];
#pragma unroll
    for (int ks = 0; ks < 4; ++ks) {
        a_swz[ks] = (uint32_t)(((ks * 2 + a_cb) ^ l8) * 16);
        b_swz[ks] = (uint32_t)(((ks * 2 + b_cb) ^ l8) * 16);
    }

    auto load_chunk = [&](int c) {
        const uint32_t st = sbase + (uint32_t)(c % 3) * STAGE_B;
        const int k0 = c * 64;
        load_tile_cp(Af, bm, k0, st, t, 1024);            // A 128x64
        load_tile_cp(Wf, bn, k0, st + 16384, t, 2048);    // W 256x64
        CP_COMMIT();
    };

    load_chunk(0);
    load_chunk(1);
    CP_WAIT(1);
    __syncthreads();

    for (int c = 0; c < 32; ++c) {
        if (c + 2 < 32) load_chunk(c + 2);

        const uint32_t st = sbase + (uint32_t)(c % 3) * STAGE_B;
#pragma unroll
        for (int ks = 0; ks < 4; ++ks) {
            uint32_t af[4][4];
#pragma unroll
            for (int mt = 0; mt < 4; ++mt)
                ldsm_x4(af[mt], st + a_row_off[mt] + a_swz[ks]);
            uint32_t bf[4][4];
#pragma unroll
            for (int j = 0; j < 4; ++j)
                ldsm_x4(bf[j], st + 16384 + b_row_off[j] + b_swz[ks]);
#pragma unroll
            for (int mt = 0; mt < 4; ++mt)
#pragma unroll
                for (int nt = 0; nt < 8; ++nt)
                    mma16816(acc[mt][nt], af[mt], &bf[nt >> 1][(nt & 1) * 2]);
        }

        if (c + 2 < 32)      { CP_WAIT(1); }
        else if (c + 1 < 32) { CP_WAIT(0); }
        if (c + 1 < 32) __syncthreads();
    }

    // ---- epilogue ----
    const int lr  = lid >> 2;
    const int lc2 = (lid & 3) * 2;
    float2 bias2[8];
#pragma unroll
    for (int nt = 0; nt < 8; ++nt) {
        const int col = bn + warpN * 64 + nt * 8 + lc2;
        bias2[nt].x = __ldg(&bias[col]);
        bias2[nt].y = __ldg(&bias[col + 1]);
    }
#pragma unroll
    for (int mt = 0; mt < 4; ++mt) {
        const int row0 = bm + warpM * 64 + mt * 16 + lr;
#pragma unroll
        for (int nt = 0; nt < 8; ++nt) {
            const int col = bn + warpN * 64 + nt * 8 + lc2;
            float o0 = acc[mt][nt][0] + bias2[nt].x;
            float o1 = acc[mt][nt][1] + bias2[nt].y;
            float o2 = acc[mt][nt][2] + bias2[nt].x;
            float o3 = acc[mt][nt][3] + bias2[nt].y;
            if (Cf) {
                *(float2*)(Cf + (size_t)row0 * DD + col)       = make_float2(o0, o1);
                *(float2*)(Cf + (size_t)(row0 + 8) * DD + col) = make_float2(o2, o3);
            } else {
                *(uint32_t*)(Ch + (size_t)row0 * DD + col)       = pack_h2(o0 * cs, o1 * cs);
                *(uint32_t*)(Ch + (size_t)(row0 + 8) * DD + col) = pack_h2(o2 * cs, o3 * cs);
            }
        }
    }
}

// ---------------------------------------------------------------------------
// Flash attention, fp16 mma, 128-KEY blocks (UNCHANGED from 291.5us pass).
// ---------------------------------------------------------------------------
#define ABS 128
#define A_STAGES 32768
#define A_STAGE  65536                        // Kf 32KB | Vf 32KB
#define ATTN_SMEM (A_STAGES + 3 * A_STAGE)    // 229376

__device__ __forceinline__ void attn_load_kv(uint32_t sb, int kb, int h, int t)
{
    const uint32_t stbase = sb + A_STAGES + (uint32_t)(kb % 3) * A_STAGE;
    const int s0 = kb * ABS;
#pragma unroll
    for (int i = t; i < 4096; i += 256) {
        const int tensor = i >> 11;          // 0 Kf, 1 Vf
        const int r = (i >> 4) & 127;
        const int c = i & 15;
        const __half* g = tensor ? g_Vf : g_Kf;
        cp16(stbase + tensor * 32768 + r * 256 + ((c ^ (r & 7)) << 4),
             g + (size_t)(s0 + r) * DD + h * DHH + c * 8);
    }
    CP_COMMIT();
}

__global__ __launch_bounds__(256, 1)
void attn_mma()
{
    extern __shared__ __align__(1024) char smem[];
    const uint32_t sb = smem_to_u32(smem);
    const int t   = threadIdx.x;
    const int wid = t >> 5;
    const int lid = t & 31;
    const int l8  = lid & 7;
    const int mid = lid >> 3;
    const int h   = blockIdx.x & 15;
    const int qb  = 15 - (blockIdx.x >> 4);   // heavy blocks first
    const int q0  = qb * 128;
    const int nkb = qb + 1;

    // ---- prime: group 0 = Q tile + KV block 0, optional group 1 = KV1 ----
#pragma unroll
    for (int i = t; i < 2048; i += 256) {
        const int r = i >> 4;
        const int c = i & 15;
        cp16(sb + r * 256 + ((c ^ (r & 7)) << 4),
             g_Qf + (size_t)(q0 + r) * DD + h * DHH + c * 8);
    }
    attn_load_kv(sb, 0, h, t);            // commits group 0 (Q + KV0)
    if (nkb > 1) {
        attn_load_kv(sb, 1, h, t);        // group 1
        CP_WAIT(1);                       // group 0 complete
    } else {
        CP_WAIT(0);                       // only one group exists: full drain
    }
    __syncthreads();

    float oacc[16][4];
#pragma unroll
    for (int i = 0; i < 16; i++)
#pragma unroll
        for (int j = 0; j < 4; j++) oacc[i][j] = 0.0f;
    float mrow0 = -1e30f, mrow1 = -1e30f, lrow0 = 0.0f, lrow1 = 0.0f;

    for (int kb = 0; kb < nkb; ++kb) {
        if (kb + 2 < nkb) attn_load_kv(sb, kb + 2, h, t);

        const uint32_t st = sb + A_STAGES + (uint32_t)(kb % 3) * A_STAGE;

        // ---- S = Q . K^T  (128 q x 128 s) ----
        float sacc[16][4];
#pragma unroll
        for (int i = 0; i < 16; i++)
#pragma unroll
            for (int j = 0; j < 4; j++) sacc[i][j] = 0.0f;

#pragma unroll
        for (int ks = 0; ks < 8; ++ks) {
            const int qrow = wid * 16 + (lid & 15);
            const uint32_t qc = (uint32_t)(2 * ks + (lid >> 4));
            const uint32_t qoff = (uint32_t)qrow * 256 + (((qc ^ (qrow & 7))) << 4);
            uint32_t af[4];
            ldsm_x4(af, sb + qoff);
#pragma unroll
            for (int j = 0; j < 8; ++j) {
                const int krow = j * 16 + l8 + (mid >> 1) * 8;
                const uint32_t kc = (uint32_t)(2 * ks + (mid & 1));
                const uint32_t koff = (uint32_t)krow * 256 + (((kc ^ (krow & 7))) << 4);
                uint32_t bf[4];
                ldsm_x4(bf, st + koff);
                mma16816(sacc[2 * j],     af, &bf[0]);
                mma16816(sacc[2 * j + 1], af, &bf[2]);
            }
        }

        // ---- causal mask (diagonal block only: kb == qb) ----
        const int rlo = q0 + wid * 16 + (lid >> 2);
        const int rhi = rlo + 8;
        if (kb == qb) {
#pragma unroll
            for (int nt = 0; nt < 16; ++nt) {
                const int c0 = kb * ABS + nt * 8 + (lid & 3) * 2;
                if (c0 > rlo)     sacc[nt][0] = -1e30f;
                if (c0 + 1 > rlo) sacc[nt][1] = -1e30f;
                if (c0 > rhi)     sacc[nt][2] = -1e30f;
                if (c0 + 1 > rhi) sacc[nt][3] = -1e30f;
            }
        }

        // ---- online softmax (log2 domain), ONE chain per 128 keys ----
        float mx0 = -1e30f, mx1 = -1e30f;
#pragma unroll
        for (int nt = 0; nt < 16; ++nt) {
            mx0 = fmaxf(mx0, fmaxf(sacc[nt][0], sacc[nt][1]));
            mx1 = fmaxf(mx1, fmaxf(sacc[nt][2], sacc[nt][3]));
        }
        mx0 = fmaxf(mx0, __shfl_xor_sync(0xffffffffu, mx0, 1));
        mx0 = fmaxf(mx0, __shfl_xor_sync(0xffffffffu, mx0, 2));
        mx1 = fmaxf(mx1, __shfl_xor_sync(0xffffffffu, mx1, 1));
        mx1 = fmaxf(mx1, __shfl_xor_sync(0xffffffffu, mx1, 2));
        const float mnew0 = fmaxf(mrow0, mx0);
        const float mnew1 = fmaxf(mrow1, mx1);
        const float alpha0 = ex2a(mrow0 - mnew0);
        const float alpha1 = ex2a(mrow1 - mnew1);
        float sum0 = 0.0f, sum1 = 0.0f;
#pragma unroll
        for (int nt = 0; nt < 16; ++nt) {
            sacc[nt][0] = ex2a(sacc[nt][0] - mnew0); sum0 += sacc[nt][0];
            sacc[nt][1] = ex2a(sacc[nt][1] - mnew0); sum0 += sacc[nt][1];
            sacc[nt][2] = ex2a(sacc[nt][2] - mnew1); sum1 += sacc[nt][2];
            sacc[nt][3] = ex2a(sacc[nt][3] - mnew1); sum1 += sacc[nt][3];
        }
        sum0 += __shfl_xor_sync(0xffffffffu, sum0, 1);
        sum0 += __shfl_xor_sync(0xffffffffu, sum0, 2);
        sum1 += __shfl_xor_sync(0xffffffffu, sum1, 1);
        sum1 += __shfl_xor_sync(0xffffffffu, sum1, 2);
        lrow0 = lrow0 * alpha0 + sum0;  mrow0 = mnew0;
        lrow1 = lrow1 * alpha1 + sum1;  mrow1 = mnew1;
#pragma unroll
        for (int nt = 0; nt < 16; ++nt) {
            oacc[nt][0] *= alpha0; oacc[nt][1] *= alpha0;
            oacc[nt][2] *= alpha1; oacc[nt][3] *= alpha1;
        }

        // ---- O += P . V  (128 s-rows) ----
#pragma unroll
        for (int ks = 0; ks < 8; ++ks) {
            uint32_t ph[4];
            ph[0] = pack_h2(sacc[2 * ks][0],     sacc[2 * ks][1]);
            ph[1] = pack_h2(sacc[2 * ks][2],     sacc[2 * ks][3]);
            ph[2] = pack_h2(sacc[2 * ks + 1][0], sacc[2 * ks + 1][1]);
            ph[3] = pack_h2(sacc[2 * ks + 1][2], sacc[2 * ks + 1][3]);
            const int vrow = ks * 16 + l8 + (mid & 1) * 8;
#pragma unroll
            for (int jj = 0; jj < 8; ++jj) {
                const uint32_t vc = (uint32_t)(jj * 2 + (mid >> 1));
                const uint32_t voff = (uint32_t)vrow * 256 + (((vc ^ (vrow & 7))) << 4);
                uint32_t vf[4];
                ldsm_x4_t(vf, st + 32768 + voff);
                mma16816(oacc[2 * jj],     ph, &vf[0]);
                mma16816(oacc[2 * jj + 1], ph, &vf[2]);
            }
        }

        if (kb + 2 < nkb)      { CP_WAIT(1); }
        else if (kb + 1 < nkb) { CP_WAIT(0); }
        if (kb + 1 < nkb) __syncthreads();
    }

    // ---- epilogue: O /= l, write Yf ----
    const float inv0 = 1.0f / lrow0;
    const float inv1 = 1.0f / lrow1;
    const int r0 = q0 + wid * 16 + (lid >> 2);
    const int r1 = r0 + 8;
    const int colb = h * DHH + (lid & 3) * 2;
#pragma unroll
    for (int nt = 0; nt < 16; ++nt) {
        const int col = colb + nt * 8;
        *(uint32_t*)(g_Yf + (size_t)r0 * DD + col) =
            pack_h2(oacc[nt][0] * inv0, oacc[nt][1] * inv0);
        *(uint32_t*)(g_Yf + (size_t)r1 * DD + col) =
            pack_h2(oacc[nt][2] * inv1, oacc[nt][3] * inv1);
    }
}

// ---------------------------------------------------------------------------
// Launch
// ---------------------------------------------------------------------------
extern "C" void kernel_launch(void* const* d_in, const int* in_sizes, int n_in,
                              void* d_out, int out_size)
{
    const float* x  = (const float*)d_in[0];
    const float* Wq = (const float*)d_in[1];
    const float* bq = (const float*)d_in[2];
    const float* Wk = (const float*)d_in[3];
    const float* bk = (const float*)d_in[4];
    const float* Wv = (const float*)d_in[5];
    const float* bv = (const float*)d_in[6];
    const float* Wo = (const float*)d_in[7];
    const float* bo = (const float*)d_in[8];
    float* out = (float*)d_out;

    __half *xf, *wq, *wk, *wv, *wo, *qf, *kf, *vf, *yf;
    cudaGetSymbolAddress((void**)&xf, g_xf);
    cudaGetSymbolAddress((void**)&wq, g_Wq_f); cudaGetSymbolAddress((void**)&wk, g_Wk_f);
    cudaGetSymbolAddress((void**)&wv, g_Wv_f); cudaGetSymbolAddress((void**)&wo, g_Wo_f);
    cudaGetSymbolAddress((void**)&qf, g_Qf);   cudaGetSymbolAddress((void**)&kf, g_Kf);
    cudaGetSymbolAddress((void**)&vf, g_Vf);   cudaGetSymbolAddress((void**)&yf, g_Yf);

    cudaFuncSetAttribute(gemm_mma, cudaFuncAttributeMaxDynamicSharedMemorySize, GEMM_SMEM);
    cudaFuncSetAttribute(attn_mma, cudaFuncAttributeMaxDynamicSharedMemorySize, ATTN_SMEM);

    const int nv4 = (TT * DD / 4) / 256;   // 4096 blocks (float4 granules)
    conv_f16<<<dim3(nv4, 5), 256>>>(x, xf, Wq, wq, Wk, wk, Wv, wv, Wo, wo);

    // fused QKV projection (1-pass): Q (scaled), K, V fp16 out; N-tile 256
    gemm_mma<<<dim3(8, 16, 3), 256, GEMM_SMEM>>>(
        xf,
        wq, bq, nullptr, qf, SCALE_Q,
        wk, bk, nullptr, kf, 1.0f,
        wv, bv, nullptr, vf, 1.0f);

    attn_mma<<<256, 256, ATTN_SMEM>>>();

    // output projection (1-pass), fp32 epilogue; N-tile 256
    gemm_mma<<<dim3(8, 16, 1), 256, GEMM_SMEM>>>(
        yf,
        wo, bo, out, nullptr, 1.0f,
        wo, bo, out, nullptr, 1.0f,
        wo, bo, out, nullptr, 1.0f);
}

// round 17
// speedup vs baseline: 6.7302x; 1.0008x over previous
#include <cuda_runtime.h>
#include <cuda_fp16.h>
#include <math.h>
#include <stdint.h>

// Problem constants
#define TT 2048
#define DD 2048
#define HH 16
#define DHH 128

// ---------------------------------------------------------------------------
// Scratch (__device__ globals; allocation-free rule).  All fp16 single.
// ---------------------------------------------------------------------------
__device__ __half g_xf[TT * DD];
__device__ __half g_Wq_f[DD * DD], g_Wk_f[DD * DD];
__device__ __half g_Wv_f[DD * DD], g_Wo_f[DD * DD];
__device__ __half g_Qf[TT * DD];                         // Q (pre-scaled)
__device__ __half g_Kf[TT * DD];
__device__ __half g_Vf[TT * DD];
__device__ __half g_Yf[TT * DD];

// ---------------------------------------------------------------------------
// sm_80-ISA helpers (ptxas target here is sm_100 baseline: no tcgen05)
// ---------------------------------------------------------------------------
__device__ __forceinline__ uint32_t smem_to_u32(const void* p) {
    uint32_t a;
    asm("{ .reg .u64 t; cvta.to.shared.u64 t, %1; cvt.u32.u64 %0, t; }"
        : "=r"(a) : "l"(p));
    return a;
}
__device__ __forceinline__ void cp16(uint32_t dst, const void* src) {
    asm volatile("cp.async.cg.shared.global [%0], [%1], 16;"
                 :: "r"(dst), "l"(src) : "memory");
}
#define CP_COMMIT() asm volatile("cp.async.commit_group;" ::: "memory")
#define CP_WAIT(n)  asm volatile("cp.async.wait_group %0;" :: "n"(n) : "memory")

__device__ __forceinline__ void ldsm_x4(uint32_t* r, uint32_t addr) {
    asm volatile("ldmatrix.sync.aligned.m8n8.x4.shared.b16 {%0,%1,%2,%3}, [%4];"
                 : "=r"(r[0]), "=r"(r[1]), "=r"(r[2]), "=r"(r[3]) : "r"(addr));
}
__device__ __forceinline__ void ldsm_x4_t(uint32_t* r, uint32_t addr) {
    asm volatile("ldmatrix.sync.aligned.m8n8.x4.trans.shared.b16 {%0,%1,%2,%3}, [%4];"
                 : "=r"(r[0]), "=r"(r[1]), "=r"(r[2]), "=r"(r[3]) : "r"(addr));
}
__device__ __forceinline__ void mma16816(float* d, const uint32_t* a, const uint32_t* b) {
    asm volatile(
        "mma.sync.aligned.m16n8k16.row.col.f32.f16.f16.f32 "
        "{%0,%1,%2,%3}, {%4,%5,%6,%7}, {%8,%9}, {%0,%1,%2,%3};"
        : "+f"(d[0]), "+f"(d[1]), "+f"(d[2]), "+f"(d[3])
        : "r"(a[0]), "r"(a[1]), "r"(a[2]), "r"(a[3]), "r"(b[0]), "r"(b[1]));
}
__device__ __forceinline__ float ex2a(float x) {
    float y;
    asm("ex2.approx.ftz.f32 %0, %1;" : "=f"(y) : "f"(x));
    return y;
}
__device__ __forceinline__ uint32_t pack_h2(float a, float b) {
    __half2 v = __floats2half2_rn(a, b);
    return *(uint32_t*)&v;
}

#define SCALE_Q (0.08838834764831845f * 1.4426950408889634f)  // 1/sqrt(128)*log2(e)

// ---------------------------------------------------------------------------
// convert fp32 -> fp16 single; blockIdx.y selects one of 5 tensors
// ---------------------------------------------------------------------------
__global__ void conv_f16(const float* __restrict__ s0, __half* __restrict__ d0,
                         const float* __restrict__ s1, __half* __restrict__ d1,
                         const float* __restrict__ s2, __half* __restrict__ d2,
                         const float* __restrict__ s3, __half* __restrict__ d3,
                         const float* __restrict__ s4, __half* __restrict__ d4)
{
    const int z = blockIdx.y;
    const float* s = (z == 0) ? s0 : (z == 1) ? s1 : (z == 2) ? s2 : (z == 3) ? s3 : s4;
    __half* d      = (z == 0) ? d0 : (z == 1) ? d1 : (z == 2) ? d2 : (z == 3) ? d3 : d4;
    const int i = blockIdx.x * blockDim.x + threadIdx.x;
    float4 v = ((const float4*)s)[i];
    ((uint2*)d)[i] = make_uint2(pack_h2(v.x, v.y), pack_h2(v.z, v.w));
}

// ---------------------------------------------------------------------------
// 1-pass fp16 GEMM (UNCHANGED from 289.3us baseline): C = A @ W^T + bias.
// CTA tile 128(M) x 256(N), BK=64, 8 warps in 2x4, warp tile 64x64.
// 3-stage cp.async pipeline, one __syncthreads per chunk, occ 1.
// ---------------------------------------------------------------------------
#define STAGE_B   49152                // A 16KB | W 32KB
#define GEMM_SMEM (3 * STAGE_B)        // 147456

__device__ __forceinline__ void load_tile_cp(const __half* __restrict__ g,
                                             int row0, int k0, uint32_t sdst,
                                             int t, int n16)
{
#pragma unroll
    for (int i = t; i < n16; i += 256) {
        const int r = i >> 3, c = i & 7;
        cp16(sdst + r * 128 + ((c ^ (r & 7)) * 16),
             g + (size_t)(row0 + r) * DD + k0 + c * 8);
    }
}

__global__ __launch_bounds__(256, 1)
void gemm_mma(const __half* __restrict__ Af,
              const __half* __restrict__ W0, const float* __restrict__ b0,
              float* Cf0, __half* Ch0, float cs0,
              const __half* __restrict__ W1, const float* __restrict__ b1,
              float* Cf1, __half* Ch1, float cs1,
              const __half* __restrict__ W2, const float* __restrict__ b2,
              float* Cf2, __half* Ch2, float cs2)
{
    extern __shared__ __align__(1024) char smem[];
    const uint32_t sbase = smem_to_u32(smem);
    const int t   = threadIdx.x;
    const int wid = t >> 5;
    const int lid = t & 31;
    const int z   = blockIdx.z;

    const __half* Wf   = (z == 0) ? W0  : ((z == 1) ? W1  : W2);
    const float* bias  = (z == 0) ? b0  : ((z == 1) ? b1  : b2);
    float* Cf          = (z == 0) ? Cf0 : ((z == 1) ? Cf1 : Cf2);
    __half* Ch         = (z == 0) ? Ch0 : ((z == 1) ? Ch1 : Ch2);
    const float cs     = (z == 0) ? cs0 : ((z == 1) ? cs1 : cs2);

    const int bm = blockIdx.y * 128;
    const int bn = blockIdx.x * 256;
    const int warpM = wid >> 2;       // 0..1  (64 M-rows each)
    const int warpN = wid & 3;        // 0..3  (64 N-cols each)

    float acc[4][8][4];
#pragma unroll
    for (int i = 0; i < 4; i++)
#pragma unroll
        for (int j = 0; j < 8; j++)
#pragma unroll
            for (int k = 0; k < 4; k++) acc[i][j][k] = 0.0f;

    const int l8  = lid & 7;
    const int mid = lid >> 3;
    const int a_cb   = mid >> 1;
    const int a_rowl = warpM * 64 + l8 + (mid & 1) * 8;
    const int b_cb   = mid & 1;
    const int b_rowl = warpN * 64 + l8 + (mid >> 1) * 8;

    uint32_t a_row_off[4], b_row_off[4];
#pragma unroll
    for (int mt = 0; mt < 4; ++mt) a_row_off[mt] = (uint32_t)(a_rowl + mt * 16) * 128u;
#pragma unroll
    for (int j = 0; j < 4; ++j)    b_row_off[j]  = (uint32_t)(b_rowl + j * 16) * 128u;

    uint32_t a_swz[4], b_swz[4];
#pragma unroll
    for (int ks = 0; ks < 4; ++ks) {
        a_swz[ks] = (uint32_t)(((ks * 2 + a_cb) ^ l8) * 16);
        b_swz[ks] = (uint32_t)(((ks * 2 + b_cb) ^ l8) * 16);
    }

    auto load_chunk = [&](int c) {
        const uint32_t st = sbase + (uint32_t)(c % 3) * STAGE_B;
        const int k0 = c * 64;
        load_tile_cp(Af, bm, k0, st, t, 1024);            // A 128x64
        load_tile_cp(Wf, bn, k0, st + 16384, t, 2048);    // W 256x64
        CP_COMMIT();
    };

    load_chunk(0);
    load_chunk(1);
    CP_WAIT(1);
    __syncthreads();

    for (int c = 0; c < 32; ++c) {
        if (c + 2 < 32) load_chunk(c + 2);

        const uint32_t st = sbase + (uint32_t)(c % 3) * STAGE_B;
#pragma unroll
        for (int ks = 0; ks < 4; ++ks) {
            uint32_t af[4][4];
#pragma unroll
            for (int mt = 0; mt < 4; ++mt)
                ldsm_x4(af[mt], st + a_row_off[mt] + a_swz[ks]);
            uint32_t bf[4][4];
#pragma unroll
            for (int j = 0; j < 4; ++j)
                ldsm_x4(bf[j], st + 16384 + b_row_off[j] + b_swz[ks]);
#pragma unroll
            for (int mt = 0; mt < 4; ++mt)
#pragma unroll
                for (int nt = 0; nt < 8; ++nt)
                    mma16816(acc[mt][nt], af[mt], &bf[nt >> 1][(nt & 1) * 2]);
        }

        if (c + 2 < 32)      { CP_WAIT(1); }
        else if (c + 1 < 32) { CP_WAIT(0); }
        if (c + 1 < 32) __syncthreads();
    }

    // ---- epilogue ----
    const int lr  = lid >> 2;
    const int lc2 = (lid & 3) * 2;
    float2 bias2[8];
#pragma unroll
    for (int nt = 0; nt < 8; ++nt) {
        const int col = bn + warpN * 64 + nt * 8 + lc2;
        bias2[nt].x = __ldg(&bias[col]);
        bias2[nt].y = __ldg(&bias[col + 1]);
    }
#pragma unroll
    for (int mt = 0; mt < 4; ++mt) {
        const int row0 = bm + warpM * 64 + mt * 16 + lr;
#pragma unroll
        for (int nt = 0; nt < 8; ++nt) {
            const int col = bn + warpN * 64 + nt * 8 + lc2;
            float o0 = acc[mt][nt][0] + bias2[nt].x;
            float o1 = acc[mt][nt][1] + bias2[nt].y;
            float o2 = acc[mt][nt][2] + bias2[nt].x;
            float o3 = acc[mt][nt][3] + bias2[nt].y;
            if (Cf) {
                *(float2*)(Cf + (size_t)row0 * DD + col)       = make_float2(o0, o1);
                *(float2*)(Cf + (size_t)(row0 + 8) * DD + col) = make_float2(o2, o3);
            } else {
                *(uint32_t*)(Ch + (size_t)row0 * DD + col)       = pack_h2(o0 * cs, o1 * cs);
                *(uint32_t*)(Ch + (size_t)(row0 + 8) * DD + col) = pack_h2(o2 * cs, o3 * cs);
            }
        }
    }
}

// ---------------------------------------------------------------------------
// Flash attention, fp16 mma, 128-KEY blocks.
// CHANGE vs 289.3 baseline: QK and PV inner loops batch ALL 8 ldsm per
// ks before issuing HMMAs (was 1 ldsm -> 2 dependent HMMA per j, exposing
// ~30cyc LDSM latency per step). HMMA issue order unchanged -> arithmetic
// is bit-identical (rel_err must stay 6.333833e-4).
// ---------------------------------------------------------------------------
#define ABS 128
#define A_STAGES 32768
#define A_STAGE  65536                        // Kf 32KB | Vf 32KB
#define ATTN_SMEM (A_STAGES + 3 * A_STAGE)    // 229376

__device__ __forceinline__ void attn_load_kv(uint32_t sb, int kb, int h, int t)
{
    const uint32_t stbase = sb + A_STAGES + (uint32_t)(kb % 3) * A_STAGE;
    const int s0 = kb * ABS;
#pragma unroll
    for (int i = t; i < 4096; i += 256) {
        const int tensor = i >> 11;          // 0 Kf, 1 Vf
        const int r = (i >> 4) & 127;
        const int c = i & 15;
        const __half* g = tensor ? g_Vf : g_Kf;
        cp16(stbase + tensor * 32768 + r * 256 + ((c ^ (r & 7)) << 4),
             g + (size_t)(s0 + r) * DD + h * DHH + c * 8);
    }
    CP_COMMIT();
}

__global__ __launch_bounds__(256, 1)
void attn_mma()
{
    extern __shared__ __align__(1024) char smem[];
    const uint32_t sb = smem_to_u32(smem);
    const int t   = threadIdx.x;
    const int wid = t >> 5;
    const int lid = t & 31;
    const int l8  = lid & 7;
    const int mid = lid >> 3;
    const int h   = blockIdx.x & 15;
    const int qb  = 15 - (blockIdx.x >> 4);   // heavy blocks first
    const int q0  = qb * 128;
    const int nkb = qb + 1;

    // ---- prime: group 0 = Q tile + KV block 0, optional group 1 = KV1 ----
#pragma unroll
    for (int i = t; i < 2048; i += 256) {
        const int r = i >> 4;
        const int c = i & 15;
        cp16(sb + r * 256 + ((c ^ (r & 7)) << 4),
             g_Qf + (size_t)(q0 + r) * DD + h * DHH + c * 8);
    }
    attn_load_kv(sb, 0, h, t);            // commits group 0 (Q + KV0)
    if (nkb > 1) {
        attn_load_kv(sb, 1, h, t);        // group 1
        CP_WAIT(1);                       // group 0 complete
    } else {
        CP_WAIT(0);                       // only one group exists: full drain
    }
    __syncthreads();

    // precomputed K-row offsets (row part only; swizzle column varies by ks)
    uint32_t k_row_off[8], v_row_off[8];
#pragma unroll
    for (int j = 0; j < 8; ++j)
        k_row_off[j] = (uint32_t)(j * 16 + l8 + (mid >> 1) * 8) * 256u;
#pragma unroll
    for (int ks = 0; ks < 8; ++ks)
        v_row_off[ks] = (uint32_t)(ks * 16 + l8 + (mid & 1) * 8) * 256u;

    float oacc[16][4];
#pragma unroll
    for (int i = 0; i < 16; i++)
#pragma unroll
        for (int j = 0; j < 4; j++) oacc[i][j] = 0.0f;
    float mrow0 = -1e30f, mrow1 = -1e30f, lrow0 = 0.0f, lrow1 = 0.0f;

    for (int kb = 0; kb < nkb; ++kb) {
        if (kb + 2 < nkb) attn_load_kv(sb, kb + 2, h, t);

        const uint32_t st = sb + A_STAGES + (uint32_t)(kb % 3) * A_STAGE;

        // ---- S = Q . K^T  (128 q x 128 s); batched LDSM per ks ----
        float sacc[16][4];
#pragma unroll
        for (int i = 0; i < 16; i++)
#pragma unroll
            for (int j = 0; j < 4; j++) sacc[i][j] = 0.0f;

#pragma unroll
        for (int ks = 0; ks < 8; ++ks) {
            const int qrow = wid * 16 + (lid & 15);
            const uint32_t qc = (uint32_t)(2 * ks + (lid >> 4));
            const uint32_t qoff = (uint32_t)qrow * 256 + (((qc ^ (qrow & 7))) << 4);
            uint32_t af[4];
            ldsm_x4(af, sb + qoff);
            uint32_t bf[8][4];
#pragma unroll
            for (int j = 0; j < 8; ++j) {
                const int krow8 = j * 16 + l8 + (mid >> 1) * 8;
                const uint32_t kc = (uint32_t)(2 * ks + (mid & 1));
                ldsm_x4(bf[j], st + k_row_off[j] + (((kc ^ (krow8 & 7))) << 4));
            }
#pragma unroll
            for (int j = 0; j < 8; ++j) {
                mma16816(sacc[2 * j],     af, &bf[j][0]);
                mma16816(sacc[2 * j + 1], af, &bf[j][2]);
            }
        }

        // ---- causal mask (diagonal block only: kb == qb) ----
        const int rlo = q0 + wid * 16 + (lid >> 2);
        const int rhi = rlo + 8;
        if (kb == qb) {
#pragma unroll
            for (int nt = 0; nt < 16; ++nt) {
                const int c0 = kb * ABS + nt * 8 + (lid & 3) * 2;
                if (c0 > rlo)     sacc[nt][0] = -1e30f;
                if (c0 + 1 > rlo) sacc[nt][1] = -1e30f;
                if (c0 > rhi)     sacc[nt][2] = -1e30f;
                if (c0 + 1 > rhi) sacc[nt][3] = -1e30f;
            }
        }

        // ---- online softmax (log2 domain), ONE chain per 128 keys ----
        float mx0 = -1e30f, mx1 = -1e30f;
#pragma unroll
        for (int nt = 0; nt < 16; ++nt) {
            mx0 = fmaxf(mx0, fmaxf(sacc[nt][0], sacc[nt][1]));
            mx1 = fmaxf(mx1, fmaxf(sacc[nt][2], sacc[nt][3]));
        }
        mx0 = fmaxf(mx0, __shfl_xor_sync(0xffffffffu, mx0, 1));
        mx0 = fmaxf(mx0, __shfl_xor_sync(0xffffffffu, mx0, 2));
        mx1 = fmaxf(mx1, __shfl_xor_sync(0xffffffffu, mx1, 1));
        mx1 = fmaxf(mx1, __shfl_xor_sync(0xffffffffu, mx1, 2));
        const float mnew0 = fmaxf(mrow0, mx0);
        const float mnew1 = fmaxf(mrow1, mx1);
        const float alpha0 = ex2a(mrow0 - mnew0);
        const float alpha1 = ex2a(mrow1 - mnew1);
        float sum0 = 0.0f, sum1 = 0.0f;
#pragma unroll
        for (int nt = 0; nt < 16; ++nt) {
            sacc[nt][0] = ex2a(sacc[nt][0] - mnew0); sum0 += sacc[nt][0];
            sacc[nt][1] = ex2a(sacc[nt][1] - mnew0); sum0 += sacc[nt][1];
            sacc[nt][2] = ex2a(sacc[nt][2] - mnew1); sum1 += sacc[nt][2];
            sacc[nt][3] = ex2a(sacc[nt][3] - mnew1); sum1 += sacc[nt][3];
        }
        sum0 += __shfl_xor_sync(0xffffffffu, sum0, 1);
        sum0 += __shfl_xor_sync(0xffffffffu, sum0, 2);
        sum1 += __shfl_xor_sync(0xffffffffu, sum1, 1);
        sum1 += __shfl_xor_sync(0xffffffffu, sum1, 2);
        lrow0 = lrow0 * alpha0 + sum0;  mrow0 = mnew0;
        lrow1 = lrow1 * alpha1 + sum1;  mrow1 = mnew1;
#pragma unroll
        for (int nt = 0; nt < 16; ++nt) {
            oacc[nt][0] *= alpha0; oacc[nt][1] *= alpha0;
            oacc[nt][2] *= alpha1; oacc[nt][3] *= alpha1;
        }

        // ---- O += P . V  (128 s-rows); batched LDSM per ks ----
#pragma unroll
        for (int ks = 0; ks < 8; ++ks) {
            uint32_t ph[4];
            ph[0] = pack_h2(sacc[2 * ks][0],     sacc[2 * ks][1]);
            ph[1] = pack_h2(sacc[2 * ks][2],     sacc[2 * ks][3]);
            ph[2] = pack_h2(sacc[2 * ks + 1][0], sacc[2 * ks + 1][1]);
            ph[3] = pack_h2(sacc[2 * ks + 1][2], sacc[2 * ks + 1][3]);
            const int vrow8 = ks * 16 + l8 + (mid & 1) * 8;
            uint32_t vf[8][4];
#pragma unroll
            for (int jj = 0; jj < 8; ++jj) {
                const uint32_t vc = (uint32_t)(jj * 2 + (mid >> 1));
                ldsm_x4_t(vf[jj], st + 32768 + v_row_off[ks] + (((vc ^ (vrow8 & 7))) << 4));
            }
#pragma unroll
            for (int jj = 0; jj < 8; ++jj) {
                mma16816(oacc[2 * jj],     ph, &vf[jj][0]);
                mma16816(oacc[2 * jj + 1], ph, &vf[jj][2]);
            }
        }

        if (kb + 2 < nkb)      { CP_WAIT(1); }
        else if (kb + 1 < nkb) { CP_WAIT(0); }
        if (kb + 1 < nkb) __syncthreads();
    }

    // ---- epilogue: O /= l, write Yf ----
    const float inv0 = 1.0f / lrow0;
    const float inv1 = 1.0f / lrow1;
    const int r0 = q0 + wid * 16 + (lid >> 2);
    const int r1 = r0 + 8;
    const int colb = h * DHH + (lid & 3) * 2;
#pragma unroll
    for (int nt = 0; nt < 16; ++nt) {
        const int col = colb + nt * 8;
        *(uint32_t*)(g_Yf + (size_t)r0 * DD + col) =
            pack_h2(oacc[nt][0] * inv0, oacc[nt][1] * inv0);
        *(uint32_t*)(g_Yf + (size_t)r1 * DD + col) =
            pack_h2(oacc[nt][2] * inv1, oacc[nt][3] * inv1);
    }
}

// ---------------------------------------------------------------------------
// Launch
// ---------------------------------------------------------------------------
extern "C" void kernel_launch(void* const* d_in, const int* in_sizes, int n_in,
                              void* d_out, int out_size)
{
    const float* x  = (const float*)d_in[0];
    const float* Wq = (const float*)d_in[1];
    const float* bq = (const float*)d_in[2];
    const float* Wk = (const float*)d_in[3];
    const float* bk = (const float*)d_in[4];
    const float* Wv = (const float*)d_in[5];
    const float* bv = (const float*)d_in[6];
    const float* Wo = (const float*)d_in[7];
    const float* bo = (const float*)d_in[8];
    float* out = (float*)d_out;

    __half *xf, *wq, *wk, *wv, *wo, *qf, *kf, *vf, *yf;
    cudaGetSymbolAddress((void**)&xf, g_xf);
    cudaGetSymbolAddress((void**)&wq, g_Wq_f); cudaGetSymbolAddress((void**)&wk, g_Wk_f);
    cudaGetSymbolAddress((void**)&wv, g_Wv_f); cudaGetSymbolAddress((void**)&wo, g_Wo_f);
    cudaGetSymbolAddress((void**)&qf, g_Qf);   cudaGetSymbolAddress((void**)&kf, g_Kf);
    cudaGetSymbolAddress((void**)&vf, g_Vf);   cudaGetSymbolAddress((void**)&yf, g_Yf);

    cudaFuncSetAttribute(gemm_mma, cudaFuncAttributeMaxDynamicSharedMemorySize, GEMM_SMEM);
    cudaFuncSetAttribute(attn_mma, cudaFuncAttributeMaxDynamicSharedMemorySize, ATTN_SMEM);

    const int nv4 = (TT * DD / 4) / 256;   // 4096 blocks (float4 granules)
    conv_f16<<<dim3(nv4, 5), 256>>>(x, xf, Wq, wq, Wk, wk, Wv, wv, Wo, wo);

    // fused QKV projection (1-pass): Q (scaled), K, V fp16 out; N-tile 256
    gemm_mma<<<dim3(8, 16, 3), 256, GEMM_SMEM>>>(
        xf,
        wq, bq, nullptr, qf, SCALE_Q,
        wk, bk, nullptr, kf, 1.0f,
        wv, bv, nullptr, vf, 1.0f);

    attn_mma<<<256, 256, ATTN_SMEM>>>();

    // output projection (1-pass), fp32 epilogue; N-tile 256
    gemm_mma<<<dim3(8, 16, 1), 256, GEMM_SMEM>>>(
        yf,
        wo, bo, out, nullptr, 1.0f,
        wo, bo, out, nullptr, 1.0f,
        wo, bo, out, nullptr, 1.0f);
}